// round 11
// baseline (speedup 1.0000x reference)
#include <cuda_runtime.h>
#include <cuda_fp16.h>
#include <float.h>
#include <stdint.h>

// ---------------- problem constants ----------------
#define BB    8
#define NPT   2048
#define BNP   16384          // BB*NPT
#define KNN   20
#define CH    64
#define FD    256            // 4*CH
#define EMB   1024

// ---------------- scratch (device globals; no mallocs allowed) ----------------
__device__ float4 d_P4[BB*NPT];
__device__ int   d_nbr[BNP*KNN];
__device__ int   d_deg[BNP];
__device__ int   d_rowstart[BNP+1];
__device__ int   d_cursor[BNP];
__device__ int   d_bsum[16];
__device__ int   d_rev[BNP*KNN];
__device__ float d_F[BNP*FD];
__device__ float d_sup[BNP*CH];
__device__ float d_z[BNP*CH];
__device__ float d_rz[BNP*CH];
__device__ __half d_Yh[(size_t)EMB*BNP];   // conv output fp16 [e][p], 32 MB
__device__ unsigned d_maxK[BB*EMB], d_minK[BB*EMB];  // per (b,e) raw-y extrema keys
__device__ float d_x12[BB*2*EMB];
__device__ float d_h512[BB*512];
__device__ float d_h256[BB*256];
__device__ float d_sumA[4*CH], d_sqA[4*CH];
__device__ float d_sumB[CH], d_sqB[CH];
__device__ float d_sumY[EMB], d_sqY[EMB];
__device__ __half d_Ah[EMB*FD], d_Al[EMB*FD];   // wconv fp16 hi/lo
__device__ __half d_Fh[BNP*FD], d_Fl[BNP*FD];   // features fp16 hi/lo

// ---------------- helpers ----------------
__device__ __forceinline__ uint32_t smem_u32(const void* p) {
    uint32_t a;
    asm("{ .reg .u64 t; cvta.to.shared.u64 t, %1; cvt.u32.u64 %0, t; }" : "=r"(a) : "l"(p));
    return a;
}
__device__ __forceinline__ void ldm_x4(uint32_t* r, uint32_t addr) {
    asm volatile("ldmatrix.sync.aligned.m8n8.x4.shared.b16 {%0,%1,%2,%3}, [%4];"
        : "=r"(r[0]), "=r"(r[1]), "=r"(r[2]), "=r"(r[3]) : "r"(addr));
}
__device__ __forceinline__ void mma16816h(float* c, const uint32_t* a, const uint32_t* b) {
    asm volatile(
        "mma.sync.aligned.m16n8k16.row.col.f32.f16.f16.f32 "
        "{%0,%1,%2,%3}, {%4,%5,%6,%7}, {%8,%9}, {%0,%1,%2,%3};"
        : "+f"(c[0]), "+f"(c[1]), "+f"(c[2]), "+f"(c[3])
        : "r"(a[0]), "r"(a[1]), "r"(a[2]), "r"(a[3]), "r"(b[0]), "r"(b[1]));
}
__device__ __forceinline__ void cp16(uint32_t sdst, const void* gsrc) {
    asm volatile("cp.async.cg.shared.global [%0], [%1], 16;" :: "r"(sdst), "l"(gsrc));
}
#define CP_COMMIT() asm volatile("cp.async.commit_group;" ::: "memory")
#define CP_WAIT0()  asm volatile("cp.async.wait_group 0;" ::: "memory")

__device__ __forceinline__ unsigned fkey(float f) {
    unsigned u = __float_as_uint(f);
    return (u & 0x80000000u) ? ~u : (u | 0x80000000u);
}
__device__ __forceinline__ float unkey(unsigned k) {
    return (k & 0x80000000u) ? __uint_as_float(k & 0x7fffffffu) : __uint_as_float(~k);
}

// ---------------- begin: zero stats/deg + wconv fp16 hi/lo split -------------
__global__ void k_begin(const float* __restrict__ w) {
    int t = blockIdx.x*256 + threadIdx.x;   // 65536 threads
    if (t < BNP) d_deg[t] = 0;
    if (t < 4*CH) { d_sumA[t] = 0.f; d_sqA[t] = 0.f; }
    if (t < CH)   { d_sumB[t] = 0.f; d_sqB[t] = 0.f; }
    if (t < EMB)  { d_sumY[t] = 0.f; d_sqY[t] = 0.f; }
    if (t < BB*EMB) { d_maxK[t] = 0u; d_minK[t] = 0xFFFFFFFFu; }
    float4 x = ((const float4*)w)[t];       // EMB*FD/4 = 65536
    __half h0 = __float2half_rn(x.x), h1 = __float2half_rn(x.y);
    __half h2 = __float2half_rn(x.z), h3 = __float2half_rn(x.w);
    __half l0 = __float2half_rn(x.x - __half2float(h0));
    __half l1 = __float2half_rn(x.y - __half2float(h1));
    __half l2 = __float2half_rn(x.z - __half2float(h2));
    __half l3 = __float2half_rn(x.w - __half2float(h3));
    ((__half2*)d_Ah)[t*2]   = __half2(h0, h1);
    ((__half2*)d_Ah)[t*2+1] = __half2(h2, h3);
    ((__half2*)d_Al)[t*2]   = __half2(l0, l1);
    ((__half2*)d_Al)[t*2+1] = __half2(l2, l3);
}

// pts[b,c,n] = x[b, (c*N+n)%3, (c*N+n)/3]
__global__ void k_prep(const float* __restrict__ x) {
    int t = blockIdx.x*256 + threadIdx.x;
    if (t >= BNP) return;
    int b = t >> 11, n = t & 2047;
    const float* xb = x + b*3*NPT;
    float v[3]; float acc = 0.f;
    #pragma unroll
    for (int c = 0; c < 3; c++) {
        int L = c*NPT + n;
        v[c] = xb[(L % 3)*NPT + (L / 3)];
        acc += v[c]*v[c];
    }
    d_P4[t] = make_float4(v[0], v[1], v[2], acc);
}

// identical arithmetic in both KNN passes (explicit intrinsics -> deterministic)
__device__ __forceinline__ float pdist(float4 q, float4 pm) {
    float dot = __fmaf_rn(q.x, pm.x, __fmaf_rn(q.y, pm.y, __fmul_rn(q.z, pm.z)));
    return __fadd_rn(__fmaf_rn(2.f, dot, -q.w), -pm.w);
}

// ---------------- knn: two-pass threshold, 4 rows per warp share loads -------
// dynamic smem: sP 32KB | sv 16KB | si 16KB  (64KB total)
#define KNN_SMEM 65536
__global__ void __launch_bounds__(256) k_knn() {
    extern __shared__ char dsm[];
    float4* sP = (float4*)dsm;
    float*  sv = (float*)(dsm + 32768);     // [8 warps][4 rows][128]
    int*    si = (int*)(dsm + 49152);
    int b = blockIdx.x >> 6;                 // 8 batches x 64 chunks
    int chunk = blockIdx.x & 63;             // 32 rows per chunk
    for (int i = threadIdx.x; i < NPT; i += 256)
        sP[i] = d_P4[b*NPT + i];
    __syncthreads();

    int warp = threadIdx.x >> 5, lane = threadIdx.x & 31;
    int n0 = chunk*32 + warp*4;
    float4 qa[4];
    #pragma unroll
    for (int r = 0; r < 4; r++) qa[r] = sP[n0 + r];

    // pass A: one shared load feeds 4 rows
    float vmax[4];
    #pragma unroll
    for (int r = 0; r < 4; r++) vmax[r] = -FLT_MAX;
    for (int m = lane; m < NPT; m += 32) {
        float4 pm = sP[m];
        #pragma unroll
        for (int r = 0; r < 4; r++) vmax[r] = fmaxf(vmax[r], pdist(qa[r], pm));
    }

    // tau_r = 20th largest of 32 lane maxima (pop loop per row)
    float tval[4];
    #pragma unroll 1
    for (int r = 0; r < 4; r++) {
        unsigned mykey = fkey(vmax[r]);
        unsigned tkey = 0;
        #pragma unroll 1
        for (int k = 0; k < KNN; k++) {
            tkey = __reduce_max_sync(0xffffffffu, mykey);
            unsigned msk = __ballot_sync(0xffffffffu, mykey == tkey);
            if (lane == __ffs(msk) - 1) mykey = 0;
        }
        tval[r] = unkey(tkey);
    }

    // pass B: compact survivors (pd >= tau) for 4 rows per shared load
    int base[4];
    #pragma unroll
    for (int r = 0; r < 4; r++) base[r] = 0;
    float* svw = sv + warp*4*128;
    int*   siw = si + warp*4*128;
    for (int m = lane; m < NPT; m += 32) {
        float4 pm = sP[m];
        #pragma unroll
        for (int r = 0; r < 4; r++) {
            float pd = pdist(qa[r], pm);
            bool s = (pd >= tval[r]);
            unsigned msk = __ballot_sync(0xffffffffu, s);
            if (s) {
                int pos = base[r] + __popc(msk & ((1u << lane) - 1));
                if (pos < 128) { svw[r*128 + pos] = pd; siw[r*128 + pos] = m; }
            }
            base[r] += __popc(msk);
        }
    }
    __syncwarp();

    #pragma unroll 1
    for (int r = 0; r < 4; r++) {
        int S = base[r] < 128 ? base[r] : 128;
        float v[4]; int id[4];
        #pragma unroll
        for (int j = 0; j < 4; j++) {
            int idx = lane + j*32;
            if (idx < S) { v[j] = svw[r*128 + idx]; id[j] = siw[r*128 + idx]; }
            else         { v[j] = -FLT_MAX;         id[j] = 0x7fffffff; }
        }
        #define CE(A_, B_) { \
            bool sw_ = (v[B_] > v[A_]) || (v[B_] == v[A_] && id[B_] < id[A_]); \
            if (sw_) { float tv_ = v[A_]; v[A_] = v[B_]; v[B_] = tv_; \
                       int ti_ = id[A_]; id[A_] = id[B_]; id[B_] = ti_; } }
        CE(0,1) CE(2,3) CE(0,2) CE(1,3) CE(1,2)
        #undef CE

        int pg = b*NPT + n0 + r;
        #pragma unroll 1
        for (int k = 0; k < KNN; k++) {
            unsigned mk = fkey(v[0]);
            unsigned best = __reduce_max_sync(0xffffffffu, mk);
            int cand = (mk == best) ? id[0] : 0x7fffffff;
            int bmi = __reduce_min_sync(0xffffffffu, cand);
            if (mk == best && id[0] == bmi) {
                v[0] = v[1]; id[0] = id[1];
                v[1] = v[2]; id[1] = id[2];
                v[2] = v[3]; id[2] = id[3];
                v[3] = -FLT_MAX; id[3] = 0x7fffffff;
            }
            if (lane == 0) {
                int qg = b*NPT + bmi;
                d_nbr[pg*KNN + k] = qg;
                atomicAdd(&d_deg[qg], 1);
            }
        }
    }
}

// ---------------- parallel scan ----------------
__global__ void k_scanA() {
    int t = threadIdx.x, g = blockIdx.x*1024 + t;
    int v = d_deg[g];
    int lane = t & 31, wid = t >> 5;
    int vv = v;
    #pragma unroll
    for (int o = 1; o < 32; o <<= 1) { int u = __shfl_up_sync(0xffffffffu, vv, o); if (lane >= o) vv += u; }
    __shared__ int ws[32];
    if (lane == 31) ws[wid] = vv;
    __syncthreads();
    if (wid == 0) {
        int w = ws[lane];
        #pragma unroll
        for (int o = 1; o < 32; o <<= 1) { int u = __shfl_up_sync(0xffffffffu, w, o); if (lane >= o) w += u; }
        ws[lane] = w;
    }
    __syncthreads();
    int incl = vv + (wid ? ws[wid-1] : 0);
    d_rowstart[g] = incl - v;
    if (t == 1023) d_bsum[blockIdx.x] = incl;
}

__global__ void k_scanB() {
    int g = blockIdx.x*256 + threadIdx.x;
    int sb = g >> 10;
    int off = 0;
    #pragma unroll 1
    for (int i = 0; i < sb; i++) off += d_bsum[i];
    int rs = d_rowstart[g] + off;
    d_rowstart[g] = rs;
    d_cursor[g] = rs;
    if (g == BNP - 1) {
        int tot = 0;
        #pragma unroll
        for (int i = 0; i < 16; i++) tot += d_bsum[i];
        d_rowstart[BNP] = tot;
    }
}

__global__ void k_fill() {
    int p = blockIdx.x*256 + threadIdx.x;
    if (p >= BNP) return;
    #pragma unroll
    for (int k = 0; k < KNN; k++) {
        int q = d_nbr[p*KNN + k];
        int pos = atomicAdd(&d_cursor[q], 1);
        d_rev[pos] = p;
    }
}

// ---------------- layer 0: sup0 = flat@w0 ; rz = flat@wr + br (+ rz stats) ----
__global__ void k_l0mm(const float* __restrict__ x, const float* __restrict__ w0,
                       const float* __restrict__ wr, const float* __restrict__ br) {
    int tid = threadIdx.x;
    int t = blockIdx.x*256 + tid;
    int p = t >> 6, c = t & 63;
    int b = p >> 11, n = p & 2047;
    const float* xb = x + b*3*NPT;
    float x0 = xb[n], x1 = xb[NPT + n], x2 = xb[2*NPT + n];
    d_sup[t] = x0*w0[c] + x1*w0[64+c] + x2*w0[128+c];
    float rz = x0*wr[c] + x1*wr[64+c] + x2*wr[128+c] + br[c];
    d_rz[t] = rz;
    __shared__ float s1[256], s2[256];
    s1[tid] = rz; s2[tid] = rz*rz;
    __syncthreads();
    if (tid < 64) {
        float a = s1[tid] + s1[64+tid] + s1[128+tid] + s1[192+tid];
        float q = s2[tid] + s2[64+tid] + s2[128+tid] + s2[192+tid];
        atomicAdd(&d_sumB[tid], a);
        atomicAdd(&d_sqB[tid], q);
    }
}

// ---------------- gather (reverse CSR, 4-wide unroll for MLP) + stats --------
__global__ void k_gather_stats(const float* __restrict__ bias, int layer) {
    int t = threadIdx.x;
    int q = blockIdx.x*4 + (t >> 6);
    int c = t & 63;
    float acc = bias[c];
    int s0 = d_rowstart[q], e0 = d_rowstart[q+1];
    int i = s0;
    int e4 = s0 + ((e0 - s0) & ~3);
    for (; i < e4; i += 4) {
        int r0 = d_rev[i], r1 = d_rev[i+1], r2 = d_rev[i+2], r3 = d_rev[i+3];
        float v0 = d_sup[r0*64 + c];
        float v1 = d_sup[r1*64 + c];
        float v2 = d_sup[r2*64 + c];
        float v3 = d_sup[r3*64 + c];
        acc += v0; acc += v1; acc += v2; acc += v3;
    }
    for (; i < e0; i++) acc += d_sup[d_rev[i]*64 + c];
    d_z[q*64 + c] = acc;
    __shared__ float s1[256], s2[256];
    s1[t] = acc; s2[t] = acc*acc;
    __syncthreads();
    if (t < 64) {
        float a = s1[t] + s1[64+t] + s1[128+t] + s1[192+t];
        float qq = s2[t] + s2[64+t] + s2[128+t] + s2[192+t];
        atomicAdd(&d_sumA[layer*64 + t], a);
        atomicAdd(&d_sqA[layer*64 + t], qq);
    }
}

// ---------------- fused post (layer 0) + mm for layer 1 ----------------
__global__ void __launch_bounds__(256) k_post0_mm(
        const float* __restrict__ g0, const float* __restrict__ be0,
        const float* __restrict__ gr, const float* __restrict__ ber,
        const float* __restrict__ W1) {
    __shared__ float Hs[64*64];
    __shared__ float Ws[64*64];
    int tid = threadIdx.x;
    int p0 = blockIdx.x*64;
    int c = tid & 63, rg = tid >> 6;
    float mA = d_sumA[c]*(1.f/BNP);
    float vA = d_sqA[c]*(1.f/BNP) - mA*mA;
    float sA = rsqrtf(vA + 1e-5f)*g0[c], bA = be0[c];
    float mB = d_sumB[c]*(1.f/BNP);
    float vB = d_sqB[c]*(1.f/BNP) - mB*mB;
    float sB = rsqrtf(vB + 1e-5f)*gr[c], bB = ber[c];
    #pragma unroll
    for (int i = 0; i < 16; i++) {
        int r = rg + i*4, p = p0 + r;
        float o = fmaxf((d_z[p*64+c] - mA)*sA + bA, 0.f);
        float rr = (d_rz[p*64+c] - mB)*sB + bB;
        float h = fmaxf(o + rr, 0.f);
        Hs[r*64+c] = h;
        d_F[p*FD + c] = h;
        __half hi = __float2half_rn(h);
        d_Fh[p*FD + c] = hi;
        d_Fl[p*FD + c] = __float2half_rn(h - __half2float(hi));
    }
    for (int i = tid; i < 4096; i += 256) Ws[i] = W1[i];
    __syncthreads();
    for (int r = rg; r < 64; r += 4) {
        float acc = 0.f;
        #pragma unroll 16
        for (int k = 0; k < 64; k++) acc += Hs[r*64+k]*Ws[k*64+c];
        d_sup[(p0+r)*64+c] = acc;
    }
}

// ---------------- fused post (layers 1,2) + mm for next layer ----------------
__global__ void __launch_bounds__(256) k_postL_mm(int layer,
        const float* __restrict__ G, const float* __restrict__ Be,
        const float* __restrict__ Wn) {
    __shared__ float Hs[64*64];
    __shared__ float Ws[64*64];
    int tid = threadIdx.x;
    int p0 = blockIdx.x*64;
    int c = tid & 63, rg = tid >> 6;
    float m = d_sumA[layer*64+c]*(1.f/BNP);
    float v = d_sqA[layer*64+c]*(1.f/BNP) - m*m;
    float sc = rsqrtf(v + 1e-5f)*G[c], bc = Be[c];
    #pragma unroll
    for (int i = 0; i < 16; i++) {
        int r = rg + i*4, p = p0 + r;
        float a = fmaxf((d_z[p*64+c] - m)*sc + bc, 0.f);
        float h = fmaxf(a + d_F[p*FD + (layer-1)*64 + c], 0.f);
        Hs[r*64+c] = h;
        d_F[p*FD + layer*64 + c] = h;
        __half hi = __float2half_rn(h);
        d_Fh[p*FD + layer*64 + c] = hi;
        d_Fl[p*FD + layer*64 + c] = __float2half_rn(h - __half2float(hi));
    }
    for (int i = tid; i < 4096; i += 256) Ws[i] = Wn[i];
    __syncthreads();
    for (int r = rg; r < 64; r += 4) {
        float acc = 0.f;
        #pragma unroll 16
        for (int k = 0; k < 64; k++) acc += Hs[r*64+k]*Ws[k*64+c];
        d_sup[(p0+r)*64+c] = acc;
    }
}

// ---------------- post layer 3 ----------------
__global__ void k_post3(const float* __restrict__ G, const float* __restrict__ Be) {
    int t = blockIdx.x*256 + threadIdx.x;
    int p = t >> 6, c = t & 63;
    float m = d_sumA[3*64+c]*(1.f/BNP);
    float v = d_sqA[3*64+c]*(1.f/BNP) - m*m;
    float a = fmaxf((d_z[t] - m)*rsqrtf(v + 1e-5f)*G[c] + Be[c], 0.f);
    float h = fmaxf(a + d_F[p*FD + 2*64 + c], 0.f);
    __half hi = __float2half_rn(h);
    d_Fh[p*FD + 3*64 + c] = hi;
    d_Fl[p*FD + 3*64 + c] = __float2half_rn(h - __half2float(hi));
}

// ---------------- conv GEMM: fp16 3-term split, cp.async 2-stage -------------
// C = Ah.Bh + Al.Bh + Ah.Bl ; epilogue stores fp16 y + stats + raw extrema
#define PITCH 80
#define TSZ   (128*PITCH)
#define STAGE (4*TSZ)
#define SMEM_CONV (2*STAGE)   // 81920 B

__global__ void __launch_bounds__(256) k_conv_mma() {
    extern __shared__ __align__(16) uint8_t sm[];
    uint32_t sb = smem_u32(sm);

    int tid = threadIdx.x, wid = tid >> 5, lane = tid & 31;
    int warp_m = wid >> 2, warp_n = wid & 3;
    int bn = blockIdx.x;
    int bm = blockIdx.y;
    int bb = bn >> 4;                       // batch of this p-tile

    const uint4* gAh = (const uint4*)d_Ah;
    const uint4* gAl = (const uint4*)d_Al;
    const uint4* gBh = (const uint4*)d_Fh;
    const uint4* gBl = (const uint4*)d_Fl;

    float C[4][4][4];
    #pragma unroll
    for (int i = 0; i < 4; i++)
        #pragma unroll
        for (int j = 0; j < 4; j++)
            #pragma unroll
            for (int q = 0; q < 4; q++) C[i][j][q] = 0.f;

    int rowA  = warp_m*64 + (lane & 15);
    int halfA = lane >> 4;
    uint32_t oAh = rowA*PITCH + halfA*16;
    uint32_t oAl = TSZ + rowA*PITCH + halfA*16;
    int rowB  = warp_n*32 + (lane & 7) + ((lane >> 4) << 3);
    int halfB = (lane >> 3) & 1;
    uint32_t oBh = 2*TSZ + rowB*PITCH + halfB*16;
    uint32_t oBl = 3*TSZ + rowB*PITCH + halfB*16;

    auto issue = [&](int kc, int s) {
        uint32_t base = sb + s*STAGE;
        #pragma unroll
        for (int l = 0; l < 2; l++) {
            int i = tid + l*256;
            int row = i >> 2, c = i & 3;
            uint32_t so = row*PITCH + c*16;
            size_t ga = (size_t)(bm*128 + row)*32 + kc*4 + c;
            size_t gb = (size_t)(bn*128 + row)*32 + kc*4 + c;
            cp16(base + so,          gAh + ga);
            cp16(base + TSZ + so,    gAl + ga);
            cp16(base + 2*TSZ + so,  gBh + gb);
            cp16(base + 3*TSZ + so,  gBl + gb);
        }
        CP_COMMIT();
    };

    issue(0, 0);
    for (int kc = 0; kc < 8; kc++) {
        int s = kc & 1;
        CP_WAIT0();
        __syncthreads();
        if (kc + 1 < 8) issue(kc + 1, s ^ 1);
        uint32_t stb = sb + s*STAGE;

        #pragma unroll
        for (int ksub = 0; ksub < 2; ksub++) {
            uint32_t koff = (ksub*2)*16;
            uint32_t bh[8], bl[8];
            ldm_x4(bh + 0, stb + oBh + koff);
            ldm_x4(bh + 4, stb + oBh + koff + 16*PITCH);
            ldm_x4(bl + 0, stb + oBl + koff);
            ldm_x4(bl + 4, stb + oBl + koff + 16*PITCH);
            #pragma unroll
            for (int mt = 0; mt < 4; mt++) {
                uint32_t ah[4], al[4];
                ldm_x4(ah, stb + oAh + koff + mt*16*PITCH);
                ldm_x4(al, stb + oAl + koff + mt*16*PITCH);
                #pragma unroll
                for (int nt = 0; nt < 4; nt++) {
                    const uint32_t* ph = &bh[(nt >> 1)*4 + (nt & 1)*2];
                    const uint32_t* pl = &bl[(nt >> 1)*4 + (nt & 1)*2];
                    mma16816h(C[mt][nt], ah, ph);
                    mma16816h(C[mt][nt], al, ph);
                    mma16816h(C[mt][nt], ah, pl);
                }
            }
        }
        __syncthreads();
    }

    // epilogue: fp16 store + per-e BN partial stats + raw extrema
    #pragma unroll
    for (int mt = 0; mt < 4; mt++) {
        int e = bm*128 + warp_m*64 + mt*16 + (lane >> 2);
        float s0 = 0.f, q0 = 0.f, s1 = 0.f, q1 = 0.f;
        float mx0 = -FLT_MAX, mn0 = FLT_MAX, mx1 = -FLT_MAX, mn1 = FLT_MAX;
        #pragma unroll
        for (int nt = 0; nt < 4; nt++) {
            int p = bn*128 + warp_n*32 + nt*8 + (lane & 3)*2;
            float a0 = C[mt][nt][0], a1 = C[mt][nt][1];
            float a2 = C[mt][nt][2], a3 = C[mt][nt][3];
            *(__half2*)&d_Yh[(size_t)e*BNP + p] =
                __half2(__float2half_rn(a0), __float2half_rn(a1));
            *(__half2*)&d_Yh[(size_t)(e + 8)*BNP + p] =
                __half2(__float2half_rn(a2), __float2half_rn(a3));
            s0 += a0 + a1; q0 += a0*a0 + a1*a1;
            s1 += a2 + a3; q1 += a2*a2 + a3*a3;
            mx0 = fmaxf(mx0, fmaxf(a0, a1)); mn0 = fminf(mn0, fminf(a0, a1));
            mx1 = fmaxf(mx1, fmaxf(a2, a3)); mn1 = fminf(mn1, fminf(a2, a3));
        }
        #pragma unroll
        for (int o = 1; o < 4; o <<= 1) {
            s0 += __shfl_xor_sync(0xffffffffu, s0, o);
            q0 += __shfl_xor_sync(0xffffffffu, q0, o);
            s1 += __shfl_xor_sync(0xffffffffu, s1, o);
            q1 += __shfl_xor_sync(0xffffffffu, q1, o);
            mx0 = fmaxf(mx0, __shfl_xor_sync(0xffffffffu, mx0, o));
            mn0 = fminf(mn0, __shfl_xor_sync(0xffffffffu, mn0, o));
            mx1 = fmaxf(mx1, __shfl_xor_sync(0xffffffffu, mx1, o));
            mn1 = fminf(mn1, __shfl_xor_sync(0xffffffffu, mn1, o));
        }
        if ((lane & 3) == 0) {
            atomicAdd(&d_sumY[e], s0);     atomicAdd(&d_sqY[e], q0);
            atomicAdd(&d_sumY[e + 8], s1); atomicAdd(&d_sqY[e + 8], q1);
            atomicMax(&d_maxK[bb*EMB + e], fkey(mx0));
            atomicMin(&d_minK[bb*EMB + e], fkey(mn0));
            atomicMax(&d_maxK[bb*EMB + e + 8], fkey(mx1));
            atomicMin(&d_minK[bb*EMB + e + 8], fkey(mn1));
        }
    }
}

// ---------------- BN + leaky + mean pool (max pool from exact extrema) -------
__global__ void k_reduce(const float* __restrict__ gf, const float* __restrict__ bef) {
    int e = blockIdx.x;
    const __half2* y2 = (const __half2*)(d_Yh + (size_t)e*BNP);
    int t = threadIdx.x, lane = t & 31, w = t >> 5;
    float mu = d_sumY[e]*(1.f/BNP);
    float var = d_sqY[e]*(1.f/BNP) - mu*mu;
    float sc = rsqrtf(var + 1e-5f)*gf[e], sh = bef[e];
    __shared__ float wsum[8];
    for (int b = 0; b < BB; b++) {
        float sm = 0.f;
        const __half2* yb = y2 + b*(NPT/2);
        for (int j = t; j < NPT/2; j += 256) {
            float2 v2 = __half22float2(yb[j]);
            float v0 = (v2.x - mu)*sc + sh; v0 = v0 > 0.f ? v0 : 0.2f*v0;
            float v1 = (v2.y - mu)*sc + sh; v1 = v1 > 0.f ? v1 : 0.2f*v1;
            sm += v0 + v1;
        }
        #pragma unroll
        for (int o = 16; o; o >>= 1) sm += __shfl_xor_sync(0xffffffffu, sm, o);
        if (lane == 0) wsum[w] = sm;
        __syncthreads();
        if (t == 0) {
            float SM = 0.f;
            #pragma unroll
            for (int i = 0; i < 8; i++) SM += wsum[i];
            unsigned mk = (sc >= 0.f) ? d_maxK[b*EMB + e] : d_minK[b*EMB + e];
            float raw = unkey(mk);
            float v = (raw - mu)*sc + sh;
            v = v > 0.f ? v : 0.2f*v;
            d_x12[b*2*EMB + e] = v;
            d_x12[b*2*EMB + EMB + e] = SM*(1.f/NPT);
        }
        __syncthreads();
    }
}

// ---------------- head (k-split parallel) ----------------
__global__ void k_head1(const float* __restrict__ w1, const float* __restrict__ g6,
                        const float* __restrict__ b6) {
    int jl = threadIdx.x & 15, ks = threadIdx.x >> 4;
    int j = blockIdx.x*16 + jl;
    float acc[BB];
    #pragma unroll
    for (int b = 0; b < BB; b++) acc[b] = 0.f;
    for (int k = ks*128; k < ks*128 + 128; k++) {
        float wv = w1[k*512 + j];
        #pragma unroll
        for (int b = 0; b < BB; b++) acc[b] += d_x12[b*2*EMB + k]*wv;
    }
    __shared__ float sh[16][16][BB];
    #pragma unroll
    for (int b = 0; b < BB; b++) sh[ks][jl][b] = acc[b];
    __syncthreads();
    if (ks == 0) {
        #pragma unroll
        for (int b = 0; b < BB; b++) {
            float s = 0.f;
            #pragma unroll
            for (int i = 0; i < 16; i++) s += sh[i][jl][b];
            acc[b] = s;
        }
        float m = 0.f;
        #pragma unroll
        for (int b = 0; b < BB; b++) m += acc[b];
        m *= (1.f/BB);
        float var = 0.f;
        #pragma unroll
        for (int b = 0; b < BB; b++) { float d = acc[b]-m; var += d*d; }
        var *= (1.f/BB);
        float sc = rsqrtf(var + 1e-5f)*g6[j], bb = b6[j];
        #pragma unroll
        for (int b = 0; b < BB; b++) {
            float o = (acc[b]-m)*sc + bb;
            d_h512[b*512 + j] = o > 0.f ? o : 0.2f*o;
        }
    }
}

__global__ void k_head2(const float* __restrict__ w2, const float* __restrict__ b2,
                        const float* __restrict__ g7, const float* __restrict__ b7) {
    int jl = threadIdx.x & 31, ks = threadIdx.x >> 5;
    int j = blockIdx.x*32 + jl;
    float acc[BB];
    #pragma unroll
    for (int b = 0; b < BB; b++) acc[b] = 0.f;
    for (int k = ks*64; k < ks*64 + 64; k++) {
        float wv = w2[k*256 + j];
        #pragma unroll
        for (int b = 0; b < BB; b++) acc[b] += d_h512[b*512 + k]*wv;
    }
    __shared__ float sh[8][32][BB];
    #pragma unroll
    for (int b = 0; b < BB; b++) sh[ks][jl][b] = acc[b];
    __syncthreads();
    if (ks == 0) {
        #pragma unroll
        for (int b = 0; b < BB; b++) {
            float s = 0.f;
            #pragma unroll
            for (int i = 0; i < 8; i++) s += sh[i][jl][b];
            acc[b] = s + b2[j];
        }
        float m = 0.f;
        #pragma unroll
        for (int b = 0; b < BB; b++) m += acc[b];
        m *= (1.f/BB);
        float var = 0.f;
        #pragma unroll
        for (int b = 0; b < BB; b++) { float d = acc[b]-m; var += d*d; }
        var *= (1.f/BB);
        float sc = rsqrtf(var + 1e-5f)*g7[j], bb = b7[j];
        #pragma unroll
        for (int b = 0; b < BB; b++) {
            float o = (acc[b]-m)*sc + bb;
            d_h256[b*256 + j] = o > 0.f ? o : 0.2f*o;
        }
    }
}

__global__ void k_head3(const float* __restrict__ w3, const float* __restrict__ b3,
                        float* __restrict__ out) {
    int jl = threadIdx.x & 63, ks = threadIdx.x >> 6;
    float acc[BB];
    #pragma unroll
    for (int b = 0; b < BB; b++) acc[b] = 0.f;
    if (jl < 40) {
        for (int k = ks*64; k < ks*64 + 64; k++) {
            float wv = w3[k*40 + jl];
            #pragma unroll
            for (int b = 0; b < BB; b++) acc[b] += d_h256[b*256 + k]*wv;
        }
    }
    __shared__ float sh[4][64][BB];
    #pragma unroll
    for (int b = 0; b < BB; b++) sh[ks][jl][b] = acc[b];
    __syncthreads();
    if (ks == 0 && jl < 40) {
        #pragma unroll
        for (int b = 0; b < BB; b++) {
            float s = b3[jl];
            #pragma unroll
            for (int i = 0; i < 4; i++) s += sh[i][jl][b];
            out[b*40 + jl] = s;
        }
    }
}

// ---------------- launch ----------------
extern "C" void kernel_launch(void* const* d_in, const int* in_sizes, int n_in,
                              void* d_out, int out_size) {
    const float* x     = (const float*)d_in[0];
    const float* w0    = (const float*)d_in[1];
    const float* b0    = (const float*)d_in[2];
    const float* g0    = (const float*)d_in[3];
    const float* be0   = (const float*)d_in[4];
    const float* wr    = (const float*)d_in[5];
    const float* br    = (const float*)d_in[6];
    const float* gr    = (const float*)d_in[7];
    const float* ber   = (const float*)d_in[8];
    const float* W     = (const float*)d_in[9];
    const float* Bv    = (const float*)d_in[10];
    const float* G     = (const float*)d_in[11];
    const float* Be    = (const float*)d_in[12];
    const float* wconv = (const float*)d_in[13];
    const float* gf    = (const float*)d_in[14];
    const float* bef   = (const float*)d_in[15];
    const float* w1    = (const float*)d_in[16];
    const float* g6    = (const float*)d_in[17];
    const float* b6    = (const float*)d_in[18];
    const float* w2    = (const float*)d_in[19];
    const float* b2    = (const float*)d_in[20];
    const float* g7    = (const float*)d_in[21];
    const float* b7    = (const float*)d_in[22];
    const float* w3    = (const float*)d_in[23];
    const float* b3    = (const float*)d_in[24];
    float* out = (float*)d_out;

    static int smem_set = 0;
    if (!smem_set) {
        cudaFuncSetAttribute(k_conv_mma, cudaFuncAttributeMaxDynamicSharedMemorySize, SMEM_CONV);
        cudaFuncSetAttribute(k_knn, cudaFuncAttributeMaxDynamicSharedMemorySize, KNN_SMEM);
        smem_set = 1;
    }

    // graph build (k_knn kept in the 4th = captured slot)
    k_begin<<<256, 256>>>(wconv);
    k_prep<<<64, 256>>>(x);
    k_l0mm<<<4096, 256>>>(x, w0, wr, br);
    k_knn<<<512, 256, KNN_SMEM>>>();
    k_scanA<<<16, 1024>>>();
    k_scanB<<<64, 256>>>();
    k_fill<<<64, 256>>>();

    // layer 0
    k_gather_stats<<<4096, 256>>>(b0, 0);
    k_post0_mm<<<256, 256>>>(g0, be0, gr, ber, W);

    // layers 1..3
    k_gather_stats<<<4096, 256>>>(Bv, 1);
    k_postL_mm<<<256, 256>>>(1, G, Be, W + 4096);
    k_gather_stats<<<4096, 256>>>(Bv + 64, 2);
    k_postL_mm<<<256, 256>>>(2, G + 64, Be + 64, W + 8192);
    k_gather_stats<<<4096, 256>>>(Bv + 128, 3);
    k_post3<<<4096, 256>>>(G + 128, Be + 128);

    // conv 256 -> 1024 (fp16 3-term) + fused stats/extrema, then pool
    dim3 cgrid(128, 8);
    k_conv_mma<<<cgrid, 256, SMEM_CONV>>>();
    k_reduce<<<1024, 256>>>(gf, bef);

    // head
    k_head1<<<32, 256>>>(w1, g6, b6);
    k_head2<<<8, 256>>>(w2, b2, g7, b7);
    k_head3<<<1, 256>>>(w3, b3, out);
}

// round 12
// speedup vs baseline: 1.1054x; 1.1054x over previous
#include <cuda_runtime.h>
#include <cuda_fp16.h>
#include <float.h>
#include <stdint.h>

// ---------------- problem constants ----------------
#define BB    8
#define NPT   2048
#define BNP   16384          // BB*NPT
#define KNN   20
#define CH    64
#define FD    256            // 4*CH
#define EMB   1024

// ---------------- scratch (device globals; no mallocs allowed) ----------------
__device__ float4 d_P4[BB*NPT];
__device__ int   d_nbr[BNP*KNN];
__device__ int   d_deg[BNP];
__device__ int   d_rowstart[BNP+1];
__device__ int   d_cursor[BNP];
__device__ int   d_bsum[16];
__device__ int   d_rev[BNP*KNN];
__device__ float d_F[BNP*FD];
__device__ float d_sup[BNP*CH];
__device__ float d_z[BNP*CH];
__device__ float d_rz[BNP*CH];
__device__ __half d_Yh[(size_t)EMB*BNP];   // conv output fp16 [e][p], 32 MB
__device__ unsigned d_maxK[BB*EMB], d_minK[BB*EMB];  // per (b,e) raw-y extrema keys
__device__ float d_x12[BB*2*EMB];
__device__ float d_h512[BB*512];
__device__ float d_h256[BB*256];
__device__ float d_sumA[4*CH], d_sqA[4*CH];
__device__ float d_sumB[CH], d_sqB[CH];
__device__ float d_sumY[EMB], d_sqY[EMB];
__device__ __half d_Ah[EMB*FD], d_Al[EMB*FD];   // wconv fp16 hi/lo
__device__ __half d_Fh[BNP*FD], d_Fl[BNP*FD];   // features fp16 hi/lo

// ---------------- helpers ----------------
__device__ __forceinline__ uint32_t smem_u32(const void* p) {
    uint32_t a;
    asm("{ .reg .u64 t; cvta.to.shared.u64 t, %1; cvt.u32.u64 %0, t; }" : "=r"(a) : "l"(p));
    return a;
}
__device__ __forceinline__ void ldm_x4(uint32_t* r, uint32_t addr) {
    asm volatile("ldmatrix.sync.aligned.m8n8.x4.shared.b16 {%0,%1,%2,%3}, [%4];"
        : "=r"(r[0]), "=r"(r[1]), "=r"(r[2]), "=r"(r[3]) : "r"(addr));
}
__device__ __forceinline__ void mma16816h(float* c, const uint32_t* a, const uint32_t* b) {
    asm volatile(
        "mma.sync.aligned.m16n8k16.row.col.f32.f16.f16.f32 "
        "{%0,%1,%2,%3}, {%4,%5,%6,%7}, {%8,%9}, {%0,%1,%2,%3};"
        : "+f"(c[0]), "+f"(c[1]), "+f"(c[2]), "+f"(c[3])
        : "r"(a[0]), "r"(a[1]), "r"(a[2]), "r"(a[3]), "r"(b[0]), "r"(b[1]));
}
__device__ __forceinline__ void cp16(uint32_t sdst, const void* gsrc) {
    asm volatile("cp.async.cg.shared.global [%0], [%1], 16;" :: "r"(sdst), "l"(gsrc));
}
#define CP_COMMIT() asm volatile("cp.async.commit_group;" ::: "memory")
#define CP_WAIT0()  asm volatile("cp.async.wait_group 0;" ::: "memory")

__device__ __forceinline__ unsigned fkey(float f) {
    unsigned u = __float_as_uint(f);
    return (u & 0x80000000u) ? ~u : (u | 0x80000000u);
}
__device__ __forceinline__ float unkey(unsigned k) {
    return (k & 0x80000000u) ? __uint_as_float(k & 0x7fffffffu) : __uint_as_float(~k);
}

// ---------------- begin: zero stats/deg + wconv fp16 hi/lo split -------------
__global__ void k_begin(const float* __restrict__ w) {
    int t = blockIdx.x*256 + threadIdx.x;   // 65536 threads
    if (t < BNP) d_deg[t] = 0;
    if (t < 4*CH) { d_sumA[t] = 0.f; d_sqA[t] = 0.f; }
    if (t < CH)   { d_sumB[t] = 0.f; d_sqB[t] = 0.f; }
    if (t < EMB)  { d_sumY[t] = 0.f; d_sqY[t] = 0.f; }
    if (t < BB*EMB) { d_maxK[t] = 0u; d_minK[t] = 0xFFFFFFFFu; }
    float4 x = ((const float4*)w)[t];       // EMB*FD/4 = 65536
    __half h0 = __float2half_rn(x.x), h1 = __float2half_rn(x.y);
    __half h2 = __float2half_rn(x.z), h3 = __float2half_rn(x.w);
    __half l0 = __float2half_rn(x.x - __half2float(h0));
    __half l1 = __float2half_rn(x.y - __half2float(h1));
    __half l2 = __float2half_rn(x.z - __half2float(h2));
    __half l3 = __float2half_rn(x.w - __half2float(h3));
    ((__half2*)d_Ah)[t*2]   = __half2(h0, h1);
    ((__half2*)d_Ah)[t*2+1] = __half2(h2, h3);
    ((__half2*)d_Al)[t*2]   = __half2(l0, l1);
    ((__half2*)d_Al)[t*2+1] = __half2(l2, l3);
}

// pts[b,c,n] = x[b, (c*N+n)%3, (c*N+n)/3]
__global__ void k_prep(const float* __restrict__ x) {
    int t = blockIdx.x*256 + threadIdx.x;
    if (t >= BNP) return;
    int b = t >> 11, n = t & 2047;
    const float* xb = x + b*3*NPT;
    float v[3]; float acc = 0.f;
    #pragma unroll
    for (int c = 0; c < 3; c++) {
        int L = c*NPT + n;
        v[c] = xb[(L % 3)*NPT + (L / 3)];
        acc += v[c]*v[c];
    }
    d_P4[t] = make_float4(v[0], v[1], v[2], acc);
}

// identical arithmetic in both KNN passes (explicit intrinsics -> deterministic)
__device__ __forceinline__ float pdist(float4 q, float4 pm) {
    float dot = __fmaf_rn(q.x, pm.x, __fmaf_rn(q.y, pm.y, __fmul_rn(q.z, pm.z)));
    return __fadd_rn(__fmaf_rn(2.f, dot, -q.w), -pm.w);
}

// ---------------- knn: two-pass threshold, 2 rows per warp, interleaved chains
__global__ void __launch_bounds__(256) k_knn() {
    __shared__ float4 sP[NPT];               // 32 KB
    __shared__ float sv[8][2][128];
    __shared__ int   si[8][2][128];
    int b = blockIdx.x >> 7;                 // 8 batches x 128 chunks
    int chunk = blockIdx.x & 127;            // 16 rows per chunk
    for (int i = threadIdx.x; i < NPT; i += 256)
        sP[i] = d_P4[b*NPT + i];
    __syncthreads();

    int warp = threadIdx.x >> 5, lane = threadIdx.x & 31;
    int n0 = chunk*16 + warp*2;
    float4 q0 = sP[n0], q1 = sP[n0 + 1];

    // pass A: shared pm loads, per-lane maxes for both rows
    float m00 = -FLT_MAX, m01 = -FLT_MAX, m10 = -FLT_MAX, m11 = -FLT_MAX;
    for (int m = lane; m < NPT; m += 64) {
        float4 pa = sP[m], pb = sP[m + 32];
        m00 = fmaxf(m00, pdist(q0, pa)); m01 = fmaxf(m01, pdist(q0, pb));
        m10 = fmaxf(m10, pdist(q1, pa)); m11 = fmaxf(m11, pdist(q1, pb));
    }
    float vmax0 = fmaxf(m00, m01), vmax1 = fmaxf(m10, m11);

    // tau = 20th largest of 32 lane maxima; both rows' chains interleaved
    unsigned mk0 = fkey(vmax0), mk1 = fkey(vmax1);
    unsigned tk0 = 0, tk1 = 0;
    #pragma unroll 1
    for (int k = 0; k < KNN; k++) {
        tk0 = __reduce_max_sync(0xffffffffu, mk0);
        tk1 = __reduce_max_sync(0xffffffffu, mk1);
        unsigned b0 = __ballot_sync(0xffffffffu, mk0 == tk0);
        unsigned b1 = __ballot_sync(0xffffffffu, mk1 == tk1);
        if (lane == __ffs(b0) - 1) mk0 = 0;
        if (lane == __ffs(b1) - 1) mk1 = 0;
    }
    float tval0 = unkey(tk0), tval1 = unkey(tk1);

    // pass B: shared pm loads, compact survivors for both rows
    int base0 = 0, base1 = 0;
    for (int m = lane; m < NPT; m += 32) {
        float4 pm = sP[m];
        float pd0 = pdist(q0, pm);
        float pd1 = pdist(q1, pm);
        bool s0 = (pd0 >= tval0);
        unsigned k0 = __ballot_sync(0xffffffffu, s0);
        if (s0) {
            int pos = base0 + __popc(k0 & ((1u << lane) - 1));
            if (pos < 128) { sv[warp][0][pos] = pd0; si[warp][0][pos] = m; }
        }
        base0 += __popc(k0);
        bool s1 = (pd1 >= tval1);
        unsigned k1 = __ballot_sync(0xffffffffu, s1);
        if (s1) {
            int pos = base1 + __popc(k1 & ((1u << lane) - 1));
            if (pos < 128) { sv[warp][1][pos] = pd1; si[warp][1][pos] = m; }
        }
        base1 += __popc(k1);
    }
    __syncwarp();

    // distribute <=4 survivors per lane per row; sort desc (value, index asc)
    int S0 = base0 < 128 ? base0 : 128;
    int S1 = base1 < 128 ? base1 : 128;
    float v0[4], v1[4]; int id0[4], id1[4];
    #pragma unroll
    for (int j = 0; j < 4; j++) {
        int idx = lane + j*32;
        if (idx < S0) { v0[j] = sv[warp][0][idx]; id0[j] = si[warp][0][idx]; }
        else          { v0[j] = -FLT_MAX;         id0[j] = 0x7fffffff; }
        if (idx < S1) { v1[j] = sv[warp][1][idx]; id1[j] = si[warp][1][idx]; }
        else          { v1[j] = -FLT_MAX;         id1[j] = 0x7fffffff; }
    }
    #define CE(V_, I_, A_, B_) { \
        bool sw_ = (V_[B_] > V_[A_]) || (V_[B_] == V_[A_] && I_[B_] < I_[A_]); \
        if (sw_) { float tv_ = V_[A_]; V_[A_] = V_[B_]; V_[B_] = tv_; \
                   int ti_ = I_[A_]; I_[A_] = I_[B_]; I_[B_] = ti_; } }
    CE(v0,id0,0,1) CE(v0,id0,2,3) CE(v0,id0,0,2) CE(v0,id0,1,3) CE(v0,id0,1,2)
    CE(v1,id1,0,1) CE(v1,id1,2,3) CE(v1,id1,0,2) CE(v1,id1,1,3) CE(v1,id1,1,2)
    #undef CE

    // exact top-20 pop merge, both rows interleaved per iteration
    int pg0 = b*NPT + n0, pg1 = pg0 + 1;
    #pragma unroll 1
    for (int k = 0; k < KNN; k++) {
        unsigned a0 = fkey(v0[0]);
        unsigned a1 = fkey(v1[0]);
        unsigned be0 = __reduce_max_sync(0xffffffffu, a0);
        unsigned be1 = __reduce_max_sync(0xffffffffu, a1);
        int c0 = (a0 == be0) ? id0[0] : 0x7fffffff;
        int c1 = (a1 == be1) ? id1[0] : 0x7fffffff;
        int bmi0 = __reduce_min_sync(0xffffffffu, c0);
        int bmi1 = __reduce_min_sync(0xffffffffu, c1);
        if (a0 == be0 && id0[0] == bmi0) {
            v0[0] = v0[1]; id0[0] = id0[1];
            v0[1] = v0[2]; id0[1] = id0[2];
            v0[2] = v0[3]; id0[2] = id0[3];
            v0[3] = -FLT_MAX; id0[3] = 0x7fffffff;
        }
        if (a1 == be1 && id1[0] == bmi1) {
            v1[0] = v1[1]; id1[0] = id1[1];
            v1[1] = v1[2]; id1[1] = id1[2];
            v1[2] = v1[3]; id1[2] = id1[3];
            v1[3] = -FLT_MAX; id1[3] = 0x7fffffff;
        }
        if (lane == 0) {
            int qg0 = b*NPT + bmi0;
            int qg1 = b*NPT + bmi1;
            d_nbr[pg0*KNN + k] = qg0;
            d_nbr[pg1*KNN + k] = qg1;
            atomicAdd(&d_deg[qg0], 1);
            atomicAdd(&d_deg[qg1], 1);
        }
    }
}

// ---------------- parallel scan ----------------
__global__ void k_scanA() {
    int t = threadIdx.x, g = blockIdx.x*1024 + t;
    int v = d_deg[g];
    int lane = t & 31, wid = t >> 5;
    int vv = v;
    #pragma unroll
    for (int o = 1; o < 32; o <<= 1) { int u = __shfl_up_sync(0xffffffffu, vv, o); if (lane >= o) vv += u; }
    __shared__ int ws[32];
    if (lane == 31) ws[wid] = vv;
    __syncthreads();
    if (wid == 0) {
        int w = ws[lane];
        #pragma unroll
        for (int o = 1; o < 32; o <<= 1) { int u = __shfl_up_sync(0xffffffffu, w, o); if (lane >= o) w += u; }
        ws[lane] = w;
    }
    __syncthreads();
    int incl = vv + (wid ? ws[wid-1] : 0);
    d_rowstart[g] = incl - v;
    if (t == 1023) d_bsum[blockIdx.x] = incl;
}

__global__ void k_scanB() {
    int g = blockIdx.x*256 + threadIdx.x;
    int sb = g >> 10;
    int off = 0;
    #pragma unroll 1
    for (int i = 0; i < sb; i++) off += d_bsum[i];
    int rs = d_rowstart[g] + off;
    d_rowstart[g] = rs;
    d_cursor[g] = rs;
    if (g == BNP - 1) {
        int tot = 0;
        #pragma unroll
        for (int i = 0; i < 16; i++) tot += d_bsum[i];
        d_rowstart[BNP] = tot;
    }
}

__global__ void k_fill() {
    int p = blockIdx.x*256 + threadIdx.x;
    if (p >= BNP) return;
    #pragma unroll
    for (int k = 0; k < KNN; k++) {
        int q = d_nbr[p*KNN + k];
        int pos = atomicAdd(&d_cursor[q], 1);
        d_rev[pos] = p;
    }
}

// ---------------- layer 0: sup0 = flat@w0 ; rz = flat@wr + br (+ rz stats) ----
__global__ void k_l0mm(const float* __restrict__ x, const float* __restrict__ w0,
                       const float* __restrict__ wr, const float* __restrict__ br) {
    int tid = threadIdx.x;
    int t = blockIdx.x*256 + tid;
    int p = t >> 6, c = t & 63;
    int b = p >> 11, n = p & 2047;
    const float* xb = x + b*3*NPT;
    float x0 = xb[n], x1 = xb[NPT + n], x2 = xb[2*NPT + n];
    d_sup[t] = x0*w0[c] + x1*w0[64+c] + x2*w0[128+c];
    float rz = x0*wr[c] + x1*wr[64+c] + x2*wr[128+c] + br[c];
    d_rz[t] = rz;
    __shared__ float s1[256], s2[256];
    s1[tid] = rz; s2[tid] = rz*rz;
    __syncthreads();
    if (tid < 64) {
        float a = s1[tid] + s1[64+tid] + s1[128+tid] + s1[192+tid];
        float q = s2[tid] + s2[64+tid] + s2[128+tid] + s2[192+tid];
        atomicAdd(&d_sumB[tid], a);
        atomicAdd(&d_sqB[tid], q);
    }
}

// ---------------- gather (reverse CSR) + bias + z stats ----------------
__global__ void k_gather_stats(const float* __restrict__ bias, int layer) {
    int t = threadIdx.x;
    int q = blockIdx.x*4 + (t >> 6);
    int c = t & 63;
    float acc = bias[c];
    int s0 = d_rowstart[q], e0 = d_rowstart[q+1];
    for (int i = s0; i < e0; i++) acc += d_sup[d_rev[i]*64 + c];
    d_z[q*64 + c] = acc;
    __shared__ float s1[256], s2[256];
    s1[t] = acc; s2[t] = acc*acc;
    __syncthreads();
    if (t < 64) {
        float a = s1[t] + s1[64+t] + s1[128+t] + s1[192+t];
        float qq = s2[t] + s2[64+t] + s2[128+t] + s2[192+t];
        atomicAdd(&d_sumA[layer*64 + t], a);
        atomicAdd(&d_sqA[layer*64 + t], qq);
    }
}

// ---------------- fused post (layer 0) + mm for layer 1 ----------------
__global__ void __launch_bounds__(256) k_post0_mm(
        const float* __restrict__ g0, const float* __restrict__ be0,
        const float* __restrict__ gr, const float* __restrict__ ber,
        const float* __restrict__ W1) {
    __shared__ float Hs[64*64];
    __shared__ float Ws[64*64];
    int tid = threadIdx.x;
    int p0 = blockIdx.x*64;
    int c = tid & 63, rg = tid >> 6;
    float mA = d_sumA[c]*(1.f/BNP);
    float vA = d_sqA[c]*(1.f/BNP) - mA*mA;
    float sA = rsqrtf(vA + 1e-5f)*g0[c], bA = be0[c];
    float mB = d_sumB[c]*(1.f/BNP);
    float vB = d_sqB[c]*(1.f/BNP) - mB*mB;
    float sB = rsqrtf(vB + 1e-5f)*gr[c], bB = ber[c];
    #pragma unroll
    for (int i = 0; i < 16; i++) {
        int r = rg + i*4, p = p0 + r;
        float o = fmaxf((d_z[p*64+c] - mA)*sA + bA, 0.f);
        float rr = (d_rz[p*64+c] - mB)*sB + bB;
        float h = fmaxf(o + rr, 0.f);
        Hs[r*64+c] = h;
        d_F[p*FD + c] = h;
        __half hi = __float2half_rn(h);
        d_Fh[p*FD + c] = hi;
        d_Fl[p*FD + c] = __float2half_rn(h - __half2float(hi));
    }
    for (int i = tid; i < 4096; i += 256) Ws[i] = W1[i];
    __syncthreads();
    for (int r = rg; r < 64; r += 4) {
        float acc = 0.f;
        #pragma unroll 16
        for (int k = 0; k < 64; k++) acc += Hs[r*64+k]*Ws[k*64+c];
        d_sup[(p0+r)*64+c] = acc;
    }
}

// ---------------- fused post (layers 1,2) + mm for next layer ----------------
__global__ void __launch_bounds__(256) k_postL_mm(int layer,
        const float* __restrict__ G, const float* __restrict__ Be,
        const float* __restrict__ Wn) {
    __shared__ float Hs[64*64];
    __shared__ float Ws[64*64];
    int tid = threadIdx.x;
    int p0 = blockIdx.x*64;
    int c = tid & 63, rg = tid >> 6;
    float m = d_sumA[layer*64+c]*(1.f/BNP);
    float v = d_sqA[layer*64+c]*(1.f/BNP) - m*m;
    float sc = rsqrtf(v + 1e-5f)*G[c], bc = Be[c];
    #pragma unroll
    for (int i = 0; i < 16; i++) {
        int r = rg + i*4, p = p0 + r;
        float a = fmaxf((d_z[p*64+c] - m)*sc + bc, 0.f);
        float h = fmaxf(a + d_F[p*FD + (layer-1)*64 + c], 0.f);
        Hs[r*64+c] = h;
        d_F[p*FD + layer*64 + c] = h;
        __half hi = __float2half_rn(h);
        d_Fh[p*FD + layer*64 + c] = hi;
        d_Fl[p*FD + layer*64 + c] = __float2half_rn(h - __half2float(hi));
    }
    for (int i = tid; i < 4096; i += 256) Ws[i] = Wn[i];
    __syncthreads();
    for (int r = rg; r < 64; r += 4) {
        float acc = 0.f;
        #pragma unroll 16
        for (int k = 0; k < 64; k++) acc += Hs[r*64+k]*Ws[k*64+c];
        d_sup[(p0+r)*64+c] = acc;
    }
}

// ---------------- post layer 3 ----------------
__global__ void k_post3(const float* __restrict__ G, const float* __restrict__ Be) {
    int t = blockIdx.x*256 + threadIdx.x;
    int p = t >> 6, c = t & 63;
    float m = d_sumA[3*64+c]*(1.f/BNP);
    float v = d_sqA[3*64+c]*(1.f/BNP) - m*m;
    float a = fmaxf((d_z[t] - m)*rsqrtf(v + 1e-5f)*G[c] + Be[c], 0.f);
    float h = fmaxf(a + d_F[p*FD + 2*64 + c], 0.f);
    __half hi = __float2half_rn(h);
    d_Fh[p*FD + 3*64 + c] = hi;
    d_Fl[p*FD + 3*64 + c] = __float2half_rn(h - __half2float(hi));
}

// ---------------- conv GEMM: fp16 3-term split, cp.async 2-stage -------------
// C = Ah.Bh + Al.Bh + Ah.Bl ; epilogue stores fp16 y + stats + raw extrema
#define PITCH 80
#define TSZ   (128*PITCH)
#define STAGE (4*TSZ)
#define SMEM_CONV (2*STAGE)   // 81920 B

__global__ void __launch_bounds__(256) k_conv_mma() {
    extern __shared__ __align__(16) uint8_t sm[];
    uint32_t sb = smem_u32(sm);

    int tid = threadIdx.x, wid = tid >> 5, lane = tid & 31;
    int warp_m = wid >> 2, warp_n = wid & 3;
    int bn = blockIdx.x;
    int bm = blockIdx.y;
    int bb = bn >> 4;                       // batch of this p-tile

    const uint4* gAh = (const uint4*)d_Ah;
    const uint4* gAl = (const uint4*)d_Al;
    const uint4* gBh = (const uint4*)d_Fh;
    const uint4* gBl = (const uint4*)d_Fl;

    float C[4][4][4];
    #pragma unroll
    for (int i = 0; i < 4; i++)
        #pragma unroll
        for (int j = 0; j < 4; j++)
            #pragma unroll
            for (int q = 0; q < 4; q++) C[i][j][q] = 0.f;

    int rowA  = warp_m*64 + (lane & 15);
    int halfA = lane >> 4;
    uint32_t oAh = rowA*PITCH + halfA*16;
    uint32_t oAl = TSZ + rowA*PITCH + halfA*16;
    int rowB  = warp_n*32 + (lane & 7) + ((lane >> 4) << 3);
    int halfB = (lane >> 3) & 1;
    uint32_t oBh = 2*TSZ + rowB*PITCH + halfB*16;
    uint32_t oBl = 3*TSZ + rowB*PITCH + halfB*16;

    auto issue = [&](int kc, int s) {
        uint32_t base = sb + s*STAGE;
        #pragma unroll
        for (int l = 0; l < 2; l++) {
            int i = tid + l*256;
            int row = i >> 2, c = i & 3;
            uint32_t so = row*PITCH + c*16;
            size_t ga = (size_t)(bm*128 + row)*32 + kc*4 + c;
            size_t gb = (size_t)(bn*128 + row)*32 + kc*4 + c;
            cp16(base + so,          gAh + ga);
            cp16(base + TSZ + so,    gAl + ga);
            cp16(base + 2*TSZ + so,  gBh + gb);
            cp16(base + 3*TSZ + so,  gBl + gb);
        }
        CP_COMMIT();
    };

    issue(0, 0);
    for (int kc = 0; kc < 8; kc++) {
        int s = kc & 1;
        CP_WAIT0();
        __syncthreads();       // data ready AND all warps done with prior compute
        if (kc + 1 < 8) issue(kc + 1, s ^ 1);
        uint32_t stb = sb + s*STAGE;

        #pragma unroll
        for (int ksub = 0; ksub < 2; ksub++) {
            uint32_t koff = (ksub*2)*16;
            uint32_t bh[8], bl[8];
            ldm_x4(bh + 0, stb + oBh + koff);
            ldm_x4(bh + 4, stb + oBh + koff + 16*PITCH);
            ldm_x4(bl + 0, stb + oBl + koff);
            ldm_x4(bl + 4, stb + oBl + koff + 16*PITCH);
            #pragma unroll
            for (int mt = 0; mt < 4; mt++) {
                uint32_t ah[4], al[4];
                ldm_x4(ah, stb + oAh + koff + mt*16*PITCH);
                ldm_x4(al, stb + oAl + koff + mt*16*PITCH);
                #pragma unroll
                for (int nt = 0; nt < 4; nt++) {
                    const uint32_t* ph = &bh[(nt >> 1)*4 + (nt & 1)*2];
                    const uint32_t* pl = &bl[(nt >> 1)*4 + (nt & 1)*2];
                    mma16816h(C[mt][nt], ah, ph);
                    mma16816h(C[mt][nt], al, ph);
                    mma16816h(C[mt][nt], ah, pl);
                }
            }
        }
        // no trailing sync: next iteration's barrier orders compute before reissue
    }

    // epilogue: fp16 store + per-e BN partial stats + raw extrema
    #pragma unroll
    for (int mt = 0; mt < 4; mt++) {
        int e = bm*128 + warp_m*64 + mt*16 + (lane >> 2);
        float s0 = 0.f, q0 = 0.f, s1 = 0.f, q1 = 0.f;
        float mx0 = -FLT_MAX, mn0 = FLT_MAX, mx1 = -FLT_MAX, mn1 = FLT_MAX;
        #pragma unroll
        for (int nt = 0; nt < 4; nt++) {
            int p = bn*128 + warp_n*32 + nt*8 + (lane & 3)*2;
            float a0 = C[mt][nt][0], a1 = C[mt][nt][1];
            float a2 = C[mt][nt][2], a3 = C[mt][nt][3];
            *(__half2*)&d_Yh[(size_t)e*BNP + p] =
                __half2(__float2half_rn(a0), __float2half_rn(a1));
            *(__half2*)&d_Yh[(size_t)(e + 8)*BNP + p] =
                __half2(__float2half_rn(a2), __float2half_rn(a3));
            s0 += a0 + a1; q0 += a0*a0 + a1*a1;
            s1 += a2 + a3; q1 += a2*a2 + a3*a3;
            mx0 = fmaxf(mx0, fmaxf(a0, a1)); mn0 = fminf(mn0, fminf(a0, a1));
            mx1 = fmaxf(mx1, fmaxf(a2, a3)); mn1 = fminf(mn1, fminf(a2, a3));
        }
        #pragma unroll
        for (int o = 1; o < 4; o <<= 1) {
            s0 += __shfl_xor_sync(0xffffffffu, s0, o);
            q0 += __shfl_xor_sync(0xffffffffu, q0, o);
            s1 += __shfl_xor_sync(0xffffffffu, s1, o);
            q1 += __shfl_xor_sync(0xffffffffu, q1, o);
            mx0 = fmaxf(mx0, __shfl_xor_sync(0xffffffffu, mx0, o));
            mn0 = fminf(mn0, __shfl_xor_sync(0xffffffffu, mn0, o));
            mx1 = fmaxf(mx1, __shfl_xor_sync(0xffffffffu, mx1, o));
            mn1 = fminf(mn1, __shfl_xor_sync(0xffffffffu, mn1, o));
        }
        if ((lane & 3) == 0) {
            atomicAdd(&d_sumY[e], s0);     atomicAdd(&d_sqY[e], q0);
            atomicAdd(&d_sumY[e + 8], s1); atomicAdd(&d_sqY[e + 8], q1);
            atomicMax(&d_maxK[bb*EMB + e], fkey(mx0));
            atomicMin(&d_minK[bb*EMB + e], fkey(mn0));
            atomicMax(&d_maxK[bb*EMB + e + 8], fkey(mx1));
            atomicMin(&d_minK[bb*EMB + e + 8], fkey(mn1));
        }
    }
}

// ---------------- BN + leaky + mean pool (max pool from exact extrema) -------
__global__ void k_reduce(const float* __restrict__ gf, const float* __restrict__ bef) {
    int e = blockIdx.x;
    const __half2* y2 = (const __half2*)(d_Yh + (size_t)e*BNP);
    int t = threadIdx.x, lane = t & 31, w = t >> 5;
    float mu = d_sumY[e]*(1.f/BNP);
    float var = d_sqY[e]*(1.f/BNP) - mu*mu;
    float sc = rsqrtf(var + 1e-5f)*gf[e], sh = bef[e];
    __shared__ float wsum[8];
    for (int b = 0; b < BB; b++) {
        float sm = 0.f;
        const __half2* yb = y2 + b*(NPT/2);
        for (int j = t; j < NPT/2; j += 256) {
            float2 v2 = __half22float2(yb[j]);
            float v0 = (v2.x - mu)*sc + sh; v0 = v0 > 0.f ? v0 : 0.2f*v0;
            float v1 = (v2.y - mu)*sc + sh; v1 = v1 > 0.f ? v1 : 0.2f*v1;
            sm += v0 + v1;
        }
        #pragma unroll
        for (int o = 16; o; o >>= 1) sm += __shfl_xor_sync(0xffffffffu, sm, o);
        if (lane == 0) wsum[w] = sm;
        __syncthreads();
        if (t == 0) {
            float SM = 0.f;
            #pragma unroll
            for (int i = 0; i < 8; i++) SM += wsum[i];
            unsigned mk = (sc >= 0.f) ? d_maxK[b*EMB + e] : d_minK[b*EMB + e];
            float raw = unkey(mk);
            float v = (raw - mu)*sc + sh;
            v = v > 0.f ? v : 0.2f*v;
            d_x12[b*2*EMB + e] = v;
            d_x12[b*2*EMB + EMB + e] = SM*(1.f/NPT);
        }
        __syncthreads();
    }
}

// ---------------- head (k-split parallel) ----------------
__global__ void k_head1(const float* __restrict__ w1, const float* __restrict__ g6,
                        const float* __restrict__ b6) {
    int jl = threadIdx.x & 15, ks = threadIdx.x >> 4;
    int j = blockIdx.x*16 + jl;
    float acc[BB];
    #pragma unroll
    for (int b = 0; b < BB; b++) acc[b] = 0.f;
    for (int k = ks*128; k < ks*128 + 128; k++) {
        float wv = w1[k*512 + j];
        #pragma unroll
        for (int b = 0; b < BB; b++) acc[b] += d_x12[b*2*EMB + k]*wv;
    }
    __shared__ float sh[16][16][BB];
    #pragma unroll
    for (int b = 0; b < BB; b++) sh[ks][jl][b] = acc[b];
    __syncthreads();
    if (ks == 0) {
        #pragma unroll
        for (int b = 0; b < BB; b++) {
            float s = 0.f;
            #pragma unroll
            for (int i = 0; i < 16; i++) s += sh[i][jl][b];
            acc[b] = s;
        }
        float m = 0.f;
        #pragma unroll
        for (int b = 0; b < BB; b++) m += acc[b];
        m *= (1.f/BB);
        float var = 0.f;
        #pragma unroll
        for (int b = 0; b < BB; b++) { float d = acc[b]-m; var += d*d; }
        var *= (1.f/BB);
        float sc = rsqrtf(var + 1e-5f)*g6[j], bb = b6[j];
        #pragma unroll
        for (int b = 0; b < BB; b++) {
            float o = (acc[b]-m)*sc + bb;
            d_h512[b*512 + j] = o > 0.f ? o : 0.2f*o;
        }
    }
}

__global__ void k_head2(const float* __restrict__ w2, const float* __restrict__ b2,
                        const float* __restrict__ g7, const float* __restrict__ b7) {
    int jl = threadIdx.x & 31, ks = threadIdx.x >> 5;
    int j = blockIdx.x*32 + jl;
    float acc[BB];
    #pragma unroll
    for (int b = 0; b < BB; b++) acc[b] = 0.f;
    for (int k = ks*64; k < ks*64 + 64; k++) {
        float wv = w2[k*256 + j];
        #pragma unroll
        for (int b = 0; b < BB; b++) acc[b] += d_h512[b*512 + k]*wv;
    }
    __shared__ float sh[8][32][BB];
    #pragma unroll
    for (int b = 0; b < BB; b++) sh[ks][jl][b] = acc[b];
    __syncthreads();
    if (ks == 0) {
        #pragma unroll
        for (int b = 0; b < BB; b++) {
            float s = 0.f;
            #pragma unroll
            for (int i = 0; i < 8; i++) s += sh[i][jl][b];
            acc[b] = s + b2[j];
        }
        float m = 0.f;
        #pragma unroll
        for (int b = 0; b < BB; b++) m += acc[b];
        m *= (1.f/BB);
        float var = 0.f;
        #pragma unroll
        for (int b = 0; b < BB; b++) { float d = acc[b]-m; var += d*d; }
        var *= (1.f/BB);
        float sc = rsqrtf(var + 1e-5f)*g7[j], bb = b7[j];
        #pragma unroll
        for (int b = 0; b < BB; b++) {
            float o = (acc[b]-m)*sc + bb;
            d_h256[b*256 + j] = o > 0.f ? o : 0.2f*o;
        }
    }
}

__global__ void k_head3(const float* __restrict__ w3, const float* __restrict__ b3,
                        float* __restrict__ out) {
    int jl = threadIdx.x & 63, ks = threadIdx.x >> 6;
    float acc[BB];
    #pragma unroll
    for (int b = 0; b < BB; b++) acc[b] = 0.f;
    if (jl < 40) {
        for (int k = ks*64; k < ks*64 + 64; k++) {
            float wv = w3[k*40 + jl];
            #pragma unroll
            for (int b = 0; b < BB; b++) acc[b] += d_h256[b*256 + k]*wv;
        }
    }
    __shared__ float sh[4][64][BB];
    #pragma unroll
    for (int b = 0; b < BB; b++) sh[ks][jl][b] = acc[b];
    __syncthreads();
    if (ks == 0 && jl < 40) {
        #pragma unroll
        for (int b = 0; b < BB; b++) {
            float s = b3[jl];
            #pragma unroll
            for (int i = 0; i < 4; i++) s += sh[i][jl][b];
            out[b*40 + jl] = s;
        }
    }
}

// ---------------- launch ----------------
extern "C" void kernel_launch(void* const* d_in, const int* in_sizes, int n_in,
                              void* d_out, int out_size) {
    const float* x     = (const float*)d_in[0];
    const float* w0    = (const float*)d_in[1];
    const float* b0    = (const float*)d_in[2];
    const float* g0    = (const float*)d_in[3];
    const float* be0   = (const float*)d_in[4];
    const float* wr    = (const float*)d_in[5];
    const float* br    = (const float*)d_in[6];
    const float* gr    = (const float*)d_in[7];
    const float* ber   = (const float*)d_in[8];
    const float* W     = (const float*)d_in[9];
    const float* Bv    = (const float*)d_in[10];
    const float* G     = (const float*)d_in[11];
    const float* Be    = (const float*)d_in[12];
    const float* wconv = (const float*)d_in[13];
    const float* gf    = (const float*)d_in[14];
    const float* bef   = (const float*)d_in[15];
    const float* w1    = (const float*)d_in[16];
    const float* g6    = (const float*)d_in[17];
    const float* b6    = (const float*)d_in[18];
    const float* w2    = (const float*)d_in[19];
    const float* b2    = (const float*)d_in[20];
    const float* g7    = (const float*)d_in[21];
    const float* b7    = (const float*)d_in[22];
    const float* w3    = (const float*)d_in[23];
    const float* b3    = (const float*)d_in[24];
    float* out = (float*)d_out;

    static int smem_set = 0;
    if (!smem_set) {
        cudaFuncSetAttribute(k_conv_mma, cudaFuncAttributeMaxDynamicSharedMemorySize, SMEM_CONV);
        smem_set = 1;
    }

    // graph build (k_knn kept in the 4th = captured slot)
    k_begin<<<256, 256>>>(wconv);
    k_prep<<<64, 256>>>(x);
    k_l0mm<<<4096, 256>>>(x, w0, wr, br);
    k_knn<<<1024, 256>>>();
    k_scanA<<<16, 1024>>>();
    k_scanB<<<64, 256>>>();
    k_fill<<<64, 256>>>();

    // layer 0
    k_gather_stats<<<4096, 256>>>(b0, 0);
    k_post0_mm<<<256, 256>>>(g0, be0, gr, ber, W);

    // layers 1..3
    k_gather_stats<<<4096, 256>>>(Bv, 1);
    k_postL_mm<<<256, 256>>>(1, G, Be, W + 4096);
    k_gather_stats<<<4096, 256>>>(Bv + 64, 2);
    k_postL_mm<<<256, 256>>>(2, G + 64, Be + 64, W + 8192);
    k_gather_stats<<<4096, 256>>>(Bv + 128, 3);
    k_post3<<<4096, 256>>>(G + 128, Be + 128);

    // conv 256 -> 1024 (fp16 3-term) + fused stats/extrema, then pool
    dim3 cgrid(128, 8);
    k_conv_mma<<<cgrid, 256, SMEM_CONV>>>();
    k_reduce<<<1024, 256>>>(gf, bef);

    // head
    k_head1<<<32, 256>>>(w1, g6, b6);
    k_head2<<<8, 256>>>(w2, b2, g7, b7);
    k_head3<<<1, 256>>>(w3, b3, out);
}

// round 13
// speedup vs baseline: 1.1826x; 1.0698x over previous
#include <cuda_runtime.h>
#include <cuda_fp16.h>
#include <float.h>
#include <stdint.h>

// ---------------- problem constants ----------------
#define BB    8
#define NPT   2048
#define BNP   16384          // BB*NPT
#define KNN   20
#define CH    64
#define FD    256            // 4*CH
#define EMB   1024

// ---------------- scratch (device globals; no mallocs allowed) ----------------
__device__ float4 d_P4[BB*NPT];
__device__ int   d_nbr[BNP*KNN];
__device__ int   d_deg[BNP];
__device__ int   d_rowstart[BNP+1];
__device__ int   d_cursor[BNP];
__device__ int   d_bsum[16];
__device__ int   d_rev[BNP*KNN];
__device__ float d_F[BNP*FD];
__device__ float d_sup[BNP*CH];
__device__ float d_z[BNP*CH];
__device__ float d_rz[BNP*CH];
__device__ __half d_Yh[(size_t)EMB*BNP];   // conv output fp16 [e][p], 32 MB
__device__ unsigned d_maxK[BB*EMB], d_minK[BB*EMB];  // per (b,e) raw-y extrema keys
__device__ float d_x12[BB*2*EMB];
__device__ float d_h512[BB*512];
__device__ float d_h256[BB*256];
__device__ float d_sumA[4*CH], d_sqA[4*CH];
__device__ float d_sumB[CH], d_sqB[CH];
__device__ float d_sumY[EMB], d_sqY[EMB];
__device__ __half d_Ah[EMB*FD], d_Al[EMB*FD];   // wconv fp16 hi/lo
__device__ __half d_Fh[BNP*FD], d_Fl[BNP*FD];   // features fp16 hi/lo

// ---------------- helpers ----------------
__device__ __forceinline__ uint32_t smem_u32(const void* p) {
    uint32_t a;
    asm("{ .reg .u64 t; cvta.to.shared.u64 t, %1; cvt.u32.u64 %0, t; }" : "=r"(a) : "l"(p));
    return a;
}
__device__ __forceinline__ void ldm_x4(uint32_t* r, uint32_t addr) {
    asm volatile("ldmatrix.sync.aligned.m8n8.x4.shared.b16 {%0,%1,%2,%3}, [%4];"
        : "=r"(r[0]), "=r"(r[1]), "=r"(r[2]), "=r"(r[3]) : "r"(addr));
}
__device__ __forceinline__ void mma16816h(float* c, const uint32_t* a, const uint32_t* b) {
    asm volatile(
        "mma.sync.aligned.m16n8k16.row.col.f32.f16.f16.f32 "
        "{%0,%1,%2,%3}, {%4,%5,%6,%7}, {%8,%9}, {%0,%1,%2,%3};"
        : "+f"(c[0]), "+f"(c[1]), "+f"(c[2]), "+f"(c[3])
        : "r"(a[0]), "r"(a[1]), "r"(a[2]), "r"(a[3]), "r"(b[0]), "r"(b[1]));
}
__device__ __forceinline__ void cp16(uint32_t sdst, const void* gsrc) {
    asm volatile("cp.async.cg.shared.global [%0], [%1], 16;" :: "r"(sdst), "l"(gsrc));
}
#define CP_COMMIT() asm volatile("cp.async.commit_group;" ::: "memory")
#define CP_WAIT0()  asm volatile("cp.async.wait_group 0;" ::: "memory")

__device__ __forceinline__ unsigned fkey(float f) {
    unsigned u = __float_as_uint(f);
    return (u & 0x80000000u) ? ~u : (u | 0x80000000u);
}
__device__ __forceinline__ float unkey(unsigned k) {
    return (k & 0x80000000u) ? __uint_as_float(k & 0x7fffffffu) : __uint_as_float(~k);
}

// ---------------- begin: zero stats/deg + wconv fp16 hi/lo split -------------
__global__ void k_begin(const float* __restrict__ w) {
    int t = blockIdx.x*256 + threadIdx.x;   // 65536 threads
    if (t < BNP) d_deg[t] = 0;
    if (t < 4*CH) { d_sumA[t] = 0.f; d_sqA[t] = 0.f; }
    if (t < CH)   { d_sumB[t] = 0.f; d_sqB[t] = 0.f; }
    if (t < EMB)  { d_sumY[t] = 0.f; d_sqY[t] = 0.f; }
    if (t < BB*EMB) { d_maxK[t] = 0u; d_minK[t] = 0xFFFFFFFFu; }
    float4 x = ((const float4*)w)[t];       // EMB*FD/4 = 65536
    __half h0 = __float2half_rn(x.x), h1 = __float2half_rn(x.y);
    __half h2 = __float2half_rn(x.z), h3 = __float2half_rn(x.w);
    __half l0 = __float2half_rn(x.x - __half2float(h0));
    __half l1 = __float2half_rn(x.y - __half2float(h1));
    __half l2 = __float2half_rn(x.z - __half2float(h2));
    __half l3 = __float2half_rn(x.w - __half2float(h3));
    ((__half2*)d_Ah)[t*2]   = __half2(h0, h1);
    ((__half2*)d_Ah)[t*2+1] = __half2(h2, h3);
    ((__half2*)d_Al)[t*2]   = __half2(l0, l1);
    ((__half2*)d_Al)[t*2+1] = __half2(l2, l3);
}

// pts[b,c,n] = x[b, (c*N+n)%3, (c*N+n)/3]
__global__ void k_prep(const float* __restrict__ x) {
    int t = blockIdx.x*256 + threadIdx.x;
    if (t >= BNP) return;
    int b = t >> 11, n = t & 2047;
    const float* xb = x + b*3*NPT;
    float v[3]; float acc = 0.f;
    #pragma unroll
    for (int c = 0; c < 3; c++) {
        int L = c*NPT + n;
        v[c] = xb[(L % 3)*NPT + (L / 3)];
        acc += v[c]*v[c];
    }
    d_P4[t] = make_float4(v[0], v[1], v[2], acc);
}

// identical arithmetic in both KNN passes (explicit intrinsics -> deterministic)
__device__ __forceinline__ float pdist(float4 q, float4 pm) {
    float dot = __fmaf_rn(q.x, pm.x, __fmaf_rn(q.y, pm.y, __fmul_rn(q.z, pm.z)));
    return __fadd_rn(__fmaf_rn(2.f, dot, -q.w), -pm.w);
}

// ---------------- knn: two-pass threshold, 2 rows per warp, interleaved chains
__global__ void __launch_bounds__(256) k_knn() {
    __shared__ float4 sP[NPT];               // 32 KB
    __shared__ float sv[8][2][128];
    __shared__ int   si[8][2][128];
    int b = blockIdx.x >> 7;                 // 8 batches x 128 chunks
    int chunk = blockIdx.x & 127;            // 16 rows per chunk
    for (int i = threadIdx.x; i < NPT; i += 256)
        sP[i] = d_P4[b*NPT + i];
    __syncthreads();

    int warp = threadIdx.x >> 5, lane = threadIdx.x & 31;
    int n0 = chunk*16 + warp*2;
    float4 q0 = sP[n0], q1 = sP[n0 + 1];

    // pass A: shared pm loads, per-lane maxes for both rows
    float m00 = -FLT_MAX, m01 = -FLT_MAX, m10 = -FLT_MAX, m11 = -FLT_MAX;
    for (int m = lane; m < NPT; m += 64) {
        float4 pa = sP[m], pb = sP[m + 32];
        m00 = fmaxf(m00, pdist(q0, pa)); m01 = fmaxf(m01, pdist(q0, pb));
        m10 = fmaxf(m10, pdist(q1, pa)); m11 = fmaxf(m11, pdist(q1, pb));
    }
    float vmax0 = fmaxf(m00, m01), vmax1 = fmaxf(m10, m11);

    // tau = 20th largest of 32 lane maxima; both rows' chains interleaved
    unsigned mk0 = fkey(vmax0), mk1 = fkey(vmax1);
    unsigned tk0 = 0, tk1 = 0;
    #pragma unroll 1
    for (int k = 0; k < KNN; k++) {
        tk0 = __reduce_max_sync(0xffffffffu, mk0);
        tk1 = __reduce_max_sync(0xffffffffu, mk1);
        unsigned b0 = __ballot_sync(0xffffffffu, mk0 == tk0);
        unsigned b1 = __ballot_sync(0xffffffffu, mk1 == tk1);
        if (lane == __ffs(b0) - 1) mk0 = 0;
        if (lane == __ffs(b1) - 1) mk1 = 0;
    }
    float tval0 = unkey(tk0), tval1 = unkey(tk1);

    // pass B: shared pm loads, compact survivors for both rows
    int base0 = 0, base1 = 0;
    for (int m = lane; m < NPT; m += 32) {
        float4 pm = sP[m];
        float pd0 = pdist(q0, pm);
        float pd1 = pdist(q1, pm);
        bool s0 = (pd0 >= tval0);
        unsigned k0 = __ballot_sync(0xffffffffu, s0);
        if (s0) {
            int pos = base0 + __popc(k0 & ((1u << lane) - 1));
            if (pos < 128) { sv[warp][0][pos] = pd0; si[warp][0][pos] = m; }
        }
        base0 += __popc(k0);
        bool s1 = (pd1 >= tval1);
        unsigned k1 = __ballot_sync(0xffffffffu, s1);
        if (s1) {
            int pos = base1 + __popc(k1 & ((1u << lane) - 1));
            if (pos < 128) { sv[warp][1][pos] = pd1; si[warp][1][pos] = m; }
        }
        base1 += __popc(k1);
    }
    __syncwarp();

    // distribute <=4 survivors per lane per row; sort desc (value, index asc)
    int S0 = base0 < 128 ? base0 : 128;
    int S1 = base1 < 128 ? base1 : 128;
    float v0[4], v1[4]; int id0[4], id1[4];
    #pragma unroll
    for (int j = 0; j < 4; j++) {
        int idx = lane + j*32;
        if (idx < S0) { v0[j] = sv[warp][0][idx]; id0[j] = si[warp][0][idx]; }
        else          { v0[j] = -FLT_MAX;         id0[j] = 0x7fffffff; }
        if (idx < S1) { v1[j] = sv[warp][1][idx]; id1[j] = si[warp][1][idx]; }
        else          { v1[j] = -FLT_MAX;         id1[j] = 0x7fffffff; }
    }
    #define CE(V_, I_, A_, B_) { \
        bool sw_ = (V_[B_] > V_[A_]) || (V_[B_] == V_[A_] && I_[B_] < I_[A_]); \
        if (sw_) { float tv_ = V_[A_]; V_[A_] = V_[B_]; V_[B_] = tv_; \
                   int ti_ = I_[A_]; I_[A_] = I_[B_]; I_[B_] = ti_; } }
    CE(v0,id0,0,1) CE(v0,id0,2,3) CE(v0,id0,0,2) CE(v0,id0,1,3) CE(v0,id0,1,2)
    CE(v1,id1,0,1) CE(v1,id1,2,3) CE(v1,id1,0,2) CE(v1,id1,1,3) CE(v1,id1,1,2)
    #undef CE

    // exact top-20 pop merge, both rows interleaved per iteration
    int pg0 = b*NPT + n0, pg1 = pg0 + 1;
    #pragma unroll 1
    for (int k = 0; k < KNN; k++) {
        unsigned a0 = fkey(v0[0]);
        unsigned a1 = fkey(v1[0]);
        unsigned be0 = __reduce_max_sync(0xffffffffu, a0);
        unsigned be1 = __reduce_max_sync(0xffffffffu, a1);
        int c0 = (a0 == be0) ? id0[0] : 0x7fffffff;
        int c1 = (a1 == be1) ? id1[0] : 0x7fffffff;
        int bmi0 = __reduce_min_sync(0xffffffffu, c0);
        int bmi1 = __reduce_min_sync(0xffffffffu, c1);
        if (a0 == be0 && id0[0] == bmi0) {
            v0[0] = v0[1]; id0[0] = id0[1];
            v0[1] = v0[2]; id0[1] = id0[2];
            v0[2] = v0[3]; id0[2] = id0[3];
            v0[3] = -FLT_MAX; id0[3] = 0x7fffffff;
        }
        if (a1 == be1 && id1[0] == bmi1) {
            v1[0] = v1[1]; id1[0] = id1[1];
            v1[1] = v1[2]; id1[1] = id1[2];
            v1[2] = v1[3]; id1[2] = id1[3];
            v1[3] = -FLT_MAX; id1[3] = 0x7fffffff;
        }
        if (lane == 0) {
            int qg0 = b*NPT + bmi0;
            int qg1 = b*NPT + bmi1;
            d_nbr[pg0*KNN + k] = qg0;
            d_nbr[pg1*KNN + k] = qg1;
            atomicAdd(&d_deg[qg0], 1);
            atomicAdd(&d_deg[qg1], 1);
        }
    }
}

// ---------------- parallel scan ----------------
__global__ void k_scanA() {
    int t = threadIdx.x, g = blockIdx.x*1024 + t;
    int v = d_deg[g];
    int lane = t & 31, wid = t >> 5;
    int vv = v;
    #pragma unroll
    for (int o = 1; o < 32; o <<= 1) { int u = __shfl_up_sync(0xffffffffu, vv, o); if (lane >= o) vv += u; }
    __shared__ int ws[32];
    if (lane == 31) ws[wid] = vv;
    __syncthreads();
    if (wid == 0) {
        int w = ws[lane];
        #pragma unroll
        for (int o = 1; o < 32; o <<= 1) { int u = __shfl_up_sync(0xffffffffu, w, o); if (lane >= o) w += u; }
        ws[lane] = w;
    }
    __syncthreads();
    int incl = vv + (wid ? ws[wid-1] : 0);
    d_rowstart[g] = incl - v;
    if (t == 1023) d_bsum[blockIdx.x] = incl;
}

__global__ void k_scanB() {
    int g = blockIdx.x*256 + threadIdx.x;
    int sb = g >> 10;
    int off = 0;
    #pragma unroll 1
    for (int i = 0; i < sb; i++) off += d_bsum[i];
    int rs = d_rowstart[g] + off;
    d_rowstart[g] = rs;
    d_cursor[g] = rs;
    if (g == BNP - 1) {
        int tot = 0;
        #pragma unroll
        for (int i = 0; i < 16; i++) tot += d_bsum[i];
        d_rowstart[BNP] = tot;
    }
}

__global__ void k_fill() {
    int p = blockIdx.x*256 + threadIdx.x;
    if (p >= BNP) return;
    #pragma unroll
    for (int k = 0; k < KNN; k++) {
        int q = d_nbr[p*KNN + k];
        int pos = atomicAdd(&d_cursor[q], 1);
        d_rev[pos] = p;
    }
}

// ---------------- layer 0: sup0 = flat@w0 ; rz = flat@wr + br (+ rz stats) ----
__global__ void k_l0mm(const float* __restrict__ x, const float* __restrict__ w0,
                       const float* __restrict__ wr, const float* __restrict__ br) {
    int tid = threadIdx.x;
    int t = blockIdx.x*256 + tid;
    int p = t >> 6, c = t & 63;
    int b = p >> 11, n = p & 2047;
    const float* xb = x + b*3*NPT;
    float x0 = xb[n], x1 = xb[NPT + n], x2 = xb[2*NPT + n];
    d_sup[t] = x0*w0[c] + x1*w0[64+c] + x2*w0[128+c];
    float rz = x0*wr[c] + x1*wr[64+c] + x2*wr[128+c] + br[c];
    d_rz[t] = rz;
    __shared__ float s1[256], s2[256];
    s1[tid] = rz; s2[tid] = rz*rz;
    __syncthreads();
    if (tid < 64) {
        float a = s1[tid] + s1[64+tid] + s1[128+tid] + s1[192+tid];
        float q = s2[tid] + s2[64+tid] + s2[128+tid] + s2[192+tid];
        atomicAdd(&d_sumB[tid], a);
        atomicAdd(&d_sqB[tid], q);
    }
}

// ---------------- gather: warp per point, shuffled indices, 4-deep MLP -------
// 8 warps/block = 8 points/block; thread owns channels (lane, lane+32)
__global__ void __launch_bounds__(256) k_gather_stats(const float* __restrict__ bias, int layer) {
    int t = threadIdx.x, warp = t >> 5, lane = t & 31;
    int q = blockIdx.x*8 + warp;
    int s0 = d_rowstart[q], e0 = d_rowstart[q+1];
    int deg = e0 - s0;
    // warp-parallel index load (deg <= ~100 typical; handle any deg)
    float a0 = bias[lane], a1 = bias[lane+32];
    int i = 0;
    while (i < deg) {
        int nload = deg - i; if (nload > 32) nload = 32;
        int idx = (lane < nload) ? d_rev[s0 + i + lane] : 0;
        int j = 0;
        for (; j + 4 <= nload; j += 4) {
            int r0 = __shfl_sync(0xffffffffu, idx, j);
            int r1 = __shfl_sync(0xffffffffu, idx, j+1);
            int r2 = __shfl_sync(0xffffffffu, idx, j+2);
            int r3 = __shfl_sync(0xffffffffu, idx, j+3);
            float u0 = d_sup[r0*64 + lane],      w0v = d_sup[r0*64 + lane + 32];
            float u1 = d_sup[r1*64 + lane],      w1v = d_sup[r1*64 + lane + 32];
            float u2 = d_sup[r2*64 + lane],      w2v = d_sup[r2*64 + lane + 32];
            float u3 = d_sup[r3*64 + lane],      w3v = d_sup[r3*64 + lane + 32];
            a0 += u0; a0 += u1; a0 += u2; a0 += u3;
            a1 += w0v; a1 += w1v; a1 += w2v; a1 += w3v;
        }
        for (; j < nload; j++) {
            int r = __shfl_sync(0xffffffffu, idx, j);
            a0 += d_sup[r*64 + lane];
            a1 += d_sup[r*64 + lane + 32];
        }
        i += nload;
    }
    d_z[q*64 + lane] = a0;
    d_z[q*64 + lane + 32] = a1;
    // block stats: 8 warps x 64 channels -> shared reduce
    __shared__ float s1[8][64], s2[8][64];
    s1[warp][lane] = a0;        s1[warp][lane+32] = a1;
    s2[warp][lane] = a0*a0;     s2[warp][lane+32] = a1*a1;
    __syncthreads();
    if (t < 64) {
        float sa = 0.f, sq = 0.f;
        #pragma unroll
        for (int wv = 0; wv < 8; wv++) { sa += s1[wv][t]; sq += s2[wv][t]; }
        atomicAdd(&d_sumA[layer*64 + t], sa);
        atomicAdd(&d_sqA[layer*64 + t], sq);
    }
}

// ---------------- fused post (layer 0) + mm for layer 1 ----------------
__global__ void __launch_bounds__(256) k_post0_mm(
        const float* __restrict__ g0, const float* __restrict__ be0,
        const float* __restrict__ gr, const float* __restrict__ ber,
        const float* __restrict__ W1) {
    __shared__ float Hs[64*64];
    __shared__ float Ws[64*64];
    int tid = threadIdx.x;
    int p0 = blockIdx.x*64;
    int c = tid & 63, rg = tid >> 6;
    float mA = d_sumA[c]*(1.f/BNP);
    float vA = d_sqA[c]*(1.f/BNP) - mA*mA;
    float sA = rsqrtf(vA + 1e-5f)*g0[c], bA = be0[c];
    float mB = d_sumB[c]*(1.f/BNP);
    float vB = d_sqB[c]*(1.f/BNP) - mB*mB;
    float sB = rsqrtf(vB + 1e-5f)*gr[c], bB = ber[c];
    #pragma unroll
    for (int i = 0; i < 16; i++) {
        int r = rg + i*4, p = p0 + r;
        float o = fmaxf((d_z[p*64+c] - mA)*sA + bA, 0.f);
        float rr = (d_rz[p*64+c] - mB)*sB + bB;
        float h = fmaxf(o + rr, 0.f);
        Hs[r*64+c] = h;
        d_F[p*FD + c] = h;
        __half hi = __float2half_rn(h);
        d_Fh[p*FD + c] = hi;
        d_Fl[p*FD + c] = __float2half_rn(h - __half2float(hi));
    }
    for (int i = tid; i < 4096; i += 256) Ws[i] = W1[i];
    __syncthreads();
    for (int r = rg; r < 64; r += 4) {
        float acc = 0.f;
        #pragma unroll 16
        for (int k = 0; k < 64; k++) acc += Hs[r*64+k]*Ws[k*64+c];
        d_sup[(p0+r)*64+c] = acc;
    }
}

// ---------------- fused post (layers 1,2) + mm for next layer ----------------
__global__ void __launch_bounds__(256) k_postL_mm(int layer,
        const float* __restrict__ G, const float* __restrict__ Be,
        const float* __restrict__ Wn) {
    __shared__ float Hs[64*64];
    __shared__ float Ws[64*64];
    int tid = threadIdx.x;
    int p0 = blockIdx.x*64;
    int c = tid & 63, rg = tid >> 6;
    float m = d_sumA[layer*64+c]*(1.f/BNP);
    float v = d_sqA[layer*64+c]*(1.f/BNP) - m*m;
    float sc = rsqrtf(v + 1e-5f)*G[c], bc = Be[c];
    #pragma unroll
    for (int i = 0; i < 16; i++) {
        int r = rg + i*4, p = p0 + r;
        float a = fmaxf((d_z[p*64+c] - m)*sc + bc, 0.f);
        float h = fmaxf(a + d_F[p*FD + (layer-1)*64 + c], 0.f);
        Hs[r*64+c] = h;
        d_F[p*FD + layer*64 + c] = h;
        __half hi = __float2half_rn(h);
        d_Fh[p*FD + layer*64 + c] = hi;
        d_Fl[p*FD + layer*64 + c] = __float2half_rn(h - __half2float(hi));
    }
    for (int i = tid; i < 4096; i += 256) Ws[i] = Wn[i];
    __syncthreads();
    for (int r = rg; r < 64; r += 4) {
        float acc = 0.f;
        #pragma unroll 16
        for (int k = 0; k < 64; k++) acc += Hs[r*64+k]*Ws[k*64+c];
        d_sup[(p0+r)*64+c] = acc;
    }
}

// ---------------- post layer 3 ----------------
__global__ void k_post3(const float* __restrict__ G, const float* __restrict__ Be) {
    int t = blockIdx.x*256 + threadIdx.x;
    int p = t >> 6, c = t & 63;
    float m = d_sumA[3*64+c]*(1.f/BNP);
    float v = d_sqA[3*64+c]*(1.f/BNP) - m*m;
    float a = fmaxf((d_z[t] - m)*rsqrtf(v + 1e-5f)*G[c] + Be[c], 0.f);
    float h = fmaxf(a + d_F[p*FD + 2*64 + c], 0.f);
    __half hi = __float2half_rn(h);
    d_Fh[p*FD + 3*64 + c] = hi;
    d_Fl[p*FD + 3*64 + c] = __float2half_rn(h - __half2float(hi));
}

// ---------------- conv GEMM: fp16 3-term split, cp.async 2-stage -------------
// C = Ah.Bh + Al.Bh + Ah.Bl ; epilogue stores fp16 y + stats + raw extrema
#define PITCH 80
#define TSZ   (128*PITCH)
#define STAGE (4*TSZ)
#define SMEM_CONV (2*STAGE)   // 81920 B

__global__ void __launch_bounds__(256) k_conv_mma() {
    extern __shared__ __align__(16) uint8_t sm[];
    uint32_t sb = smem_u32(sm);

    int tid = threadIdx.x, wid = tid >> 5, lane = tid & 31;
    int warp_m = wid >> 2, warp_n = wid & 3;
    int bn = blockIdx.x;
    int bm = blockIdx.y;
    int bb = bn >> 4;                       // batch of this p-tile

    const uint4* gAh = (const uint4*)d_Ah;
    const uint4* gAl = (const uint4*)d_Al;
    const uint4* gBh = (const uint4*)d_Fh;
    const uint4* gBl = (const uint4*)d_Fl;

    float C[4][4][4];
    #pragma unroll
    for (int i = 0; i < 4; i++)
        #pragma unroll
        for (int j = 0; j < 4; j++)
            #pragma unroll
            for (int q = 0; q < 4; q++) C[i][j][q] = 0.f;

    int rowA  = warp_m*64 + (lane & 15);
    int halfA = lane >> 4;
    uint32_t oAh = rowA*PITCH + halfA*16;
    uint32_t oAl = TSZ + rowA*PITCH + halfA*16;
    int rowB  = warp_n*32 + (lane & 7) + ((lane >> 4) << 3);
    int halfB = (lane >> 3) & 1;
    uint32_t oBh = 2*TSZ + rowB*PITCH + halfB*16;
    uint32_t oBl = 3*TSZ + rowB*PITCH + halfB*16;

    auto issue = [&](int kc, int s) {
        uint32_t base = sb + s*STAGE;
        #pragma unroll
        for (int l = 0; l < 2; l++) {
            int i = tid + l*256;
            int row = i >> 2, c = i & 3;
            uint32_t so = row*PITCH + c*16;
            size_t ga = (size_t)(bm*128 + row)*32 + kc*4 + c;
            size_t gb = (size_t)(bn*128 + row)*32 + kc*4 + c;
            cp16(base + so,          gAh + ga);
            cp16(base + TSZ + so,    gAl + ga);
            cp16(base + 2*TSZ + so,  gBh + gb);
            cp16(base + 3*TSZ + so,  gBl + gb);
        }
        CP_COMMIT();
    };

    issue(0, 0);
    for (int kc = 0; kc < 8; kc++) {
        int s = kc & 1;
        CP_WAIT0();
        __syncthreads();
        if (kc + 1 < 8) issue(kc + 1, s ^ 1);
        uint32_t stb = sb + s*STAGE;

        #pragma unroll
        for (int ksub = 0; ksub < 2; ksub++) {
            uint32_t koff = (ksub*2)*16;
            uint32_t bh[8], bl[8];
            ldm_x4(bh + 0, stb + oBh + koff);
            ldm_x4(bh + 4, stb + oBh + koff + 16*PITCH);
            ldm_x4(bl + 0, stb + oBl + koff);
            ldm_x4(bl + 4, stb + oBl + koff + 16*PITCH);
            #pragma unroll
            for (int mt = 0; mt < 4; mt++) {
                uint32_t ah[4], al[4];
                ldm_x4(ah, stb + oAh + koff + mt*16*PITCH);
                ldm_x4(al, stb + oAl + koff + mt*16*PITCH);
                #pragma unroll
                for (int nt = 0; nt < 4; nt++) {
                    const uint32_t* ph = &bh[(nt >> 1)*4 + (nt & 1)*2];
                    const uint32_t* pl = &bl[(nt >> 1)*4 + (nt & 1)*2];
                    mma16816h(C[mt][nt], ah, ph);
                    mma16816h(C[mt][nt], al, ph);
                    mma16816h(C[mt][nt], ah, pl);
                }
            }
        }
    }

    // epilogue: fp16 store + per-e BN partial stats + raw extrema
    #pragma unroll
    for (int mt = 0; mt < 4; mt++) {
        int e = bm*128 + warp_m*64 + mt*16 + (lane >> 2);
        float s0 = 0.f, q0 = 0.f, s1 = 0.f, q1 = 0.f;
        float mx0 = -FLT_MAX, mn0 = FLT_MAX, mx1 = -FLT_MAX, mn1 = FLT_MAX;
        #pragma unroll
        for (int nt = 0; nt < 4; nt++) {
            int p = bn*128 + warp_n*32 + nt*8 + (lane & 3)*2;
            float a0 = C[mt][nt][0], a1 = C[mt][nt][1];
            float a2 = C[mt][nt][2], a3 = C[mt][nt][3];
            *(__half2*)&d_Yh[(size_t)e*BNP + p] =
                __half2(__float2half_rn(a0), __float2half_rn(a1));
            *(__half2*)&d_Yh[(size_t)(e + 8)*BNP + p] =
                __half2(__float2half_rn(a2), __float2half_rn(a3));
            s0 += a0 + a1; q0 += a0*a0 + a1*a1;
            s1 += a2 + a3; q1 += a2*a2 + a3*a3;
            mx0 = fmaxf(mx0, fmaxf(a0, a1)); mn0 = fminf(mn0, fminf(a0, a1));
            mx1 = fmaxf(mx1, fmaxf(a2, a3)); mn1 = fminf(mn1, fminf(a2, a3));
        }
        #pragma unroll
        for (int o = 1; o < 4; o <<= 1) {
            s0 += __shfl_xor_sync(0xffffffffu, s0, o);
            q0 += __shfl_xor_sync(0xffffffffu, q0, o);
            s1 += __shfl_xor_sync(0xffffffffu, s1, o);
            q1 += __shfl_xor_sync(0xffffffffu, q1, o);
            mx0 = fmaxf(mx0, __shfl_xor_sync(0xffffffffu, mx0, o));
            mn0 = fminf(mn0, __shfl_xor_sync(0xffffffffu, mn0, o));
            mx1 = fmaxf(mx1, __shfl_xor_sync(0xffffffffu, mx1, o));
            mn1 = fminf(mn1, __shfl_xor_sync(0xffffffffu, mn1, o));
        }
        if ((lane & 3) == 0) {
            atomicAdd(&d_sumY[e], s0);     atomicAdd(&d_sqY[e], q0);
            atomicAdd(&d_sumY[e + 8], s1); atomicAdd(&d_sqY[e + 8], q1);
            atomicMax(&d_maxK[bb*EMB + e], fkey(mx0));
            atomicMin(&d_minK[bb*EMB + e], fkey(mn0));
            atomicMax(&d_maxK[bb*EMB + e + 8], fkey(mx1));
            atomicMin(&d_minK[bb*EMB + e + 8], fkey(mn1));
        }
    }
}

// ---------------- BN + leaky + mean pool (max pool from exact extrema) -------
__global__ void k_reduce(const float* __restrict__ gf, const float* __restrict__ bef) {
    int e = blockIdx.x;
    const __half2* y2 = (const __half2*)(d_Yh + (size_t)e*BNP);
    int t = threadIdx.x, lane = t & 31, w = t >> 5;
    float mu = d_sumY[e]*(1.f/BNP);
    float var = d_sqY[e]*(1.f/BNP) - mu*mu;
    float sc = rsqrtf(var + 1e-5f)*gf[e], sh = bef[e];
    __shared__ float wsum[8];
    for (int b = 0; b < BB; b++) {
        float sm = 0.f;
        const __half2* yb = y2 + b*(NPT/2);
        for (int j = t; j < NPT/2; j += 256) {
            float2 v2 = __half22float2(yb[j]);
            float v0 = (v2.x - mu)*sc + sh; v0 = v0 > 0.f ? v0 : 0.2f*v0;
            float v1 = (v2.y - mu)*sc + sh; v1 = v1 > 0.f ? v1 : 0.2f*v1;
            sm += v0 + v1;
        }
        #pragma unroll
        for (int o = 16; o; o >>= 1) sm += __shfl_xor_sync(0xffffffffu, sm, o);
        if (lane == 0) wsum[w] = sm;
        __syncthreads();
        if (t == 0) {
            float SM = 0.f;
            #pragma unroll
            for (int i = 0; i < 8; i++) SM += wsum[i];
            unsigned mk = (sc >= 0.f) ? d_maxK[b*EMB + e] : d_minK[b*EMB + e];
            float raw = unkey(mk);
            float v = (raw - mu)*sc + sh;
            v = v > 0.f ? v : 0.2f*v;
            d_x12[b*2*EMB + e] = v;
            d_x12[b*2*EMB + EMB + e] = SM*(1.f/NPT);
        }
        __syncthreads();
    }
}

// ---------------- head (k-split parallel) ----------------
__global__ void k_head1(const float* __restrict__ w1, const float* __restrict__ g6,
                        const float* __restrict__ b6) {
    int jl = threadIdx.x & 15, ks = threadIdx.x >> 4;
    int j = blockIdx.x*16 + jl;
    float acc[BB];
    #pragma unroll
    for (int b = 0; b < BB; b++) acc[b] = 0.f;
    for (int k = ks*128; k < ks*128 + 128; k++) {
        float wv = w1[k*512 + j];
        #pragma unroll
        for (int b = 0; b < BB; b++) acc[b] += d_x12[b*2*EMB + k]*wv;
    }
    __shared__ float sh[16][16][BB];
    #pragma unroll
    for (int b = 0; b < BB; b++) sh[ks][jl][b] = acc[b];
    __syncthreads();
    if (ks == 0) {
        #pragma unroll
        for (int b = 0; b < BB; b++) {
            float s = 0.f;
            #pragma unroll
            for (int i = 0; i < 16; i++) s += sh[i][jl][b];
            acc[b] = s;
        }
        float m = 0.f;
        #pragma unroll
        for (int b = 0; b < BB; b++) m += acc[b];
        m *= (1.f/BB);
        float var = 0.f;
        #pragma unroll
        for (int b = 0; b < BB; b++) { float d = acc[b]-m; var += d*d; }
        var *= (1.f/BB);
        float sc = rsqrtf(var + 1e-5f)*g6[j], bb = b6[j];
        #pragma unroll
        for (int b = 0; b < BB; b++) {
            float o = (acc[b]-m)*sc + bb;
            d_h512[b*512 + j] = o > 0.f ? o : 0.2f*o;
        }
    }
}

__global__ void k_head2(const float* __restrict__ w2, const float* __restrict__ b2,
                        const float* __restrict__ g7, const float* __restrict__ b7) {
    int jl = threadIdx.x & 31, ks = threadIdx.x >> 5;
    int j = blockIdx.x*32 + jl;
    float acc[BB];
    #pragma unroll
    for (int b = 0; b < BB; b++) acc[b] = 0.f;
    for (int k = ks*64; k < ks*64 + 64; k++) {
        float wv = w2[k*256 + j];
        #pragma unroll
        for (int b = 0; b < BB; b++) acc[b] += d_h512[b*512 + k]*wv;
    }
    __shared__ float sh[8][32][BB];
    #pragma unroll
    for (int b = 0; b < BB; b++) sh[ks][jl][b] = acc[b];
    __syncthreads();
    if (ks == 0) {
        #pragma unroll
        for (int b = 0; b < BB; b++) {
            float s = 0.f;
            #pragma unroll
            for (int i = 0; i < 8; i++) s += sh[i][jl][b];
            acc[b] = s + b2[j];
        }
        float m = 0.f;
        #pragma unroll
        for (int b = 0; b < BB; b++) m += acc[b];
        m *= (1.f/BB);
        float var = 0.f;
        #pragma unroll
        for (int b = 0; b < BB; b++) { float d = acc[b]-m; var += d*d; }
        var *= (1.f/BB);
        float sc = rsqrtf(var + 1e-5f)*g7[j], bb = b7[j];
        #pragma unroll
        for (int b = 0; b < BB; b++) {
            float o = (acc[b]-m)*sc + bb;
            d_h256[b*256 + j] = o > 0.f ? o : 0.2f*o;
        }
    }
}

__global__ void k_head3(const float* __restrict__ w3, const float* __restrict__ b3,
                        float* __restrict__ out) {
    int jl = threadIdx.x & 63, ks = threadIdx.x >> 6;
    float acc[BB];
    #pragma unroll
    for (int b = 0; b < BB; b++) acc[b] = 0.f;
    if (jl < 40) {
        for (int k = ks*64; k < ks*64 + 64; k++) {
            float wv = w3[k*40 + jl];
            #pragma unroll
            for (int b = 0; b < BB; b++) acc[b] += d_h256[b*256 + k]*wv;
        }
    }
    __shared__ float sh[4][64][BB];
    #pragma unroll
    for (int b = 0; b < BB; b++) sh[ks][jl][b] = acc[b];
    __syncthreads();
    if (ks == 0 && jl < 40) {
        #pragma unroll
        for (int b = 0; b < BB; b++) {
            float s = b3[jl];
            #pragma unroll
            for (int i = 0; i < 4; i++) s += sh[i][jl][b];
            out[b*40 + jl] = s;
        }
    }
}

// ---------------- launch ----------------
extern "C" void kernel_launch(void* const* d_in, const int* in_sizes, int n_in,
                              void* d_out, int out_size) {
    const float* x     = (const float*)d_in[0];
    const float* w0    = (const float*)d_in[1];
    const float* b0    = (const float*)d_in[2];
    const float* g0    = (const float*)d_in[3];
    const float* be0   = (const float*)d_in[4];
    const float* wr    = (const float*)d_in[5];
    const float* br    = (const float*)d_in[6];
    const float* gr    = (const float*)d_in[7];
    const float* ber   = (const float*)d_in[8];
    const float* W     = (const float*)d_in[9];
    const float* Bv    = (const float*)d_in[10];
    const float* G     = (const float*)d_in[11];
    const float* Be    = (const float*)d_in[12];
    const float* wconv = (const float*)d_in[13];
    const float* gf    = (const float*)d_in[14];
    const float* bef   = (const float*)d_in[15];
    const float* w1    = (const float*)d_in[16];
    const float* g6    = (const float*)d_in[17];
    const float* b6    = (const float*)d_in[18];
    const float* w2    = (const float*)d_in[19];
    const float* b2    = (const float*)d_in[20];
    const float* g7    = (const float*)d_in[21];
    const float* b7    = (const float*)d_in[22];
    const float* w3    = (const float*)d_in[23];
    const float* b3    = (const float*)d_in[24];
    float* out = (float*)d_out;

    static int smem_set = 0;
    if (!smem_set) {
        cudaFuncSetAttribute(k_conv_mma, cudaFuncAttributeMaxDynamicSharedMemorySize, SMEM_CONV);
        smem_set = 1;
    }

    // graph build (k_knn kept in the 4th = captured slot)
    k_begin<<<256, 256>>>(wconv);
    k_prep<<<64, 256>>>(x);
    k_l0mm<<<4096, 256>>>(x, w0, wr, br);
    k_knn<<<1024, 256>>>();
    k_scanA<<<16, 1024>>>();
    k_scanB<<<64, 256>>>();
    k_fill<<<64, 256>>>();

    // layer 0
    k_gather_stats<<<2048, 256>>>(b0, 0);
    k_post0_mm<<<256, 256>>>(g0, be0, gr, ber, W);

    // layers 1..3
    k_gather_stats<<<2048, 256>>>(Bv, 1);
    k_postL_mm<<<256, 256>>>(1, G, Be, W + 4096);
    k_gather_stats<<<2048, 256>>>(Bv + 64, 2);
    k_postL_mm<<<256, 256>>>(2, G + 64, Be + 64, W + 8192);
    k_gather_stats<<<2048, 256>>>(Bv + 128, 3);
    k_post3<<<4096, 256>>>(G + 128, Be + 128);

    // conv 256 -> 1024 (fp16 3-term) + fused stats/extrema, then pool
    dim3 cgrid(128, 8);
    k_conv_mma<<<cgrid, 256, SMEM_CONV>>>();
    k_reduce<<<1024, 256>>>(gf, bef);

    // head
    k_head1<<<32, 256>>>(w1, g6, b6);
    k_head2<<<8, 256>>>(w2, b2, g7, b7);
    k_head3<<<1, 256>>>(w3, b3, out);
}

// round 14
// speedup vs baseline: 1.2022x; 1.0166x over previous
#include <cuda_runtime.h>
#include <cuda_fp16.h>
#include <float.h>
#include <stdint.h>

// ---------------- problem constants ----------------
#define BB    8
#define NPT   2048
#define BNP   16384          // BB*NPT
#define KNN   20
#define CH    64
#define FD    256            // 4*CH
#define EMB   1024

// ---------------- scratch (device globals; no mallocs allowed) ----------------
__device__ float4 d_P4[BB*NPT];
__device__ int   d_nbr[BNP*KNN];
__device__ int   d_deg[BNP];
__device__ int   d_rowstart[BNP+1];
__device__ int   d_cursor[BNP];
__device__ int   d_bsum[16];
__device__ int   d_rev[BNP*KNN];
__device__ float d_F[BNP*FD];
__device__ float d_sup[BNP*CH];
__device__ float d_z[BNP*CH];
__device__ float d_rz[BNP*CH];
__device__ __half d_Yh[(size_t)EMB*BNP];   // conv output fp16 [e][p], 32 MB
__device__ unsigned d_maxK[BB*EMB], d_minK[BB*EMB];  // per (b,e) raw-y extrema keys
__device__ float d_x12[BB*2*EMB];
__device__ float d_h512[BB*512];
__device__ float d_h256[BB*256];
__device__ float d_sumA[4*CH], d_sqA[4*CH];
__device__ float d_sumB[CH], d_sqB[CH];
__device__ float d_sumY[EMB], d_sqY[EMB];
__device__ __half d_Ah[EMB*FD], d_Al[EMB*FD];   // wconv fp16 hi/lo
__device__ __half d_Fh[BNP*FD], d_Fl[BNP*FD];   // features fp16 hi/lo

// ---------------- helpers ----------------
__device__ __forceinline__ uint32_t smem_u32(const void* p) {
    uint32_t a;
    asm("{ .reg .u64 t; cvta.to.shared.u64 t, %1; cvt.u32.u64 %0, t; }" : "=r"(a) : "l"(p));
    return a;
}
__device__ __forceinline__ void ldm_x4(uint32_t* r, uint32_t addr) {
    asm volatile("ldmatrix.sync.aligned.m8n8.x4.shared.b16 {%0,%1,%2,%3}, [%4];"
        : "=r"(r[0]), "=r"(r[1]), "=r"(r[2]), "=r"(r[3]) : "r"(addr));
}
__device__ __forceinline__ void mma16816h(float* c, const uint32_t* a, const uint32_t* b) {
    asm volatile(
        "mma.sync.aligned.m16n8k16.row.col.f32.f16.f16.f32 "
        "{%0,%1,%2,%3}, {%4,%5,%6,%7}, {%8,%9}, {%0,%1,%2,%3};"
        : "+f"(c[0]), "+f"(c[1]), "+f"(c[2]), "+f"(c[3])
        : "r"(a[0]), "r"(a[1]), "r"(a[2]), "r"(a[3]), "r"(b[0]), "r"(b[1]));
}
__device__ __forceinline__ void cp16(uint32_t sdst, const void* gsrc) {
    asm volatile("cp.async.cg.shared.global [%0], [%1], 16;" :: "r"(sdst), "l"(gsrc));
}
#define CP_COMMIT() asm volatile("cp.async.commit_group;" ::: "memory")
#define CP_WAIT0()  asm volatile("cp.async.wait_group 0;" ::: "memory")

__device__ __forceinline__ unsigned fkey(float f) {
    unsigned u = __float_as_uint(f);
    return (u & 0x80000000u) ? ~u : (u | 0x80000000u);
}
__device__ __forceinline__ float unkey(unsigned k) {
    return (k & 0x80000000u) ? __uint_as_float(k & 0x7fffffffu) : __uint_as_float(~k);
}

// ---------------- begin: zero stats/deg + wconv fp16 hi/lo split -------------
__global__ void k_begin(const float* __restrict__ w) {
    int t = blockIdx.x*256 + threadIdx.x;   // 65536 threads
    if (t < BNP) d_deg[t] = 0;
    if (t < 4*CH) { d_sumA[t] = 0.f; d_sqA[t] = 0.f; }
    if (t < CH)   { d_sumB[t] = 0.f; d_sqB[t] = 0.f; }
    if (t < EMB)  { d_sumY[t] = 0.f; d_sqY[t] = 0.f; }
    if (t < BB*EMB) { d_maxK[t] = 0u; d_minK[t] = 0xFFFFFFFFu; }
    float4 x = ((const float4*)w)[t];       // EMB*FD/4 = 65536
    __half h0 = __float2half_rn(x.x), h1 = __float2half_rn(x.y);
    __half h2 = __float2half_rn(x.z), h3 = __float2half_rn(x.w);
    __half l0 = __float2half_rn(x.x - __half2float(h0));
    __half l1 = __float2half_rn(x.y - __half2float(h1));
    __half l2 = __float2half_rn(x.z - __half2float(h2));
    __half l3 = __float2half_rn(x.w - __half2float(h3));
    ((__half2*)d_Ah)[t*2]   = __half2(h0, h1);
    ((__half2*)d_Ah)[t*2+1] = __half2(h2, h3);
    ((__half2*)d_Al)[t*2]   = __half2(l0, l1);
    ((__half2*)d_Al)[t*2+1] = __half2(l2, l3);
}

// pts[b,c,n] = x[b, (c*N+n)%3, (c*N+n)/3]
__global__ void k_prep(const float* __restrict__ x) {
    int t = blockIdx.x*256 + threadIdx.x;
    if (t >= BNP) return;
    int b = t >> 11, n = t & 2047;
    const float* xb = x + b*3*NPT;
    float v[3]; float acc = 0.f;
    #pragma unroll
    for (int c = 0; c < 3; c++) {
        int L = c*NPT + n;
        v[c] = xb[(L % 3)*NPT + (L / 3)];
        acc += v[c]*v[c];
    }
    d_P4[t] = make_float4(v[0], v[1], v[2], acc);
}

// identical arithmetic in both KNN passes (explicit intrinsics -> deterministic)
__device__ __forceinline__ float pdist(float4 q, float4 pm) {
    float dot = __fmaf_rn(q.x, pm.x, __fmaf_rn(q.y, pm.y, __fmul_rn(q.z, pm.z)));
    return __fadd_rn(__fmaf_rn(2.f, dot, -q.w), -pm.w);
}

// ---------------- knn: two-pass threshold, 2 rows per warp, interleaved chains
__global__ void __launch_bounds__(256) k_knn() {
    __shared__ float4 sP[NPT];               // 32 KB
    __shared__ float sv[8][2][128];
    __shared__ int   si[8][2][128];
    int b = blockIdx.x >> 7;                 // 8 batches x 128 chunks
    int chunk = blockIdx.x & 127;            // 16 rows per chunk
    for (int i = threadIdx.x; i < NPT; i += 256)
        sP[i] = d_P4[b*NPT + i];
    __syncthreads();

    int warp = threadIdx.x >> 5, lane = threadIdx.x & 31;
    int n0 = chunk*16 + warp*2;
    float4 q0 = sP[n0], q1 = sP[n0 + 1];

    // pass A: shared pm loads, per-lane maxes for both rows
    float m00 = -FLT_MAX, m01 = -FLT_MAX, m10 = -FLT_MAX, m11 = -FLT_MAX;
    for (int m = lane; m < NPT; m += 64) {
        float4 pa = sP[m], pb = sP[m + 32];
        m00 = fmaxf(m00, pdist(q0, pa)); m01 = fmaxf(m01, pdist(q0, pb));
        m10 = fmaxf(m10, pdist(q1, pa)); m11 = fmaxf(m11, pdist(q1, pb));
    }
    float vmax0 = fmaxf(m00, m01), vmax1 = fmaxf(m10, m11);

    // tau = 20th largest of 32 lane maxima; both rows' chains interleaved
    unsigned mk0 = fkey(vmax0), mk1 = fkey(vmax1);
    unsigned tk0 = 0, tk1 = 0;
    #pragma unroll 1
    for (int k = 0; k < KNN; k++) {
        tk0 = __reduce_max_sync(0xffffffffu, mk0);
        tk1 = __reduce_max_sync(0xffffffffu, mk1);
        unsigned b0 = __ballot_sync(0xffffffffu, mk0 == tk0);
        unsigned b1 = __ballot_sync(0xffffffffu, mk1 == tk1);
        if (lane == __ffs(b0) - 1) mk0 = 0;
        if (lane == __ffs(b1) - 1) mk1 = 0;
    }
    float tval0 = unkey(tk0), tval1 = unkey(tk1);

    // pass B: shared pm loads, compact survivors for both rows
    int base0 = 0, base1 = 0;
    for (int m = lane; m < NPT; m += 32) {
        float4 pm = sP[m];
        float pd0 = pdist(q0, pm);
        float pd1 = pdist(q1, pm);
        bool s0 = (pd0 >= tval0);
        unsigned k0 = __ballot_sync(0xffffffffu, s0);
        if (s0) {
            int pos = base0 + __popc(k0 & ((1u << lane) - 1));
            if (pos < 128) { sv[warp][0][pos] = pd0; si[warp][0][pos] = m; }
        }
        base0 += __popc(k0);
        bool s1 = (pd1 >= tval1);
        unsigned k1 = __ballot_sync(0xffffffffu, s1);
        if (s1) {
            int pos = base1 + __popc(k1 & ((1u << lane) - 1));
            if (pos < 128) { sv[warp][1][pos] = pd1; si[warp][1][pos] = m; }
        }
        base1 += __popc(k1);
    }
    __syncwarp();

    // distribute <=4 survivors per lane per row; sort desc (value, index asc)
    int S0 = base0 < 128 ? base0 : 128;
    int S1 = base1 < 128 ? base1 : 128;
    float v0[4], v1[4]; int id0[4], id1[4];
    #pragma unroll
    for (int j = 0; j < 4; j++) {
        int idx = lane + j*32;
        if (idx < S0) { v0[j] = sv[warp][0][idx]; id0[j] = si[warp][0][idx]; }
        else          { v0[j] = -FLT_MAX;         id0[j] = 0x7fffffff; }
        if (idx < S1) { v1[j] = sv[warp][1][idx]; id1[j] = si[warp][1][idx]; }
        else          { v1[j] = -FLT_MAX;         id1[j] = 0x7fffffff; }
    }
    #define CE(V_, I_, A_, B_) { \
        bool sw_ = (V_[B_] > V_[A_]) || (V_[B_] == V_[A_] && I_[B_] < I_[A_]); \
        if (sw_) { float tv_ = V_[A_]; V_[A_] = V_[B_]; V_[B_] = tv_; \
                   int ti_ = I_[A_]; I_[A_] = I_[B_]; I_[B_] = ti_; } }
    CE(v0,id0,0,1) CE(v0,id0,2,3) CE(v0,id0,0,2) CE(v0,id0,1,3) CE(v0,id0,1,2)
    CE(v1,id1,0,1) CE(v1,id1,2,3) CE(v1,id1,0,2) CE(v1,id1,1,3) CE(v1,id1,1,2)
    #undef CE

    // exact top-20 pop merge, both rows interleaved per iteration
    int pg0 = b*NPT + n0, pg1 = pg0 + 1;
    #pragma unroll 1
    for (int k = 0; k < KNN; k++) {
        unsigned a0 = fkey(v0[0]);
        unsigned a1 = fkey(v1[0]);
        unsigned be0 = __reduce_max_sync(0xffffffffu, a0);
        unsigned be1 = __reduce_max_sync(0xffffffffu, a1);
        int c0 = (a0 == be0) ? id0[0] : 0x7fffffff;
        int c1 = (a1 == be1) ? id1[0] : 0x7fffffff;
        int bmi0 = __reduce_min_sync(0xffffffffu, c0);
        int bmi1 = __reduce_min_sync(0xffffffffu, c1);
        if (a0 == be0 && id0[0] == bmi0) {
            v0[0] = v0[1]; id0[0] = id0[1];
            v0[1] = v0[2]; id0[1] = id0[2];
            v0[2] = v0[3]; id0[2] = id0[3];
            v0[3] = -FLT_MAX; id0[3] = 0x7fffffff;
        }
        if (a1 == be1 && id1[0] == bmi1) {
            v1[0] = v1[1]; id1[0] = id1[1];
            v1[1] = v1[2]; id1[1] = id1[2];
            v1[2] = v1[3]; id1[2] = id1[3];
            v1[3] = -FLT_MAX; id1[3] = 0x7fffffff;
        }
        if (lane == 0) {
            int qg0 = b*NPT + bmi0;
            int qg1 = b*NPT + bmi1;
            d_nbr[pg0*KNN + k] = qg0;
            d_nbr[pg1*KNN + k] = qg1;
            atomicAdd(&d_deg[qg0], 1);
            atomicAdd(&d_deg[qg1], 1);
        }
    }
}

// ---------------- parallel scan ----------------
__global__ void k_scanA() {
    int t = threadIdx.x, g = blockIdx.x*1024 + t;
    int v = d_deg[g];
    int lane = t & 31, wid = t >> 5;
    int vv = v;
    #pragma unroll
    for (int o = 1; o < 32; o <<= 1) { int u = __shfl_up_sync(0xffffffffu, vv, o); if (lane >= o) vv += u; }
    __shared__ int ws[32];
    if (lane == 31) ws[wid] = vv;
    __syncthreads();
    if (wid == 0) {
        int w = ws[lane];
        #pragma unroll
        for (int o = 1; o < 32; o <<= 1) { int u = __shfl_up_sync(0xffffffffu, w, o); if (lane >= o) w += u; }
        ws[lane] = w;
    }
    __syncthreads();
    int incl = vv + (wid ? ws[wid-1] : 0);
    d_rowstart[g] = incl - v;
    if (t == 1023) d_bsum[blockIdx.x] = incl;
}

__global__ void k_scanB() {
    int g = blockIdx.x*256 + threadIdx.x;
    int sb = g >> 10;
    int off = 0;
    #pragma unroll 1
    for (int i = 0; i < sb; i++) off += d_bsum[i];
    int rs = d_rowstart[g] + off;
    d_rowstart[g] = rs;
    d_cursor[g] = rs;
    if (g == BNP - 1) {
        int tot = 0;
        #pragma unroll
        for (int i = 0; i < 16; i++) tot += d_bsum[i];
        d_rowstart[BNP] = tot;
    }
}

__global__ void k_fill() {
    int p = blockIdx.x*256 + threadIdx.x;
    if (p >= BNP) return;
    #pragma unroll
    for (int k = 0; k < KNN; k++) {
        int q = d_nbr[p*KNN + k];
        int pos = atomicAdd(&d_cursor[q], 1);
        d_rev[pos] = p;
    }
}

// ---------------- layer 0: sup0 = flat@w0 ; rz = flat@wr + br (+ rz stats) ----
__global__ void k_l0mm(const float* __restrict__ x, const float* __restrict__ w0,
                       const float* __restrict__ wr, const float* __restrict__ br) {
    int tid = threadIdx.x;
    int t = blockIdx.x*256 + tid;
    int p = t >> 6, c = t & 63;
    int b = p >> 11, n = p & 2047;
    const float* xb = x + b*3*NPT;
    float x0 = xb[n], x1 = xb[NPT + n], x2 = xb[2*NPT + n];
    d_sup[t] = x0*w0[c] + x1*w0[64+c] + x2*w0[128+c];
    float rz = x0*wr[c] + x1*wr[64+c] + x2*wr[128+c] + br[c];
    d_rz[t] = rz;
    __shared__ float s1[256], s2[256];
    s1[tid] = rz; s2[tid] = rz*rz;
    __syncthreads();
    if (tid < 64) {
        float a = s1[tid] + s1[64+tid] + s1[128+tid] + s1[192+tid];
        float q = s2[tid] + s2[64+tid] + s2[128+tid] + s2[192+tid];
        atomicAdd(&d_sumB[tid], a);
        atomicAdd(&d_sqB[tid], q);
    }
}

// ---------------- gather: warp per point, shuffled indices, 4-deep MLP -------
__global__ void __launch_bounds__(256) k_gather_stats(const float* __restrict__ bias, int layer) {
    int t = threadIdx.x, warp = t >> 5, lane = t & 31;
    int q = blockIdx.x*8 + warp;
    int s0 = d_rowstart[q], e0 = d_rowstart[q+1];
    int deg = e0 - s0;
    float a0 = bias[lane], a1 = bias[lane+32];
    int i = 0;
    while (i < deg) {
        int nload = deg - i; if (nload > 32) nload = 32;
        int idx = (lane < nload) ? d_rev[s0 + i + lane] : 0;
        int j = 0;
        for (; j + 4 <= nload; j += 4) {
            int r0 = __shfl_sync(0xffffffffu, idx, j);
            int r1 = __shfl_sync(0xffffffffu, idx, j+1);
            int r2 = __shfl_sync(0xffffffffu, idx, j+2);
            int r3 = __shfl_sync(0xffffffffu, idx, j+3);
            float u0 = d_sup[r0*64 + lane],      w0v = d_sup[r0*64 + lane + 32];
            float u1 = d_sup[r1*64 + lane],      w1v = d_sup[r1*64 + lane + 32];
            float u2 = d_sup[r2*64 + lane],      w2v = d_sup[r2*64 + lane + 32];
            float u3 = d_sup[r3*64 + lane],      w3v = d_sup[r3*64 + lane + 32];
            a0 += u0; a0 += u1; a0 += u2; a0 += u3;
            a1 += w0v; a1 += w1v; a1 += w2v; a1 += w3v;
        }
        for (; j < nload; j++) {
            int r = __shfl_sync(0xffffffffu, idx, j);
            a0 += d_sup[r*64 + lane];
            a1 += d_sup[r*64 + lane + 32];
        }
        i += nload;
    }
    d_z[q*64 + lane] = a0;
    d_z[q*64 + lane + 32] = a1;
    __shared__ float s1[8][64], s2[8][64];
    s1[warp][lane] = a0;        s1[warp][lane+32] = a1;
    s2[warp][lane] = a0*a0;     s2[warp][lane+32] = a1*a1;
    __syncthreads();
    if (t < 64) {
        float sa = 0.f, sq = 0.f;
        #pragma unroll
        for (int wv = 0; wv < 8; wv++) { sa += s1[wv][t]; sq += s2[wv][t]; }
        atomicAdd(&d_sumA[layer*64 + t], sa);
        atomicAdd(&d_sqA[layer*64 + t], sq);
    }
}

// ---------------- fused post (layer 0) + mm for layer 1 ----------------
__global__ void __launch_bounds__(256) k_post0_mm(
        const float* __restrict__ g0, const float* __restrict__ be0,
        const float* __restrict__ gr, const float* __restrict__ ber,
        const float* __restrict__ W1) {
    __shared__ float Hs[64*64];
    __shared__ float Ws[64*64];
    int tid = threadIdx.x;
    int p0 = blockIdx.x*64;
    int c = tid & 63, rg = tid >> 6;
    float mA = d_sumA[c]*(1.f/BNP);
    float vA = d_sqA[c]*(1.f/BNP) - mA*mA;
    float sA = rsqrtf(vA + 1e-5f)*g0[c], bA = be0[c];
    float mB = d_sumB[c]*(1.f/BNP);
    float vB = d_sqB[c]*(1.f/BNP) - mB*mB;
    float sB = rsqrtf(vB + 1e-5f)*gr[c], bB = ber[c];
    #pragma unroll
    for (int i = 0; i < 16; i++) {
        int r = rg + i*4, p = p0 + r;
        float o = fmaxf((d_z[p*64+c] - mA)*sA + bA, 0.f);
        float rr = (d_rz[p*64+c] - mB)*sB + bB;
        float h = fmaxf(o + rr, 0.f);
        Hs[r*64+c] = h;
        d_F[p*FD + c] = h;
        __half hi = __float2half_rn(h);
        d_Fh[p*FD + c] = hi;
        d_Fl[p*FD + c] = __float2half_rn(h - __half2float(hi));
    }
    for (int i = tid; i < 4096; i += 256) Ws[i] = W1[i];
    __syncthreads();
    for (int r = rg; r < 64; r += 4) {
        float acc = 0.f;
        #pragma unroll 16
        for (int k = 0; k < 64; k++) acc += Hs[r*64+k]*Ws[k*64+c];
        d_sup[(p0+r)*64+c] = acc;
    }
}

// ---------------- fused post (layers 1,2) + mm for next layer ----------------
__global__ void __launch_bounds__(256) k_postL_mm(int layer,
        const float* __restrict__ G, const float* __restrict__ Be,
        const float* __restrict__ Wn) {
    __shared__ float Hs[64*64];
    __shared__ float Ws[64*64];
    int tid = threadIdx.x;
    int p0 = blockIdx.x*64;
    int c = tid & 63, rg = tid >> 6;
    float m = d_sumA[layer*64+c]*(1.f/BNP);
    float v = d_sqA[layer*64+c]*(1.f/BNP) - m*m;
    float sc = rsqrtf(v + 1e-5f)*G[c], bc = Be[c];
    #pragma unroll
    for (int i = 0; i < 16; i++) {
        int r = rg + i*4, p = p0 + r;
        float a = fmaxf((d_z[p*64+c] - m)*sc + bc, 0.f);
        float h = fmaxf(a + d_F[p*FD + (layer-1)*64 + c], 0.f);
        Hs[r*64+c] = h;
        d_F[p*FD + layer*64 + c] = h;
        __half hi = __float2half_rn(h);
        d_Fh[p*FD + layer*64 + c] = hi;
        d_Fl[p*FD + layer*64 + c] = __float2half_rn(h - __half2float(hi));
    }
    for (int i = tid; i < 4096; i += 256) Ws[i] = Wn[i];
    __syncthreads();
    for (int r = rg; r < 64; r += 4) {
        float acc = 0.f;
        #pragma unroll 16
        for (int k = 0; k < 64; k++) acc += Hs[r*64+k]*Ws[k*64+c];
        d_sup[(p0+r)*64+c] = acc;
    }
}

// ---------------- post layer 3 ----------------
__global__ void k_post3(const float* __restrict__ G, const float* __restrict__ Be) {
    int t = blockIdx.x*256 + threadIdx.x;
    int p = t >> 6, c = t & 63;
    float m = d_sumA[3*64+c]*(1.f/BNP);
    float v = d_sqA[3*64+c]*(1.f/BNP) - m*m;
    float a = fmaxf((d_z[t] - m)*rsqrtf(v + 1e-5f)*G[c] + Be[c], 0.f);
    float h = fmaxf(a + d_F[p*FD + 2*64 + c], 0.f);
    __half hi = __float2half_rn(h);
    d_Fh[p*FD + 3*64 + c] = hi;
    d_Fl[p*FD + 3*64 + c] = __float2half_rn(h - __half2float(hi));
}

// ---------------- conv GEMM: fp16 3-term split, tile 128x256, cp.async 2-stage
// C = Ah.Bh + Al.Bh + Ah.Bl ; epilogue stores fp16 y + stats + raw extrema
#define PITCH 80
#define TSZA  (128*PITCH)     // 10240
#define TSZB  (256*PITCH)     // 20480
#define STAGE (2*TSZA + 2*TSZB)   // 61440
#define SMEM_CONV (2*STAGE)       // 122880 B

__global__ void __launch_bounds__(256) k_conv_mma() {
    extern __shared__ __align__(16) uint8_t sm[];
    uint32_t sb = smem_u32(sm);

    int tid = threadIdx.x, wid = tid >> 5, lane = tid & 31;
    int warp_m = wid >> 2, warp_n = wid & 3;
    int bn = blockIdx.x;   // 0..63 (256-wide p tiles)
    int bm = blockIdx.y;   // 0..7
    int bb = bn >> 3;      // batch (256 | 2048)

    const uint4* gAh = (const uint4*)d_Ah;
    const uint4* gAl = (const uint4*)d_Al;
    const uint4* gBh = (const uint4*)d_Fh;
    const uint4* gBl = (const uint4*)d_Fl;

    float C[4][8][4];
    #pragma unroll
    for (int i = 0; i < 4; i++)
        #pragma unroll
        for (int j = 0; j < 8; j++)
            #pragma unroll
            for (int q = 0; q < 4; q++) C[i][j][q] = 0.f;

    int rowA  = warp_m*64 + (lane & 15);
    int halfA = lane >> 4;
    uint32_t oAh = rowA*PITCH + halfA*16;
    uint32_t oAl = TSZA + rowA*PITCH + halfA*16;
    int rowB  = warp_n*64 + (lane & 7) + ((lane >> 4) << 3);
    int halfB = (lane >> 3) & 1;
    uint32_t oBh = 2*TSZA + rowB*PITCH + halfB*16;
    uint32_t oBl = 2*TSZA + TSZB + rowB*PITCH + halfB*16;

    auto issue = [&](int kc, int s) {
        uint32_t base = sb + s*STAGE;
        #pragma unroll
        for (int l = 0; l < 2; l++) {        // A: 512 entries
            int i = tid + l*256;
            int row = i >> 2, c = i & 3;
            uint32_t so = row*PITCH + c*16;
            size_t ga = (size_t)(bm*128 + row)*32 + kc*4 + c;
            cp16(base + so,         gAh + ga);
            cp16(base + TSZA + so,  gAl + ga);
        }
        #pragma unroll
        for (int l = 0; l < 4; l++) {        // B: 1024 entries
            int i = tid + l*256;
            int row = i >> 2, c = i & 3;
            uint32_t so = row*PITCH + c*16;
            size_t gb = (size_t)(bn*256 + row)*32 + kc*4 + c;
            cp16(base + 2*TSZA + so,        gBh + gb);
            cp16(base + 2*TSZA + TSZB + so, gBl + gb);
        }
        CP_COMMIT();
    };

    issue(0, 0);
    for (int kc = 0; kc < 8; kc++) {
        int s = kc & 1;
        CP_WAIT0();
        __syncthreads();
        if (kc + 1 < 8) issue(kc + 1, s ^ 1);
        uint32_t stb = sb + s*STAGE;

        #pragma unroll
        for (int ksub = 0; ksub < 2; ksub++) {
            uint32_t koff = (ksub*2)*16;
            uint32_t bh[16], bl[16];
            #pragma unroll
            for (int nb = 0; nb < 4; nb++) {
                ldm_x4(bh + nb*4, stb + oBh + koff + nb*16*PITCH);
                ldm_x4(bl + nb*4, stb + oBl + koff + nb*16*PITCH);
            }
            #pragma unroll
            for (int mt = 0; mt < 4; mt++) {
                uint32_t ah[4], al[4];
                ldm_x4(ah, stb + oAh + koff + mt*16*PITCH);
                ldm_x4(al, stb + oAl + koff + mt*16*PITCH);
                #pragma unroll
                for (int nt = 0; nt < 8; nt++) {
                    const uint32_t* ph = &bh[(nt >> 1)*4 + (nt & 1)*2];
                    const uint32_t* pl = &bl[(nt >> 1)*4 + (nt & 1)*2];
                    mma16816h(C[mt][nt], ah, ph);
                    mma16816h(C[mt][nt], al, ph);
                    mma16816h(C[mt][nt], ah, pl);
                }
            }
        }
    }

    // epilogue: fp16 store + per-e BN partial stats + raw extrema
    #pragma unroll
    for (int mt = 0; mt < 4; mt++) {
        int e = bm*128 + warp_m*64 + mt*16 + (lane >> 2);
        float s0 = 0.f, q0 = 0.f, s1 = 0.f, q1 = 0.f;
        float mx0 = -FLT_MAX, mn0 = FLT_MAX, mx1 = -FLT_MAX, mn1 = FLT_MAX;
        #pragma unroll
        for (int nt = 0; nt < 8; nt++) {
            int p = bn*256 + warp_n*64 + nt*8 + (lane & 3)*2;
            float a0 = C[mt][nt][0], a1 = C[mt][nt][1];
            float a2 = C[mt][nt][2], a3 = C[mt][nt][3];
            *(__half2*)&d_Yh[(size_t)e*BNP + p] =
                __half2(__float2half_rn(a0), __float2half_rn(a1));
            *(__half2*)&d_Yh[(size_t)(e + 8)*BNP + p] =
                __half2(__float2half_rn(a2), __float2half_rn(a3));
            s0 += a0 + a1; q0 += a0*a0 + a1*a1;
            s1 += a2 + a3; q1 += a2*a2 + a3*a3;
            mx0 = fmaxf(mx0, fmaxf(a0, a1)); mn0 = fminf(mn0, fminf(a0, a1));
            mx1 = fmaxf(mx1, fmaxf(a2, a3)); mn1 = fminf(mn1, fminf(a2, a3));
        }
        #pragma unroll
        for (int o = 1; o < 4; o <<= 1) {
            s0 += __shfl_xor_sync(0xffffffffu, s0, o);
            q0 += __shfl_xor_sync(0xffffffffu, q0, o);
            s1 += __shfl_xor_sync(0xffffffffu, s1, o);
            q1 += __shfl_xor_sync(0xffffffffu, q1, o);
            mx0 = fmaxf(mx0, __shfl_xor_sync(0xffffffffu, mx0, o));
            mn0 = fminf(mn0, __shfl_xor_sync(0xffffffffu, mn0, o));
            mx1 = fmaxf(mx1, __shfl_xor_sync(0xffffffffu, mx1, o));
            mn1 = fminf(mn1, __shfl_xor_sync(0xffffffffu, mn1, o));
        }
        if ((lane & 3) == 0) {
            atomicAdd(&d_sumY[e], s0);     atomicAdd(&d_sqY[e], q0);
            atomicAdd(&d_sumY[e + 8], s1); atomicAdd(&d_sqY[e + 8], q1);
            atomicMax(&d_maxK[bb*EMB + e], fkey(mx0));
            atomicMin(&d_minK[bb*EMB + e], fkey(mn0));
            atomicMax(&d_maxK[bb*EMB + e + 8], fkey(mx1));
            atomicMin(&d_minK[bb*EMB + e + 8], fkey(mn1));
        }
    }
}

// ---------------- BN + leaky + mean pool (max pool from exact extrema) -------
__global__ void k_reduce(const float* __restrict__ gf, const float* __restrict__ bef) {
    int e = blockIdx.x;
    const __half2* y2 = (const __half2*)(d_Yh + (size_t)e*BNP);
    int t = threadIdx.x, lane = t & 31, w = t >> 5;
    float mu = d_sumY[e]*(1.f/BNP);
    float var = d_sqY[e]*(1.f/BNP) - mu*mu;
    float sc = rsqrtf(var + 1e-5f)*gf[e], sh = bef[e];
    __shared__ float wsum[8];
    for (int b = 0; b < BB; b++) {
        float sm = 0.f;
        const __half2* yb = y2 + b*(NPT/2);
        for (int j = t; j < NPT/2; j += 256) {
            float2 v2 = __half22float2(yb[j]);
            float v0 = (v2.x - mu)*sc + sh; v0 = v0 > 0.f ? v0 : 0.2f*v0;
            float v1 = (v2.y - mu)*sc + sh; v1 = v1 > 0.f ? v1 : 0.2f*v1;
            sm += v0 + v1;
        }
        #pragma unroll
        for (int o = 16; o; o >>= 1) sm += __shfl_xor_sync(0xffffffffu, sm, o);
        if (lane == 0) wsum[w] = sm;
        __syncthreads();
        if (t == 0) {
            float SM = 0.f;
            #pragma unroll
            for (int i = 0; i < 8; i++) SM += wsum[i];
            unsigned mk = (sc >= 0.f) ? d_maxK[b*EMB + e] : d_minK[b*EMB + e];
            float raw = unkey(mk);
            float v = (raw - mu)*sc + sh;
            v = v > 0.f ? v : 0.2f*v;
            d_x12[b*2*EMB + e] = v;
            d_x12[b*2*EMB + EMB + e] = SM*(1.f/NPT);
        }
        __syncthreads();
    }
}

// ---------------- head (k-split parallel) ----------------
__global__ void k_head1(const float* __restrict__ w1, const float* __restrict__ g6,
                        const float* __restrict__ b6) {
    int jl = threadIdx.x & 15, ks = threadIdx.x >> 4;
    int j = blockIdx.x*16 + jl;
    float acc[BB];
    #pragma unroll
    for (int b = 0; b < BB; b++) acc[b] = 0.f;
    for (int k = ks*128; k < ks*128 + 128; k++) {
        float wv = w1[k*512 + j];
        #pragma unroll
        for (int b = 0; b < BB; b++) acc[b] += d_x12[b*2*EMB + k]*wv;
    }
    __shared__ float sh[16][16][BB];
    #pragma unroll
    for (int b = 0; b < BB; b++) sh[ks][jl][b] = acc[b];
    __syncthreads();
    if (ks == 0) {
        #pragma unroll
        for (int b = 0; b < BB; b++) {
            float s = 0.f;
            #pragma unroll
            for (int i = 0; i < 16; i++) s += sh[i][jl][b];
            acc[b] = s;
        }
        float m = 0.f;
        #pragma unroll
        for (int b = 0; b < BB; b++) m += acc[b];
        m *= (1.f/BB);
        float var = 0.f;
        #pragma unroll
        for (int b = 0; b < BB; b++) { float d = acc[b]-m; var += d*d; }
        var *= (1.f/BB);
        float sc = rsqrtf(var + 1e-5f)*g6[j], bb = b6[j];
        #pragma unroll
        for (int b = 0; b < BB; b++) {
            float o = (acc[b]-m)*sc + bb;
            d_h512[b*512 + j] = o > 0.f ? o : 0.2f*o;
        }
    }
}

__global__ void k_head2(const float* __restrict__ w2, const float* __restrict__ b2,
                        const float* __restrict__ g7, const float* __restrict__ b7) {
    int jl = threadIdx.x & 31, ks = threadIdx.x >> 5;
    int j = blockIdx.x*32 + jl;
    float acc[BB];
    #pragma unroll
    for (int b = 0; b < BB; b++) acc[b] = 0.f;
    for (int k = ks*64; k < ks*64 + 64; k++) {
        float wv = w2[k*256 + j];
        #pragma unroll
        for (int b = 0; b < BB; b++) acc[b] += d_h512[b*512 + k]*wv;
    }
    __shared__ float sh[8][32][BB];
    #pragma unroll
    for (int b = 0; b < BB; b++) sh[ks][jl][b] = acc[b];
    __syncthreads();
    if (ks == 0) {
        #pragma unroll
        for (int b = 0; b < BB; b++) {
            float s = 0.f;
            #pragma unroll
            for (int i = 0; i < 8; i++) s += sh[i][jl][b];
            acc[b] = s + b2[j];
        }
        float m = 0.f;
        #pragma unroll
        for (int b = 0; b < BB; b++) m += acc[b];
        m *= (1.f/BB);
        float var = 0.f;
        #pragma unroll
        for (int b = 0; b < BB; b++) { float d = acc[b]-m; var += d*d; }
        var *= (1.f/BB);
        float sc = rsqrtf(var + 1e-5f)*g7[j], bb = b7[j];
        #pragma unroll
        for (int b = 0; b < BB; b++) {
            float o = (acc[b]-m)*sc + bb;
            d_h256[b*256 + j] = o > 0.f ? o : 0.2f*o;
        }
    }
}

__global__ void k_head3(const float* __restrict__ w3, const float* __restrict__ b3,
                        float* __restrict__ out) {
    int jl = threadIdx.x & 63, ks = threadIdx.x >> 6;
    float acc[BB];
    #pragma unroll
    for (int b = 0; b < BB; b++) acc[b] = 0.f;
    if (jl < 40) {
        for (int k = ks*64; k < ks*64 + 64; k++) {
            float wv = w3[k*40 + jl];
            #pragma unroll
            for (int b = 0; b < BB; b++) acc[b] += d_h256[b*256 + k]*wv;
        }
    }
    __shared__ float sh[4][64][BB];
    #pragma unroll
    for (int b = 0; b < BB; b++) sh[ks][jl][b] = acc[b];
    __syncthreads();
    if (ks == 0 && jl < 40) {
        #pragma unroll
        for (int b = 0; b < BB; b++) {
            float s = b3[jl];
            #pragma unroll
            for (int i = 0; i < 4; i++) s += sh[i][jl][b];
            out[b*40 + jl] = s;
        }
    }
}

// ---------------- launch ----------------
extern "C" void kernel_launch(void* const* d_in, const int* in_sizes, int n_in,
                              void* d_out, int out_size) {
    const float* x     = (const float*)d_in[0];
    const float* w0    = (const float*)d_in[1];
    const float* b0    = (const float*)d_in[2];
    const float* g0    = (const float*)d_in[3];
    const float* be0   = (const float*)d_in[4];
    const float* wr    = (const float*)d_in[5];
    const float* br    = (const float*)d_in[6];
    const float* gr    = (const float*)d_in[7];
    const float* ber   = (const float*)d_in[8];
    const float* W     = (const float*)d_in[9];
    const float* Bv    = (const float*)d_in[10];
    const float* G     = (const float*)d_in[11];
    const float* Be    = (const float*)d_in[12];
    const float* wconv = (const float*)d_in[13];
    const float* gf    = (const float*)d_in[14];
    const float* bef   = (const float*)d_in[15];
    const float* w1    = (const float*)d_in[16];
    const float* g6    = (const float*)d_in[17];
    const float* b6    = (const float*)d_in[18];
    const float* w2    = (const float*)d_in[19];
    const float* b2    = (const float*)d_in[20];
    const float* g7    = (const float*)d_in[21];
    const float* b7    = (const float*)d_in[22];
    const float* w3    = (const float*)d_in[23];
    const float* b3    = (const float*)d_in[24];
    float* out = (float*)d_out;

    static int smem_set = 0;
    if (!smem_set) {
        cudaFuncSetAttribute(k_conv_mma, cudaFuncAttributeMaxDynamicSharedMemorySize, SMEM_CONV);
        smem_set = 1;
    }

    // graph build (k_knn kept in the 4th = captured slot)
    k_begin<<<256, 256>>>(wconv);
    k_prep<<<64, 256>>>(x);
    k_l0mm<<<4096, 256>>>(x, w0, wr, br);
    k_knn<<<1024, 256>>>();
    k_scanA<<<16, 1024>>>();
    k_scanB<<<64, 256>>>();
    k_fill<<<64, 256>>>();

    // layer 0
    k_gather_stats<<<2048, 256>>>(b0, 0);
    k_post0_mm<<<256, 256>>>(g0, be0, gr, ber, W);

    // layers 1..3
    k_gather_stats<<<2048, 256>>>(Bv, 1);
    k_postL_mm<<<256, 256>>>(1, G, Be, W + 4096);
    k_gather_stats<<<2048, 256>>>(Bv + 64, 2);
    k_postL_mm<<<256, 256>>>(2, G + 64, Be + 64, W + 8192);
    k_gather_stats<<<2048, 256>>>(Bv + 128, 3);
    k_post3<<<4096, 256>>>(G + 128, Be + 128);

    // conv 256 -> 1024 (fp16 3-term, 128x256 tile) + fused stats/extrema
    dim3 cgrid(64, 8);
    k_conv_mma<<<cgrid, 256, SMEM_CONV>>>();
    k_reduce<<<1024, 256>>>(gf, bef);

    // head
    k_head1<<<32, 256>>>(w1, g6, b6);
    k_head2<<<8, 256>>>(w2, b2, g7, b7);
    k_head3<<<1, 256>>>(w3, b3, out);
}

// round 15
// speedup vs baseline: 1.2030x; 1.0006x over previous
#include <cuda_runtime.h>
#include <cuda_fp16.h>
#include <float.h>
#include <stdint.h>

// ---------------- problem constants ----------------
#define BB    8
#define NPT   2048
#define BNP   16384          // BB*NPT
#define KNN   20
#define CH    64
#define FD    256            // 4*CH
#define EMB   1024

// ---------------- scratch (device globals; no mallocs allowed) ----------------
__device__ float4 d_P4[BB*NPT];
__device__ int   d_nbr[BNP*KNN];
__device__ int   d_deg[BNP];
__device__ int   d_rowstart[BNP+1];
__device__ int   d_cursor[BNP];
__device__ int   d_bsum[16];
__device__ int   d_rev[BNP*KNN];
__device__ float d_F[BNP*FD];
__device__ __half d_suph[BNP*CH];          // support, fp16 (gather traffic halved)
__device__ float d_z[BNP*CH];
__device__ float d_rz[BNP*CH];
__device__ __half d_Yh[(size_t)EMB*BNP];   // conv output fp16 [e][p], 32 MB
__device__ unsigned d_maxK[BB*EMB], d_minK[BB*EMB];
__device__ float d_x12[BB*2*EMB];
__device__ float d_h512[BB*512];
__device__ float d_h256[BB*256];
__device__ float d_sumA[4*CH], d_sqA[4*CH];
__device__ float d_sumB[CH], d_sqB[CH];
__device__ float d_sumY[EMB], d_sqY[EMB];
__device__ __half d_Ah[EMB*FD], d_Al[EMB*FD];   // wconv fp16 hi/lo
__device__ __half d_Fh[BNP*FD], d_Fl[BNP*FD];   // features fp16 hi/lo

// ---------------- helpers ----------------
__device__ __forceinline__ uint32_t smem_u32(const void* p) {
    uint32_t a;
    asm("{ .reg .u64 t; cvta.to.shared.u64 t, %1; cvt.u32.u64 %0, t; }" : "=r"(a) : "l"(p));
    return a;
}
__device__ __forceinline__ void ldm_x4(uint32_t* r, uint32_t addr) {
    asm volatile("ldmatrix.sync.aligned.m8n8.x4.shared.b16 {%0,%1,%2,%3}, [%4];"
        : "=r"(r[0]), "=r"(r[1]), "=r"(r[2]), "=r"(r[3]) : "r"(addr));
}
__device__ __forceinline__ void mma16816h(float* c, const uint32_t* a, const uint32_t* b) {
    asm volatile(
        "mma.sync.aligned.m16n8k16.row.col.f32.f16.f16.f32 "
        "{%0,%1,%2,%3}, {%4,%5,%6,%7}, {%8,%9}, {%0,%1,%2,%3};"
        : "+f"(c[0]), "+f"(c[1]), "+f"(c[2]), "+f"(c[3])
        : "r"(a[0]), "r"(a[1]), "r"(a[2]), "r"(a[3]), "r"(b[0]), "r"(b[1]));
}
__device__ __forceinline__ void cp16(uint32_t sdst, const void* gsrc) {
    asm volatile("cp.async.cg.shared.global [%0], [%1], 16;" :: "r"(sdst), "l"(gsrc));
}
#define CP_COMMIT() asm volatile("cp.async.commit_group;" ::: "memory")
#define CP_WAIT0()  asm volatile("cp.async.wait_group 0;" ::: "memory")

__device__ __forceinline__ unsigned fkey(float f) {
    unsigned u = __float_as_uint(f);
    return (u & 0x80000000u) ? ~u : (u | 0x80000000u);
}
__device__ __forceinline__ float unkey(unsigned k) {
    return (k & 0x80000000u) ? __uint_as_float(k & 0x7fffffffu) : __uint_as_float(~k);
}

// ---------------- begin: zero stats/deg + wconv fp16 hi/lo split -------------
__global__ void k_begin(const float* __restrict__ w) {
    int t = blockIdx.x*256 + threadIdx.x;   // 65536 threads
    if (t < BNP) d_deg[t] = 0;
    if (t < 4*CH) { d_sumA[t] = 0.f; d_sqA[t] = 0.f; }
    if (t < CH)   { d_sumB[t] = 0.f; d_sqB[t] = 0.f; }
    if (t < EMB)  { d_sumY[t] = 0.f; d_sqY[t] = 0.f; }
    if (t < BB*EMB) { d_maxK[t] = 0u; d_minK[t] = 0xFFFFFFFFu; }
    float4 x = ((const float4*)w)[t];
    __half h0 = __float2half_rn(x.x), h1 = __float2half_rn(x.y);
    __half h2 = __float2half_rn(x.z), h3 = __float2half_rn(x.w);
    __half l0 = __float2half_rn(x.x - __half2float(h0));
    __half l1 = __float2half_rn(x.y - __half2float(h1));
    __half l2 = __float2half_rn(x.z - __half2float(h2));
    __half l3 = __float2half_rn(x.w - __half2float(h3));
    ((__half2*)d_Ah)[t*2]   = __half2(h0, h1);
    ((__half2*)d_Ah)[t*2+1] = __half2(h2, h3);
    ((__half2*)d_Al)[t*2]   = __half2(l0, l1);
    ((__half2*)d_Al)[t*2+1] = __half2(l2, l3);
}

// pts[b,c,n] = x[b, (c*N+n)%3, (c*N+n)/3]
__global__ void k_prep(const float* __restrict__ x) {
    int t = blockIdx.x*256 + threadIdx.x;
    if (t >= BNP) return;
    int b = t >> 11, n = t & 2047;
    const float* xb = x + b*3*NPT;
    float v[3]; float acc = 0.f;
    #pragma unroll
    for (int c = 0; c < 3; c++) {
        int L = c*NPT + n;
        v[c] = xb[(L % 3)*NPT + (L / 3)];
        acc += v[c]*v[c];
    }
    d_P4[t] = make_float4(v[0], v[1], v[2], acc);
}

// identical arithmetic in both KNN passes
__device__ __forceinline__ float pdist(float4 q, float4 pm) {
    float dot = __fmaf_rn(q.x, pm.x, __fmaf_rn(q.y, pm.y, __fmul_rn(q.z, pm.z)));
    return __fadd_rn(__fmaf_rn(2.f, dot, -q.w), -pm.w);
}

// ---------------- knn: two-pass threshold, 2 rows per warp, interleaved chains
__global__ void __launch_bounds__(256) k_knn() {
    __shared__ float4 sP[NPT];
    __shared__ float sv[8][2][128];
    __shared__ int   si[8][2][128];
    int b = blockIdx.x >> 7;
    int chunk = blockIdx.x & 127;
    for (int i = threadIdx.x; i < NPT; i += 256)
        sP[i] = d_P4[b*NPT + i];
    __syncthreads();

    int warp = threadIdx.x >> 5, lane = threadIdx.x & 31;
    int n0 = chunk*16 + warp*2;
    float4 q0 = sP[n0], q1 = sP[n0 + 1];

    float m00 = -FLT_MAX, m01 = -FLT_MAX, m10 = -FLT_MAX, m11 = -FLT_MAX;
    for (int m = lane; m < NPT; m += 64) {
        float4 pa = sP[m], pb = sP[m + 32];
        m00 = fmaxf(m00, pdist(q0, pa)); m01 = fmaxf(m01, pdist(q0, pb));
        m10 = fmaxf(m10, pdist(q1, pa)); m11 = fmaxf(m11, pdist(q1, pb));
    }
    float vmax0 = fmaxf(m00, m01), vmax1 = fmaxf(m10, m11);

    unsigned mk0 = fkey(vmax0), mk1 = fkey(vmax1);
    unsigned tk0 = 0, tk1 = 0;
    #pragma unroll 1
    for (int k = 0; k < KNN; k++) {
        tk0 = __reduce_max_sync(0xffffffffu, mk0);
        tk1 = __reduce_max_sync(0xffffffffu, mk1);
        unsigned b0 = __ballot_sync(0xffffffffu, mk0 == tk0);
        unsigned b1 = __ballot_sync(0xffffffffu, mk1 == tk1);
        if (lane == __ffs(b0) - 1) mk0 = 0;
        if (lane == __ffs(b1) - 1) mk1 = 0;
    }
    float tval0 = unkey(tk0), tval1 = unkey(tk1);

    int base0 = 0, base1 = 0;
    for (int m = lane; m < NPT; m += 32) {
        float4 pm = sP[m];
        float pd0 = pdist(q0, pm);
        float pd1 = pdist(q1, pm);
        bool s0 = (pd0 >= tval0);
        unsigned k0 = __ballot_sync(0xffffffffu, s0);
        if (s0) {
            int pos = base0 + __popc(k0 & ((1u << lane) - 1));
            if (pos < 128) { sv[warp][0][pos] = pd0; si[warp][0][pos] = m; }
        }
        base0 += __popc(k0);
        bool s1 = (pd1 >= tval1);
        unsigned k1 = __ballot_sync(0xffffffffu, s1);
        if (s1) {
            int pos = base1 + __popc(k1 & ((1u << lane) - 1));
            if (pos < 128) { sv[warp][1][pos] = pd1; si[warp][1][pos] = m; }
        }
        base1 += __popc(k1);
    }
    __syncwarp();

    int S0 = base0 < 128 ? base0 : 128;
    int S1 = base1 < 128 ? base1 : 128;
    float v0[4], v1[4]; int id0[4], id1[4];
    #pragma unroll
    for (int j = 0; j < 4; j++) {
        int idx = lane + j*32;
        if (idx < S0) { v0[j] = sv[warp][0][idx]; id0[j] = si[warp][0][idx]; }
        else          { v0[j] = -FLT_MAX;         id0[j] = 0x7fffffff; }
        if (idx < S1) { v1[j] = sv[warp][1][idx]; id1[j] = si[warp][1][idx]; }
        else          { v1[j] = -FLT_MAX;         id1[j] = 0x7fffffff; }
    }
    #define CE(V_, I_, A_, B_) { \
        bool sw_ = (V_[B_] > V_[A_]) || (V_[B_] == V_[A_] && I_[B_] < I_[A_]); \
        if (sw_) { float tv_ = V_[A_]; V_[A_] = V_[B_]; V_[B_] = tv_; \
                   int ti_ = I_[A_]; I_[A_] = I_[B_]; I_[B_] = ti_; } }
    CE(v0,id0,0,1) CE(v0,id0,2,3) CE(v0,id0,0,2) CE(v0,id0,1,3) CE(v0,id0,1,2)
    CE(v1,id1,0,1) CE(v1,id1,2,3) CE(v1,id1,0,2) CE(v1,id1,1,3) CE(v1,id1,1,2)
    #undef CE

    int pg0 = b*NPT + n0, pg1 = pg0 + 1;
    #pragma unroll 1
    for (int k = 0; k < KNN; k++) {
        unsigned a0 = fkey(v0[0]);
        unsigned a1 = fkey(v1[0]);
        unsigned be0 = __reduce_max_sync(0xffffffffu, a0);
        unsigned be1 = __reduce_max_sync(0xffffffffu, a1);
        int c0 = (a0 == be0) ? id0[0] : 0x7fffffff;
        int c1 = (a1 == be1) ? id1[0] : 0x7fffffff;
        int bmi0 = __reduce_min_sync(0xffffffffu, c0);
        int bmi1 = __reduce_min_sync(0xffffffffu, c1);
        if (a0 == be0 && id0[0] == bmi0) {
            v0[0] = v0[1]; id0[0] = id0[1];
            v0[1] = v0[2]; id0[1] = id0[2];
            v0[2] = v0[3]; id0[2] = id0[3];
            v0[3] = -FLT_MAX; id0[3] = 0x7fffffff;
        }
        if (a1 == be1 && id1[0] == bmi1) {
            v1[0] = v1[1]; id1[0] = id1[1];
            v1[1] = v1[2]; id1[1] = id1[2];
            v1[2] = v1[3]; id1[2] = id1[3];
            v1[3] = -FLT_MAX; id1[3] = 0x7fffffff;
        }
        if (lane == 0) {
            int qg0 = b*NPT + bmi0;
            int qg1 = b*NPT + bmi1;
            d_nbr[pg0*KNN + k] = qg0;
            d_nbr[pg1*KNN + k] = qg1;
            atomicAdd(&d_deg[qg0], 1);
            atomicAdd(&d_deg[qg1], 1);
        }
    }
}

// ---------------- parallel scan ----------------
__global__ void k_scanA() {
    int t = threadIdx.x, g = blockIdx.x*1024 + t;
    int v = d_deg[g];
    int lane = t & 31, wid = t >> 5;
    int vv = v;
    #pragma unroll
    for (int o = 1; o < 32; o <<= 1) { int u = __shfl_up_sync(0xffffffffu, vv, o); if (lane >= o) vv += u; }
    __shared__ int ws[32];
    if (lane == 31) ws[wid] = vv;
    __syncthreads();
    if (wid == 0) {
        int w = ws[lane];
        #pragma unroll
        for (int o = 1; o < 32; o <<= 1) { int u = __shfl_up_sync(0xffffffffu, w, o); if (lane >= o) w += u; }
        ws[lane] = w;
    }
    __syncthreads();
    int incl = vv + (wid ? ws[wid-1] : 0);
    d_rowstart[g] = incl - v;
    if (t == 1023) d_bsum[blockIdx.x] = incl;
}

__global__ void k_scanB() {
    int g = blockIdx.x*256 + threadIdx.x;
    int sb = g >> 10;
    int off = 0;
    #pragma unroll 1
    for (int i = 0; i < sb; i++) off += d_bsum[i];
    int rs = d_rowstart[g] + off;
    d_rowstart[g] = rs;
    d_cursor[g] = rs;
    if (g == BNP - 1) {
        int tot = 0;
        #pragma unroll
        for (int i = 0; i < 16; i++) tot += d_bsum[i];
        d_rowstart[BNP] = tot;
    }
}

__global__ void k_fill() {
    int p = blockIdx.x*256 + threadIdx.x;
    if (p >= BNP) return;
    #pragma unroll
    for (int k = 0; k < KNN; k++) {
        int q = d_nbr[p*KNN + k];
        int pos = atomicAdd(&d_cursor[q], 1);
        d_rev[pos] = p;
    }
}

// ---------------- layer 0: sup0 = flat@w0 (fp16) ; rz = flat@wr + br ---------
__global__ void k_l0mm(const float* __restrict__ x, const float* __restrict__ w0,
                       const float* __restrict__ wr, const float* __restrict__ br) {
    int tid = threadIdx.x;
    int t = blockIdx.x*256 + tid;
    int p = t >> 6, c = t & 63;
    int b = p >> 11, n = p & 2047;
    const float* xb = x + b*3*NPT;
    float x0 = xb[n], x1 = xb[NPT + n], x2 = xb[2*NPT + n];
    d_suph[t] = __float2half_rn(x0*w0[c] + x1*w0[64+c] + x2*w0[128+c]);
    float rz = x0*wr[c] + x1*wr[64+c] + x2*wr[128+c] + br[c];
    d_rz[t] = rz;
    __shared__ float s1[256], s2[256];
    s1[tid] = rz; s2[tid] = rz*rz;
    __syncthreads();
    if (tid < 64) {
        float a = s1[tid] + s1[64+tid] + s1[128+tid] + s1[192+tid];
        float q = s2[tid] + s2[64+tid] + s2[128+tid] + s2[192+tid];
        atomicAdd(&d_sumB[tid], a);
        atomicAdd(&d_sqB[tid], q);
    }
}

// ---------------- gather: warp per point, half2 channel pairs ----------------
// thread owns channels (2*lane, 2*lane+1): one 4B half2 load per neighbor row
__global__ void __launch_bounds__(256) k_gather_stats(const float* __restrict__ bias, int layer) {
    int t = threadIdx.x, warp = t >> 5, lane = t & 31;
    int q = blockIdx.x*8 + warp;
    int s0 = d_rowstart[q], e0 = d_rowstart[q+1];
    int deg = e0 - s0;
    float a0 = bias[2*lane], a1 = bias[2*lane+1];
    const __half2* sup2 = (const __half2*)d_suph;
    int i = 0;
    while (i < deg) {
        int nload = deg - i; if (nload > 32) nload = 32;
        int idx = (lane < nload) ? d_rev[s0 + i + lane] : 0;
        int j = 0;
        for (; j + 4 <= nload; j += 4) {
            int r0 = __shfl_sync(0xffffffffu, idx, j);
            int r1 = __shfl_sync(0xffffffffu, idx, j+1);
            int r2 = __shfl_sync(0xffffffffu, idx, j+2);
            int r3 = __shfl_sync(0xffffffffu, idx, j+3);
            __half2 h0 = sup2[r0*32 + lane];
            __half2 h1 = sup2[r1*32 + lane];
            __half2 h2 = sup2[r2*32 + lane];
            __half2 h3 = sup2[r3*32 + lane];
            float2 f0 = __half22float2(h0), f1 = __half22float2(h1);
            float2 f2 = __half22float2(h2), f3 = __half22float2(h3);
            a0 += f0.x; a0 += f1.x; a0 += f2.x; a0 += f3.x;
            a1 += f0.y; a1 += f1.y; a1 += f2.y; a1 += f3.y;
        }
        for (; j < nload; j++) {
            int r = __shfl_sync(0xffffffffu, idx, j);
            float2 f = __half22float2(sup2[r*32 + lane]);
            a0 += f.x; a1 += f.y;
        }
        i += nload;
    }
    d_z[q*64 + 2*lane] = a0;
    d_z[q*64 + 2*lane + 1] = a1;
    __shared__ float s1[8][64], s2[8][64];
    s1[warp][2*lane] = a0;       s1[warp][2*lane+1] = a1;
    s2[warp][2*lane] = a0*a0;    s2[warp][2*lane+1] = a1*a1;
    __syncthreads();
    if (t < 64) {
        float sa = 0.f, sq = 0.f;
        #pragma unroll
        for (int wv = 0; wv < 8; wv++) { sa += s1[wv][t]; sq += s2[wv][t]; }
        atomicAdd(&d_sumA[layer*64 + t], sa);
        atomicAdd(&d_sqA[layer*64 + t], sq);
    }
}

// ---------------- fused post (layer 0) + mm for layer 1 ----------------
__global__ void __launch_bounds__(256) k_post0_mm(
        const float* __restrict__ g0, const float* __restrict__ be0,
        const float* __restrict__ gr, const float* __restrict__ ber,
        const float* __restrict__ W1) {
    __shared__ float Hs[64*64];
    __shared__ float Ws[64*64];
    int tid = threadIdx.x;
    int p0 = blockIdx.x*64;
    int c = tid & 63, rg = tid >> 6;
    float mA = d_sumA[c]*(1.f/BNP);
    float vA = d_sqA[c]*(1.f/BNP) - mA*mA;
    float sA = rsqrtf(vA + 1e-5f)*g0[c], bA = be0[c];
    float mB = d_sumB[c]*(1.f/BNP);
    float vB = d_sqB[c]*(1.f/BNP) - mB*mB;
    float sB = rsqrtf(vB + 1e-5f)*gr[c], bB = ber[c];
    #pragma unroll
    for (int i = 0; i < 16; i++) {
        int r = rg + i*4, p = p0 + r;
        float o = fmaxf((d_z[p*64+c] - mA)*sA + bA, 0.f);
        float rr = (d_rz[p*64+c] - mB)*sB + bB;
        float h = fmaxf(o + rr, 0.f);
        Hs[r*64+c] = h;
        d_F[p*FD + c] = h;
        __half hi = __float2half_rn(h);
        d_Fh[p*FD + c] = hi;
        d_Fl[p*FD + c] = __float2half_rn(h - __half2float(hi));
    }
    for (int i = tid; i < 4096; i += 256) Ws[i] = W1[i];
    __syncthreads();
    for (int r = rg; r < 64; r += 4) {
        float acc = 0.f;
        #pragma unroll 16
        for (int k = 0; k < 64; k++) acc += Hs[r*64+k]*Ws[k*64+c];
        d_suph[(p0+r)*64+c] = __float2half_rn(acc);
    }
}

// ---------------- fused post (layers 1,2) + mm for next layer ----------------
__global__ void __launch_bounds__(256) k_postL_mm(int layer,
        const float* __restrict__ G, const float* __restrict__ Be,
        const float* __restrict__ Wn) {
    __shared__ float Hs[64*64];
    __shared__ float Ws[64*64];
    int tid = threadIdx.x;
    int p0 = blockIdx.x*64;
    int c = tid & 63, rg = tid >> 6;
    float m = d_sumA[layer*64+c]*(1.f/BNP);
    float v = d_sqA[layer*64+c]*(1.f/BNP) - m*m;
    float sc = rsqrtf(v + 1e-5f)*G[c], bc = Be[c];
    #pragma unroll
    for (int i = 0; i < 16; i++) {
        int r = rg + i*4, p = p0 + r;
        float a = fmaxf((d_z[p*64+c] - m)*sc + bc, 0.f);
        float h = fmaxf(a + d_F[p*FD + (layer-1)*64 + c], 0.f);
        Hs[r*64+c] = h;
        d_F[p*FD + layer*64 + c] = h;
        __half hi = __float2half_rn(h);
        d_Fh[p*FD + layer*64 + c] = hi;
        d_Fl[p*FD + layer*64 + c] = __float2half_rn(h - __half2float(hi));
    }
    for (int i = tid; i < 4096; i += 256) Ws[i] = Wn[i];
    __syncthreads();
    for (int r = rg; r < 64; r += 4) {
        float acc = 0.f;
        #pragma unroll 16
        for (int k = 0; k < 64; k++) acc += Hs[r*64+k]*Ws[k*64+c];
        d_suph[(p0+r)*64+c] = __float2half_rn(acc);
    }
}

// ---------------- post layer 3 ----------------
__global__ void k_post3(const float* __restrict__ G, const float* __restrict__ Be) {
    int t = blockIdx.x*256 + threadIdx.x;
    int p = t >> 6, c = t & 63;
    float m = d_sumA[3*64+c]*(1.f/BNP);
    float v = d_sqA[3*64+c]*(1.f/BNP) - m*m;
    float a = fmaxf((d_z[t] - m)*rsqrtf(v + 1e-5f)*G[c] + Be[c], 0.f);
    float h = fmaxf(a + d_F[p*FD + 2*64 + c], 0.f);
    __half hi = __float2half_rn(h);
    d_Fh[p*FD + 3*64 + c] = hi;
    d_Fl[p*FD + 3*64 + c] = __float2half_rn(h - __half2float(hi));
}

// ---------------- conv GEMM: fp16 3-term split, tile 128x256, cp.async 2-stage
#define PITCH 80
#define TSZA  (128*PITCH)     // 10240
#define TSZB  (256*PITCH)     // 20480
#define STAGE (2*TSZA + 2*TSZB)   // 61440
#define SMEM_CONV (2*STAGE)       // 122880 B

__global__ void __launch_bounds__(256) k_conv_mma() {
    extern __shared__ __align__(16) uint8_t sm[];
    uint32_t sb = smem_u32(sm);

    int tid = threadIdx.x, wid = tid >> 5, lane = tid & 31;
    int warp_m = wid >> 2, warp_n = wid & 3;
    int bn = blockIdx.x;   // 0..63
    int bm = blockIdx.y;   // 0..7
    int bb = bn >> 3;      // batch

    const uint4* gAh = (const uint4*)d_Ah;
    const uint4* gAl = (const uint4*)d_Al;
    const uint4* gBh = (const uint4*)d_Fh;
    const uint4* gBl = (const uint4*)d_Fl;

    float C[4][8][4];
    #pragma unroll
    for (int i = 0; i < 4; i++)
        #pragma unroll
        for (int j = 0; j < 8; j++)
            #pragma unroll
            for (int q = 0; q < 4; q++) C[i][j][q] = 0.f;

    int rowA  = warp_m*64 + (lane & 15);
    int halfA = lane >> 4;
    uint32_t oAh = rowA*PITCH + halfA*16;
    uint32_t oAl = TSZA + rowA*PITCH + halfA*16;
    int rowB  = warp_n*64 + (lane & 7) + ((lane >> 4) << 3);
    int halfB = (lane >> 3) & 1;
    uint32_t oBh = 2*TSZA + rowB*PITCH + halfB*16;
    uint32_t oBl = 2*TSZA + TSZB + rowB*PITCH + halfB*16;

    auto issue = [&](int kc, int s) {
        uint32_t base = sb + s*STAGE;
        #pragma unroll
        for (int l = 0; l < 2; l++) {
            int i = tid + l*256;
            int row = i >> 2, c = i & 3;
            uint32_t so = row*PITCH + c*16;
            size_t ga = (size_t)(bm*128 + row)*32 + kc*4 + c;
            cp16(base + so,         gAh + ga);
            cp16(base + TSZA + so,  gAl + ga);
        }
        #pragma unroll
        for (int l = 0; l < 4; l++) {
            int i = tid + l*256;
            int row = i >> 2, c = i & 3;
            uint32_t so = row*PITCH + c*16;
            size_t gb = (size_t)(bn*256 + row)*32 + kc*4 + c;
            cp16(base + 2*TSZA + so,        gBh + gb);
            cp16(base + 2*TSZA + TSZB + so, gBl + gb);
        }
        CP_COMMIT();
    };

    issue(0, 0);
    for (int kc = 0; kc < 8; kc++) {
        int s = kc & 1;
        CP_WAIT0();
        __syncthreads();
        if (kc + 1 < 8) issue(kc + 1, s ^ 1);
        uint32_t stb = sb + s*STAGE;

        #pragma unroll
        for (int ksub = 0; ksub < 2; ksub++) {
            uint32_t koff = (ksub*2)*16;
            uint32_t bh[16], bl[16];
            #pragma unroll
            for (int nb = 0; nb < 4; nb++) {
                ldm_x4(bh + nb*4, stb + oBh + koff + nb*16*PITCH);
                ldm_x4(bl + nb*4, stb + oBl + koff + nb*16*PITCH);
            }
            #pragma unroll
            for (int mt = 0; mt < 4; mt++) {
                uint32_t ah[4], al[4];
                ldm_x4(ah, stb + oAh + koff + mt*16*PITCH);
                ldm_x4(al, stb + oAl + koff + mt*16*PITCH);
                #pragma unroll
                for (int nt = 0; nt < 8; nt++) {
                    const uint32_t* ph = &bh[(nt >> 1)*4 + (nt & 1)*2];
                    const uint32_t* pl = &bl[(nt >> 1)*4 + (nt & 1)*2];
                    mma16816h(C[mt][nt], ah, ph);
                    mma16816h(C[mt][nt], al, ph);
                    mma16816h(C[mt][nt], ah, pl);
                }
            }
        }
    }

    // epilogue: fp16 store + per-e BN partial stats + raw extrema
    #pragma unroll
    for (int mt = 0; mt < 4; mt++) {
        int e = bm*128 + warp_m*64 + mt*16 + (lane >> 2);
        float s0 = 0.f, q0 = 0.f, s1 = 0.f, q1 = 0.f;
        float mx0 = -FLT_MAX, mn0 = FLT_MAX, mx1 = -FLT_MAX, mn1 = FLT_MAX;
        #pragma unroll
        for (int nt = 0; nt < 8; nt++) {
            int p = bn*256 + warp_n*64 + nt*8 + (lane & 3)*2;
            float a0 = C[mt][nt][0], a1 = C[mt][nt][1];
            float a2 = C[mt][nt][2], a3 = C[mt][nt][3];
            *(__half2*)&d_Yh[(size_t)e*BNP + p] =
                __half2(__float2half_rn(a0), __float2half_rn(a1));
            *(__half2*)&d_Yh[(size_t)(e + 8)*BNP + p] =
                __half2(__float2half_rn(a2), __float2half_rn(a3));
            s0 += a0 + a1; q0 += a0*a0 + a1*a1;
            s1 += a2 + a3; q1 += a2*a2 + a3*a3;
            mx0 = fmaxf(mx0, fmaxf(a0, a1)); mn0 = fminf(mn0, fminf(a0, a1));
            mx1 = fmaxf(mx1, fmaxf(a2, a3)); mn1 = fminf(mn1, fminf(a2, a3));
        }
        #pragma unroll
        for (int o = 1; o < 4; o <<= 1) {
            s0 += __shfl_xor_sync(0xffffffffu, s0, o);
            q0 += __shfl_xor_sync(0xffffffffu, q0, o);
            s1 += __shfl_xor_sync(0xffffffffu, s1, o);
            q1 += __shfl_xor_sync(0xffffffffu, q1, o);
            mx0 = fmaxf(mx0, __shfl_xor_sync(0xffffffffu, mx0, o));
            mn0 = fminf(mn0, __shfl_xor_sync(0xffffffffu, mn0, o));
            mx1 = fmaxf(mx1, __shfl_xor_sync(0xffffffffu, mx1, o));
            mn1 = fminf(mn1, __shfl_xor_sync(0xffffffffu, mn1, o));
        }
        if ((lane & 3) == 0) {
            atomicAdd(&d_sumY[e], s0);     atomicAdd(&d_sqY[e], q0);
            atomicAdd(&d_sumY[e + 8], s1); atomicAdd(&d_sqY[e + 8], q1);
            atomicMax(&d_maxK[bb*EMB + e], fkey(mx0));
            atomicMin(&d_minK[bb*EMB + e], fkey(mn0));
            atomicMax(&d_maxK[bb*EMB + e + 8], fkey(mx1));
            atomicMin(&d_minK[bb*EMB + e + 8], fkey(mn1));
        }
    }
}

// ---------------- BN + leaky + mean pool (split: one block per (e,b)) --------
__global__ void k_reduce(const float* __restrict__ gf, const float* __restrict__ bef) {
    int e = blockIdx.x >> 3, b = blockIdx.x & 7;
    int t = threadIdx.x, lane = t & 31, w = t >> 5;
    float mu = d_sumY[e]*(1.f/BNP);
    float var = d_sqY[e]*(1.f/BNP) - mu*mu;
    float sc = rsqrtf(var + 1e-5f)*gf[e], sh = bef[e];
    const __half2* yb = (const __half2*)(d_Yh + (size_t)e*BNP + b*NPT);
    float sm = 0.f;
    #pragma unroll
    for (int j = t; j < NPT/2; j += 256) {
        float2 v2 = __half22float2(yb[j]);
        float v0 = (v2.x - mu)*sc + sh; v0 = v0 > 0.f ? v0 : 0.2f*v0;
        float v1 = (v2.y - mu)*sc + sh; v1 = v1 > 0.f ? v1 : 0.2f*v1;
        sm += v0 + v1;
    }
    #pragma unroll
    for (int o = 16; o; o >>= 1) sm += __shfl_xor_sync(0xffffffffu, sm, o);
    __shared__ float wsum[8];
    if (lane == 0) wsum[w] = sm;
    __syncthreads();
    if (t == 0) {
        float SM = 0.f;
        #pragma unroll
        for (int i = 0; i < 8; i++) SM += wsum[i];
        unsigned mk = (sc >= 0.f) ? d_maxK[b*EMB + e] : d_minK[b*EMB + e];
        float raw = unkey(mk);
        float v = (raw - mu)*sc + sh;
        v = v > 0.f ? v : 0.2f*v;
        d_x12[b*2*EMB + e] = v;
        d_x12[b*2*EMB + EMB + e] = SM*(1.f/NPT);
    }
}

// ---------------- head (k-split parallel) ----------------
__global__ void k_head1(const float* __restrict__ w1, const float* __restrict__ g6,
                        const float* __restrict__ b6) {
    int jl = threadIdx.x & 15, ks = threadIdx.x >> 4;
    int j = blockIdx.x*16 + jl;
    float acc[BB];
    #pragma unroll
    for (int b = 0; b < BB; b++) acc[b] = 0.f;
    for (int k = ks*128; k < ks*128 + 128; k++) {
        float wv = w1[k*512 + j];
        #pragma unroll
        for (int b = 0; b < BB; b++) acc[b] += d_x12[b*2*EMB + k]*wv;
    }
    __shared__ float sh[16][16][BB];
    #pragma unroll
    for (int b = 0; b < BB; b++) sh[ks][jl][b] = acc[b];
    __syncthreads();
    if (ks == 0) {
        #pragma unroll
        for (int b = 0; b < BB; b++) {
            float s = 0.f;
            #pragma unroll
            for (int i = 0; i < 16; i++) s += sh[i][jl][b];
            acc[b] = s;
        }
        float m = 0.f;
        #pragma unroll
        for (int b = 0; b < BB; b++) m += acc[b];
        m *= (1.f/BB);
        float var = 0.f;
        #pragma unroll
        for (int b = 0; b < BB; b++) { float d = acc[b]-m; var += d*d; }
        var *= (1.f/BB);
        float sc = rsqrtf(var + 1e-5f)*g6[j], bb = b6[j];
        #pragma unroll
        for (int b = 0; b < BB; b++) {
            float o = (acc[b]-m)*sc + bb;
            d_h512[b*512 + j] = o > 0.f ? o : 0.2f*o;
        }
    }
}

__global__ void k_head2(const float* __restrict__ w2, const float* __restrict__ b2,
                        const float* __restrict__ g7, const float* __restrict__ b7) {
    int jl = threadIdx.x & 31, ks = threadIdx.x >> 5;
    int j = blockIdx.x*32 + jl;
    float acc[BB];
    #pragma unroll
    for (int b = 0; b < BB; b++) acc[b] = 0.f;
    for (int k = ks*64; k < ks*64 + 64; k++) {
        float wv = w2[k*256 + j];
        #pragma unroll
        for (int b = 0; b < BB; b++) acc[b] += d_h512[b*512 + k]*wv;
    }
    __shared__ float sh[8][32][BB];
    #pragma unroll
    for (int b = 0; b < BB; b++) sh[ks][jl][b] = acc[b];
    __syncthreads();
    if (ks == 0) {
        #pragma unroll
        for (int b = 0; b < BB; b++) {
            float s = 0.f;
            #pragma unroll
            for (int i = 0; i < 8; i++) s += sh[i][jl][b];
            acc[b] = s + b2[j];
        }
        float m = 0.f;
        #pragma unroll
        for (int b = 0; b < BB; b++) m += acc[b];
        m *= (1.f/BB);
        float var = 0.f;
        #pragma unroll
        for (int b = 0; b < BB; b++) { float d = acc[b]-m; var += d*d; }
        var *= (1.f/BB);
        float sc = rsqrtf(var + 1e-5f)*g7[j], bb = b7[j];
        #pragma unroll
        for (int b = 0; b < BB; b++) {
            float o = (acc[b]-m)*sc + bb;
            d_h256[b*256 + j] = o > 0.f ? o : 0.2f*o;
        }
    }
}

__global__ void k_head3(const float* __restrict__ w3, const float* __restrict__ b3,
                        float* __restrict__ out) {
    int jl = threadIdx.x & 63, ks = threadIdx.x >> 6;
    float acc[BB];
    #pragma unroll
    for (int b = 0; b < BB; b++) acc[b] = 0.f;
    if (jl < 40) {
        for (int k = ks*64; k < ks*64 + 64; k++) {
            float wv = w3[k*40 + jl];
            #pragma unroll
            for (int b = 0; b < BB; b++) acc[b] += d_h256[b*256 + k]*wv;
        }
    }
    __shared__ float sh[4][64][BB];
    #pragma unroll
    for (int b = 0; b < BB; b++) sh[ks][jl][b] = acc[b];
    __syncthreads();
    if (ks == 0 && jl < 40) {
        #pragma unroll
        for (int b = 0; b < BB; b++) {
            float s = b3[jl];
            #pragma unroll
            for (int i = 0; i < 4; i++) s += sh[i][jl][b];
            out[b*40 + jl] = s;
        }
    }
}

// ---------------- launch ----------------
extern "C" void kernel_launch(void* const* d_in, const int* in_sizes, int n_in,
                              void* d_out, int out_size) {
    const float* x     = (const float*)d_in[0];
    const float* w0    = (const float*)d_in[1];
    const float* b0    = (const float*)d_in[2];
    const float* g0    = (const float*)d_in[3];
    const float* be0   = (const float*)d_in[4];
    const float* wr    = (const float*)d_in[5];
    const float* br    = (const float*)d_in[6];
    const float* gr    = (const float*)d_in[7];
    const float* ber   = (const float*)d_in[8];
    const float* W     = (const float*)d_in[9];
    const float* Bv    = (const float*)d_in[10];
    const float* G     = (const float*)d_in[11];
    const float* Be    = (const float*)d_in[12];
    const float* wconv = (const float*)d_in[13];
    const float* gf    = (const float*)d_in[14];
    const float* bef   = (const float*)d_in[15];
    const float* w1    = (const float*)d_in[16];
    const float* g6    = (const float*)d_in[17];
    const float* b6    = (const float*)d_in[18];
    const float* w2    = (const float*)d_in[19];
    const float* b2    = (const float*)d_in[20];
    const float* g7    = (const float*)d_in[21];
    const float* b7    = (const float*)d_in[22];
    const float* w3    = (const float*)d_in[23];
    const float* b3    = (const float*)d_in[24];
    float* out = (float*)d_out;

    static int smem_set = 0;
    if (!smem_set) {
        cudaFuncSetAttribute(k_conv_mma, cudaFuncAttributeMaxDynamicSharedMemorySize, SMEM_CONV);
        smem_set = 1;
    }

    // graph build (k_knn kept in the 4th = captured slot)
    k_begin<<<256, 256>>>(wconv);
    k_prep<<<64, 256>>>(x);
    k_l0mm<<<4096, 256>>>(x, w0, wr, br);
    k_knn<<<1024, 256>>>();
    k_scanA<<<16, 1024>>>();
    k_scanB<<<64, 256>>>();
    k_fill<<<64, 256>>>();

    // layer 0
    k_gather_stats<<<2048, 256>>>(b0, 0);
    k_post0_mm<<<256, 256>>>(g0, be0, gr, ber, W);

    // layers 1..3
    k_gather_stats<<<2048, 256>>>(Bv, 1);
    k_postL_mm<<<256, 256>>>(1, G, Be, W + 4096);
    k_gather_stats<<<2048, 256>>>(Bv + 64, 2);
    k_postL_mm<<<256, 256>>>(2, G + 64, Be + 64, W + 8192);
    k_gather_stats<<<2048, 256>>>(Bv + 128, 3);
    k_post3<<<4096, 256>>>(G + 128, Be + 128);

    // conv 256 -> 1024 (fp16 3-term, 128x256 tile) + fused stats/extrema
    dim3 cgrid(64, 8);
    k_conv_mma<<<cgrid, 256, SMEM_CONV>>>();
    k_reduce<<<8192, 256>>>(gf, bef);

    // head
    k_head1<<<32, 256>>>(w1, g6, b6);
    k_head2<<<8, 256>>>(w2, b2, g7, b7);
    k_head3<<<1, 256>>>(w3, b3, out);
}

// round 16
// speedup vs baseline: 1.2090x; 1.0051x over previous
#include <cuda_runtime.h>
#include <cuda_fp16.h>
#include <float.h>
#include <stdint.h>

// ---------------- problem constants ----------------
#define BB    8
#define NPT   2048
#define BNP   16384          // BB*NPT
#define KNN   20
#define CH    64
#define FD    256            // 4*CH
#define EMB   1024

// ---------------- scratch (device globals; no mallocs allowed) ----------------
__device__ float4 d_P4[BB*NPT];
__device__ int   d_nbr[BNP*KNN];
__device__ int   d_deg[BNP];
__device__ int   d_rowstart[BNP+1];
__device__ int   d_cursor[BNP];
__device__ int   d_bsum[16];
__device__ int   d_rev[BNP*KNN];
__device__ float d_F[BNP*FD];
__device__ float d_sup[BNP*CH];            // support, fp32 (accuracy-critical)
__device__ float d_z[BNP*CH];
__device__ float d_rz[BNP*CH];
__device__ __half d_Yh[(size_t)EMB*BNP];   // conv output fp16 [e][p], 32 MB
__device__ unsigned d_maxK[BB*EMB], d_minK[BB*EMB];
__device__ float d_x12[BB*2*EMB];
__device__ float d_h512[BB*512];
__device__ float d_h256[BB*256];
__device__ float d_sumA[4*CH], d_sqA[4*CH];
__device__ float d_sumB[CH], d_sqB[CH];
__device__ float d_sumY[EMB], d_sqY[EMB];
__device__ __half d_Ah[EMB*FD], d_Al[EMB*FD];   // wconv fp16 hi/lo
__device__ __half d_Fh[BNP*FD], d_Fl[BNP*FD];   // features fp16 hi/lo

// ---------------- helpers ----------------
__device__ __forceinline__ uint32_t smem_u32(const void* p) {
    uint32_t a;
    asm("{ .reg .u64 t; cvta.to.shared.u64 t, %1; cvt.u32.u64 %0, t; }" : "=r"(a) : "l"(p));
    return a;
}
__device__ __forceinline__ void ldm_x4(uint32_t* r, uint32_t addr) {
    asm volatile("ldmatrix.sync.aligned.m8n8.x4.shared.b16 {%0,%1,%2,%3}, [%4];"
        : "=r"(r[0]), "=r"(r[1]), "=r"(r[2]), "=r"(r[3]) : "r"(addr));
}
__device__ __forceinline__ void mma16816h(float* c, const uint32_t* a, const uint32_t* b) {
    asm volatile(
        "mma.sync.aligned.m16n8k16.row.col.f32.f16.f16.f32 "
        "{%0,%1,%2,%3}, {%4,%5,%6,%7}, {%8,%9}, {%0,%1,%2,%3};"
        : "+f"(c[0]), "+f"(c[1]), "+f"(c[2]), "+f"(c[3])
        : "r"(a[0]), "r"(a[1]), "r"(a[2]), "r"(a[3]), "r"(b[0]), "r"(b[1]));
}
__device__ __forceinline__ void cp16(uint32_t sdst, const void* gsrc) {
    asm volatile("cp.async.cg.shared.global [%0], [%1], 16;" :: "r"(sdst), "l"(gsrc));
}
#define CP_COMMIT() asm volatile("cp.async.commit_group;" ::: "memory")
#define CP_WAIT0()  asm volatile("cp.async.wait_group 0;" ::: "memory")

__device__ __forceinline__ unsigned fkey(float f) {
    unsigned u = __float_as_uint(f);
    return (u & 0x80000000u) ? ~u : (u | 0x80000000u);
}
__device__ __forceinline__ float unkey(unsigned k) {
    return (k & 0x80000000u) ? __uint_as_float(k & 0x7fffffffu) : __uint_as_float(~k);
}

// ---------------- begin: zero stats/deg + wconv fp16 hi/lo split -------------
__global__ void k_begin(const float* __restrict__ w) {
    int t = blockIdx.x*256 + threadIdx.x;   // 65536 threads
    if (t < BNP) d_deg[t] = 0;
    if (t < 4*CH) { d_sumA[t] = 0.f; d_sqA[t] = 0.f; }
    if (t < CH)   { d_sumB[t] = 0.f; d_sqB[t] = 0.f; }
    if (t < EMB)  { d_sumY[t] = 0.f; d_sqY[t] = 0.f; }
    if (t < BB*EMB) { d_maxK[t] = 0u; d_minK[t] = 0xFFFFFFFFu; }
    float4 x = ((const float4*)w)[t];
    __half h0 = __float2half_rn(x.x), h1 = __float2half_rn(x.y);
    __half h2 = __float2half_rn(x.z), h3 = __float2half_rn(x.w);
    __half l0 = __float2half_rn(x.x - __half2float(h0));
    __half l1 = __float2half_rn(x.y - __half2float(h1));
    __half l2 = __float2half_rn(x.z - __half2float(h2));
    __half l3 = __float2half_rn(x.w - __half2float(h3));
    ((__half2*)d_Ah)[t*2]   = __half2(h0, h1);
    ((__half2*)d_Ah)[t*2+1] = __half2(h2, h3);
    ((__half2*)d_Al)[t*2]   = __half2(l0, l1);
    ((__half2*)d_Al)[t*2+1] = __half2(l2, l3);
}

// pts[b,c,n] = x[b, (c*N+n)%3, (c*N+n)/3]
__global__ void k_prep(const float* __restrict__ x) {
    int t = blockIdx.x*256 + threadIdx.x;
    if (t >= BNP) return;
    int b = t >> 11, n = t & 2047;
    const float* xb = x + b*3*NPT;
    float v[3]; float acc = 0.f;
    #pragma unroll
    for (int c = 0; c < 3; c++) {
        int L = c*NPT + n;
        v[c] = xb[(L % 3)*NPT + (L / 3)];
        acc += v[c]*v[c];
    }
    d_P4[t] = make_float4(v[0], v[1], v[2], acc);
}

// identical arithmetic in both KNN passes
__device__ __forceinline__ float pdist(float4 q, float4 pm) {
    float dot = __fmaf_rn(q.x, pm.x, __fmaf_rn(q.y, pm.y, __fmul_rn(q.z, pm.z)));
    return __fadd_rn(__fmaf_rn(2.f, dot, -q.w), -pm.w);
}

// ---------------- knn: two-pass threshold, 2 rows per warp, interleaved chains
__global__ void __launch_bounds__(256) k_knn() {
    __shared__ float4 sP[NPT];
    __shared__ float sv[8][2][128];
    __shared__ int   si[8][2][128];
    int b = blockIdx.x >> 7;
    int chunk = blockIdx.x & 127;
    for (int i = threadIdx.x; i < NPT; i += 256)
        sP[i] = d_P4[b*NPT + i];
    __syncthreads();

    int warp = threadIdx.x >> 5, lane = threadIdx.x & 31;
    int n0 = chunk*16 + warp*2;
    float4 q0 = sP[n0], q1 = sP[n0 + 1];

    float m00 = -FLT_MAX, m01 = -FLT_MAX, m10 = -FLT_MAX, m11 = -FLT_MAX;
    for (int m = lane; m < NPT; m += 64) {
        float4 pa = sP[m], pb = sP[m + 32];
        m00 = fmaxf(m00, pdist(q0, pa)); m01 = fmaxf(m01, pdist(q0, pb));
        m10 = fmaxf(m10, pdist(q1, pa)); m11 = fmaxf(m11, pdist(q1, pb));
    }
    float vmax0 = fmaxf(m00, m01), vmax1 = fmaxf(m10, m11);

    unsigned mk0 = fkey(vmax0), mk1 = fkey(vmax1);
    unsigned tk0 = 0, tk1 = 0;
    #pragma unroll 1
    for (int k = 0; k < KNN; k++) {
        tk0 = __reduce_max_sync(0xffffffffu, mk0);
        tk1 = __reduce_max_sync(0xffffffffu, mk1);
        unsigned b0 = __ballot_sync(0xffffffffu, mk0 == tk0);
        unsigned b1 = __ballot_sync(0xffffffffu, mk1 == tk1);
        if (lane == __ffs(b0) - 1) mk0 = 0;
        if (lane == __ffs(b1) - 1) mk1 = 0;
    }
    float tval0 = unkey(tk0), tval1 = unkey(tk1);

    int base0 = 0, base1 = 0;
    for (int m = lane; m < NPT; m += 32) {
        float4 pm = sP[m];
        float pd0 = pdist(q0, pm);
        float pd1 = pdist(q1, pm);
        bool s0 = (pd0 >= tval0);
        unsigned k0 = __ballot_sync(0xffffffffu, s0);
        if (s0) {
            int pos = base0 + __popc(k0 & ((1u << lane) - 1));
            if (pos < 128) { sv[warp][0][pos] = pd0; si[warp][0][pos] = m; }
        }
        base0 += __popc(k0);
        bool s1 = (pd1 >= tval1);
        unsigned k1 = __ballot_sync(0xffffffffu, s1);
        if (s1) {
            int pos = base1 + __popc(k1 & ((1u << lane) - 1));
            if (pos < 128) { sv[warp][1][pos] = pd1; si[warp][1][pos] = m; }
        }
        base1 += __popc(k1);
    }
    __syncwarp();

    int S0 = base0 < 128 ? base0 : 128;
    int S1 = base1 < 128 ? base1 : 128;
    float v0[4], v1[4]; int id0[4], id1[4];
    #pragma unroll
    for (int j = 0; j < 4; j++) {
        int idx = lane + j*32;
        if (idx < S0) { v0[j] = sv[warp][0][idx]; id0[j] = si[warp][0][idx]; }
        else          { v0[j] = -FLT_MAX;         id0[j] = 0x7fffffff; }
        if (idx < S1) { v1[j] = sv[warp][1][idx]; id1[j] = si[warp][1][idx]; }
        else          { v1[j] = -FLT_MAX;         id1[j] = 0x7fffffff; }
    }
    #define CE(V_, I_, A_, B_) { \
        bool sw_ = (V_[B_] > V_[A_]) || (V_[B_] == V_[A_] && I_[B_] < I_[A_]); \
        if (sw_) { float tv_ = V_[A_]; V_[A_] = V_[B_]; V_[B_] = tv_; \
                   int ti_ = I_[A_]; I_[A_] = I_[B_]; I_[B_] = ti_; } }
    CE(v0,id0,0,1) CE(v0,id0,2,3) CE(v0,id0,0,2) CE(v0,id0,1,3) CE(v0,id0,1,2)
    CE(v1,id1,0,1) CE(v1,id1,2,3) CE(v1,id1,0,2) CE(v1,id1,1,3) CE(v1,id1,1,2)
    #undef CE

    int pg0 = b*NPT + n0, pg1 = pg0 + 1;
    #pragma unroll 1
    for (int k = 0; k < KNN; k++) {
        unsigned a0 = fkey(v0[0]);
        unsigned a1 = fkey(v1[0]);
        unsigned be0 = __reduce_max_sync(0xffffffffu, a0);
        unsigned be1 = __reduce_max_sync(0xffffffffu, a1);
        int c0 = (a0 == be0) ? id0[0] : 0x7fffffff;
        int c1 = (a1 == be1) ? id1[0] : 0x7fffffff;
        int bmi0 = __reduce_min_sync(0xffffffffu, c0);
        int bmi1 = __reduce_min_sync(0xffffffffu, c1);
        if (a0 == be0 && id0[0] == bmi0) {
            v0[0] = v0[1]; id0[0] = id0[1];
            v0[1] = v0[2]; id0[1] = id0[2];
            v0[2] = v0[3]; id0[2] = id0[3];
            v0[3] = -FLT_MAX; id0[3] = 0x7fffffff;
        }
        if (a1 == be1 && id1[0] == bmi1) {
            v1[0] = v1[1]; id1[0] = id1[1];
            v1[1] = v1[2]; id1[1] = id1[2];
            v1[2] = v1[3]; id1[2] = id1[3];
            v1[3] = -FLT_MAX; id1[3] = 0x7fffffff;
        }
        if (lane == 0) {
            int qg0 = b*NPT + bmi0;
            int qg1 = b*NPT + bmi1;
            d_nbr[pg0*KNN + k] = qg0;
            d_nbr[pg1*KNN + k] = qg1;
            atomicAdd(&d_deg[qg0], 1);
            atomicAdd(&d_deg[qg1], 1);
        }
    }
}

// ---------------- parallel scan ----------------
__global__ void k_scanA() {
    int t = threadIdx.x, g = blockIdx.x*1024 + t;
    int v = d_deg[g];
    int lane = t & 31, wid = t >> 5;
    int vv = v;
    #pragma unroll
    for (int o = 1; o < 32; o <<= 1) { int u = __shfl_up_sync(0xffffffffu, vv, o); if (lane >= o) vv += u; }
    __shared__ int ws[32];
    if (lane == 31) ws[wid] = vv;
    __syncthreads();
    if (wid == 0) {
        int w = ws[lane];
        #pragma unroll
        for (int o = 1; o < 32; o <<= 1) { int u = __shfl_up_sync(0xffffffffu, w, o); if (lane >= o) w += u; }
        ws[lane] = w;
    }
    __syncthreads();
    int incl = vv + (wid ? ws[wid-1] : 0);
    d_rowstart[g] = incl - v;
    if (t == 1023) d_bsum[blockIdx.x] = incl;
}

__global__ void k_scanB() {
    int g = blockIdx.x*256 + threadIdx.x;
    int sb = g >> 10;
    int off = 0;
    #pragma unroll 1
    for (int i = 0; i < sb; i++) off += d_bsum[i];
    int rs = d_rowstart[g] + off;
    d_rowstart[g] = rs;
    d_cursor[g] = rs;
    if (g == BNP - 1) {
        int tot = 0;
        #pragma unroll
        for (int i = 0; i < 16; i++) tot += d_bsum[i];
        d_rowstart[BNP] = tot;
    }
}

__global__ void k_fill() {
    int p = blockIdx.x*256 + threadIdx.x;
    if (p >= BNP) return;
    #pragma unroll
    for (int k = 0; k < KNN; k++) {
        int q = d_nbr[p*KNN + k];
        int pos = atomicAdd(&d_cursor[q], 1);
        d_rev[pos] = p;
    }
}

// ---------------- layer 0: sup0 = flat@w0 ; rz = flat@wr + br (+ rz stats) ----
__global__ void k_l0mm(const float* __restrict__ x, const float* __restrict__ w0,
                       const float* __restrict__ wr, const float* __restrict__ br) {
    int tid = threadIdx.x;
    int t = blockIdx.x*256 + tid;
    int p = t >> 6, c = t & 63;
    int b = p >> 11, n = p & 2047;
    const float* xb = x + b*3*NPT;
    float x0 = xb[n], x1 = xb[NPT + n], x2 = xb[2*NPT + n];
    d_sup[t] = x0*w0[c] + x1*w0[64+c] + x2*w0[128+c];
    float rz = x0*wr[c] + x1*wr[64+c] + x2*wr[128+c] + br[c];
    d_rz[t] = rz;
    __shared__ float s1[256], s2[256];
    s1[tid] = rz; s2[tid] = rz*rz;
    __syncthreads();
    if (tid < 64) {
        float a = s1[tid] + s1[64+tid] + s1[128+tid] + s1[192+tid];
        float q = s2[tid] + s2[64+tid] + s2[128+tid] + s2[192+tid];
        atomicAdd(&d_sumB[tid], a);
        atomicAdd(&d_sqB[tid], q);
    }
}

// ---------------- gather: warp per point, float2 channel pairs ----------------
// thread owns channels (2*lane, 2*lane+1): one 8B load per neighbor row
__global__ void __launch_bounds__(256) k_gather_stats(const float* __restrict__ bias, int layer) {
    int t = threadIdx.x, warp = t >> 5, lane = t & 31;
    int q = blockIdx.x*8 + warp;
    int s0 = d_rowstart[q], e0 = d_rowstart[q+1];
    int deg = e0 - s0;
    float a0 = bias[2*lane], a1 = bias[2*lane+1];
    const float2* sup2 = (const float2*)d_sup;
    int i = 0;
    while (i < deg) {
        int nload = deg - i; if (nload > 32) nload = 32;
        int idx = (lane < nload) ? d_rev[s0 + i + lane] : 0;
        int j = 0;
        for (; j + 4 <= nload; j += 4) {
            int r0 = __shfl_sync(0xffffffffu, idx, j);
            int r1 = __shfl_sync(0xffffffffu, idx, j+1);
            int r2 = __shfl_sync(0xffffffffu, idx, j+2);
            int r3 = __shfl_sync(0xffffffffu, idx, j+3);
            float2 f0 = sup2[r0*32 + lane];
            float2 f1 = sup2[r1*32 + lane];
            float2 f2 = sup2[r2*32 + lane];
            float2 f3 = sup2[r3*32 + lane];
            a0 += f0.x; a0 += f1.x; a0 += f2.x; a0 += f3.x;
            a1 += f0.y; a1 += f1.y; a1 += f2.y; a1 += f3.y;
        }
        for (; j < nload; j++) {
            int r = __shfl_sync(0xffffffffu, idx, j);
            float2 f = sup2[r*32 + lane];
            a0 += f.x; a1 += f.y;
        }
        i += nload;
    }
    d_z[q*64 + 2*lane] = a0;
    d_z[q*64 + 2*lane + 1] = a1;
    __shared__ float s1[8][64], s2[8][64];
    s1[warp][2*lane] = a0;       s1[warp][2*lane+1] = a1;
    s2[warp][2*lane] = a0*a0;    s2[warp][2*lane+1] = a1*a1;
    __syncthreads();
    if (t < 64) {
        float sa = 0.f, sq = 0.f;
        #pragma unroll
        for (int wv = 0; wv < 8; wv++) { sa += s1[wv][t]; sq += s2[wv][t]; }
        atomicAdd(&d_sumA[layer*64 + t], sa);
        atomicAdd(&d_sqA[layer*64 + t], sq);
    }
}

// ---------------- fused post (layer 0) + mm for layer 1 ----------------
__global__ void __launch_bounds__(256) k_post0_mm(
        const float* __restrict__ g0, const float* __restrict__ be0,
        const float* __restrict__ gr, const float* __restrict__ ber,
        const float* __restrict__ W1) {
    __shared__ float Hs[64*64];
    __shared__ float Ws[64*64];
    int tid = threadIdx.x;
    int p0 = blockIdx.x*64;
    int c = tid & 63, rg = tid >> 6;
    float mA = d_sumA[c]*(1.f/BNP);
    float vA = d_sqA[c]*(1.f/BNP) - mA*mA;
    float sA = rsqrtf(vA + 1e-5f)*g0[c], bA = be0[c];
    float mB = d_sumB[c]*(1.f/BNP);
    float vB = d_sqB[c]*(1.f/BNP) - mB*mB;
    float sB = rsqrtf(vB + 1e-5f)*gr[c], bB = ber[c];
    #pragma unroll
    for (int i = 0; i < 16; i++) {
        int r = rg + i*4, p = p0 + r;
        float o = fmaxf((d_z[p*64+c] - mA)*sA + bA, 0.f);
        float rr = (d_rz[p*64+c] - mB)*sB + bB;
        float h = fmaxf(o + rr, 0.f);
        Hs[r*64+c] = h;
        d_F[p*FD + c] = h;
        __half hi = __float2half_rn(h);
        d_Fh[p*FD + c] = hi;
        d_Fl[p*FD + c] = __float2half_rn(h - __half2float(hi));
    }
    for (int i = tid; i < 4096; i += 256) Ws[i] = W1[i];
    __syncthreads();
    for (int r = rg; r < 64; r += 4) {
        float acc = 0.f;
        #pragma unroll 16
        for (int k = 0; k < 64; k++) acc += Hs[r*64+k]*Ws[k*64+c];
        d_sup[(p0+r)*64+c] = acc;
    }
}

// ---------------- fused post (layers 1,2) + mm for next layer ----------------
__global__ void __launch_bounds__(256) k_postL_mm(int layer,
        const float* __restrict__ G, const float* __restrict__ Be,
        const float* __restrict__ Wn) {
    __shared__ float Hs[64*64];
    __shared__ float Ws[64*64];
    int tid = threadIdx.x;
    int p0 = blockIdx.x*64;
    int c = tid & 63, rg = tid >> 6;
    float m = d_sumA[layer*64+c]*(1.f/BNP);
    float v = d_sqA[layer*64+c]*(1.f/BNP) - m*m;
    float sc = rsqrtf(v + 1e-5f)*G[c], bc = Be[c];
    #pragma unroll
    for (int i = 0; i < 16; i++) {
        int r = rg + i*4, p = p0 + r;
        float a = fmaxf((d_z[p*64+c] - m)*sc + bc, 0.f);
        float h = fmaxf(a + d_F[p*FD + (layer-1)*64 + c], 0.f);
        Hs[r*64+c] = h;
        d_F[p*FD + layer*64 + c] = h;
        __half hi = __float2half_rn(h);
        d_Fh[p*FD + layer*64 + c] = hi;
        d_Fl[p*FD + layer*64 + c] = __float2half_rn(h - __half2float(hi));
    }
    for (int i = tid; i < 4096; i += 256) Ws[i] = Wn[i];
    __syncthreads();
    for (int r = rg; r < 64; r += 4) {
        float acc = 0.f;
        #pragma unroll 16
        for (int k = 0; k < 64; k++) acc += Hs[r*64+k]*Ws[k*64+c];
        d_sup[(p0+r)*64+c] = acc;
    }
}

// ---------------- post layer 3 ----------------
__global__ void k_post3(const float* __restrict__ G, const float* __restrict__ Be) {
    int t = blockIdx.x*256 + threadIdx.x;
    int p = t >> 6, c = t & 63;
    float m = d_sumA[3*64+c]*(1.f/BNP);
    float v = d_sqA[3*64+c]*(1.f/BNP) - m*m;
    float a = fmaxf((d_z[t] - m)*rsqrtf(v + 1e-5f)*G[c] + Be[c], 0.f);
    float h = fmaxf(a + d_F[p*FD + 2*64 + c], 0.f);
    __half hi = __float2half_rn(h);
    d_Fh[p*FD + 3*64 + c] = hi;
    d_Fl[p*FD + 3*64 + c] = __float2half_rn(h - __half2float(hi));
}

// ---------------- conv GEMM: fp16 3-term split, tile 128x256, cp.async 2-stage
#define PITCH 80
#define TSZA  (128*PITCH)     // 10240
#define TSZB  (256*PITCH)     // 20480
#define STAGE (2*TSZA + 2*TSZB)   // 61440
#define SMEM_CONV (2*STAGE)       // 122880 B

__global__ void __launch_bounds__(256) k_conv_mma() {
    extern __shared__ __align__(16) uint8_t sm[];
    uint32_t sb = smem_u32(sm);

    int tid = threadIdx.x, wid = tid >> 5, lane = tid & 31;
    int warp_m = wid >> 2, warp_n = wid & 3;
    int bn = blockIdx.x;   // 0..63
    int bm = blockIdx.y;   // 0..7
    int bb = bn >> 3;      // batch

    const uint4* gAh = (const uint4*)d_Ah;
    const uint4* gAl = (const uint4*)d_Al;
    const uint4* gBh = (const uint4*)d_Fh;
    const uint4* gBl = (const uint4*)d_Fl;

    float C[4][8][4];
    #pragma unroll
    for (int i = 0; i < 4; i++)
        #pragma unroll
        for (int j = 0; j < 8; j++)
            #pragma unroll
            for (int q = 0; q < 4; q++) C[i][j][q] = 0.f;

    int rowA  = warp_m*64 + (lane & 15);
    int halfA = lane >> 4;
    uint32_t oAh = rowA*PITCH + halfA*16;
    uint32_t oAl = TSZA + rowA*PITCH + halfA*16;
    int rowB  = warp_n*64 + (lane & 7) + ((lane >> 4) << 3);
    int halfB = (lane >> 3) & 1;
    uint32_t oBh = 2*TSZA + rowB*PITCH + halfB*16;
    uint32_t oBl = 2*TSZA + TSZB + rowB*PITCH + halfB*16;

    auto issue = [&](int kc, int s) {
        uint32_t base = sb + s*STAGE;
        #pragma unroll
        for (int l = 0; l < 2; l++) {
            int i = tid + l*256;
            int row = i >> 2, c = i & 3;
            uint32_t so = row*PITCH + c*16;
            size_t ga = (size_t)(bm*128 + row)*32 + kc*4 + c;
            cp16(base + so,         gAh + ga);
            cp16(base + TSZA + so,  gAl + ga);
        }
        #pragma unroll
        for (int l = 0; l < 4; l++) {
            int i = tid + l*256;
            int row = i >> 2, c = i & 3;
            uint32_t so = row*PITCH + c*16;
            size_t gb = (size_t)(bn*256 + row)*32 + kc*4 + c;
            cp16(base + 2*TSZA + so,        gBh + gb);
            cp16(base + 2*TSZA + TSZB + so, gBl + gb);
        }
        CP_COMMIT();
    };

    issue(0, 0);
    for (int kc = 0; kc < 8; kc++) {
        int s = kc & 1;
        CP_WAIT0();
        __syncthreads();
        if (kc + 1 < 8) issue(kc + 1, s ^ 1);
        uint32_t stb = sb + s*STAGE;

        #pragma unroll
        for (int ksub = 0; ksub < 2; ksub++) {
            uint32_t koff = (ksub*2)*16;
            uint32_t bh[16], bl[16];
            #pragma unroll
            for (int nb = 0; nb < 4; nb++) {
                ldm_x4(bh + nb*4, stb + oBh + koff + nb*16*PITCH);
                ldm_x4(bl + nb*4, stb + oBl + koff + nb*16*PITCH);
            }
            #pragma unroll
            for (int mt = 0; mt < 4; mt++) {
                uint32_t ah[4], al[4];
                ldm_x4(ah, stb + oAh + koff + mt*16*PITCH);
                ldm_x4(al, stb + oAl + koff + mt*16*PITCH);
                #pragma unroll
                for (int nt = 0; nt < 8; nt++) {
                    const uint32_t* ph = &bh[(nt >> 1)*4 + (nt & 1)*2];
                    const uint32_t* pl = &bl[(nt >> 1)*4 + (nt & 1)*2];
                    mma16816h(C[mt][nt], ah, ph);
                    mma16816h(C[mt][nt], al, ph);
                    mma16816h(C[mt][nt], ah, pl);
                }
            }
        }
    }

    // epilogue: fp16 store + per-e BN partial stats + raw extrema
    #pragma unroll
    for (int mt = 0; mt < 4; mt++) {
        int e = bm*128 + warp_m*64 + mt*16 + (lane >> 2);
        float s0 = 0.f, q0 = 0.f, s1 = 0.f, q1 = 0.f;
        float mx0 = -FLT_MAX, mn0 = FLT_MAX, mx1 = -FLT_MAX, mn1 = FLT_MAX;
        #pragma unroll
        for (int nt = 0; nt < 8; nt++) {
            int p = bn*256 + warp_n*64 + nt*8 + (lane & 3)*2;
            float a0 = C[mt][nt][0], a1 = C[mt][nt][1];
            float a2 = C[mt][nt][2], a3 = C[mt][nt][3];
            *(__half2*)&d_Yh[(size_t)e*BNP + p] =
                __half2(__float2half_rn(a0), __float2half_rn(a1));
            *(__half2*)&d_Yh[(size_t)(e + 8)*BNP + p] =
                __half2(__float2half_rn(a2), __float2half_rn(a3));
            s0 += a0 + a1; q0 += a0*a0 + a1*a1;
            s1 += a2 + a3; q1 += a2*a2 + a3*a3;
            mx0 = fmaxf(mx0, fmaxf(a0, a1)); mn0 = fminf(mn0, fminf(a0, a1));
            mx1 = fmaxf(mx1, fmaxf(a2, a3)); mn1 = fminf(mn1, fminf(a2, a3));
        }
        #pragma unroll
        for (int o = 1; o < 4; o <<= 1) {
            s0 += __shfl_xor_sync(0xffffffffu, s0, o);
            q0 += __shfl_xor_sync(0xffffffffu, q0, o);
            s1 += __shfl_xor_sync(0xffffffffu, s1, o);
            q1 += __shfl_xor_sync(0xffffffffu, q1, o);
            mx0 = fmaxf(mx0, __shfl_xor_sync(0xffffffffu, mx0, o));
            mn0 = fminf(mn0, __shfl_xor_sync(0xffffffffu, mn0, o));
            mx1 = fmaxf(mx1, __shfl_xor_sync(0xffffffffu, mx1, o));
            mn1 = fminf(mn1, __shfl_xor_sync(0xffffffffu, mn1, o));
        }
        if ((lane & 3) == 0) {
            atomicAdd(&d_sumY[e], s0);     atomicAdd(&d_sqY[e], q0);
            atomicAdd(&d_sumY[e + 8], s1); atomicAdd(&d_sqY[e + 8], q1);
            atomicMax(&d_maxK[bb*EMB + e], fkey(mx0));
            atomicMin(&d_minK[bb*EMB + e], fkey(mn0));
            atomicMax(&d_maxK[bb*EMB + e + 8], fkey(mx1));
            atomicMin(&d_minK[bb*EMB + e + 8], fkey(mn1));
        }
    }
}

// ---------------- BN + leaky + mean pool (split: one block per (e,b)) --------
__global__ void k_reduce(const float* __restrict__ gf, const float* __restrict__ bef) {
    int e = blockIdx.x >> 3, b = blockIdx.x & 7;
    int t = threadIdx.x, lane = t & 31, w = t >> 5;
    float mu = d_sumY[e]*(1.f/BNP);
    float var = d_sqY[e]*(1.f/BNP) - mu*mu;
    float sc = rsqrtf(var + 1e-5f)*gf[e], sh = bef[e];
    const __half2* yb = (const __half2*)(d_Yh + (size_t)e*BNP + b*NPT);
    float sm = 0.f;
    #pragma unroll
    for (int j = t; j < NPT/2; j += 256) {
        float2 v2 = __half22float2(yb[j]);
        float v0 = (v2.x - mu)*sc + sh; v0 = v0 > 0.f ? v0 : 0.2f*v0;
        float v1 = (v2.y - mu)*sc + sh; v1 = v1 > 0.f ? v1 : 0.2f*v1;
        sm += v0 + v1;
    }
    #pragma unroll
    for (int o = 16; o; o >>= 1) sm += __shfl_xor_sync(0xffffffffu, sm, o);
    __shared__ float wsum[8];
    if (lane == 0) wsum[w] = sm;
    __syncthreads();
    if (t == 0) {
        float SM = 0.f;
        #pragma unroll
        for (int i = 0; i < 8; i++) SM += wsum[i];
        unsigned mk = (sc >= 0.f) ? d_maxK[b*EMB + e] : d_minK[b*EMB + e];
        float raw = unkey(mk);
        float v = (raw - mu)*sc + sh;
        v = v > 0.f ? v : 0.2f*v;
        d_x12[b*2*EMB + e] = v;
        d_x12[b*2*EMB + EMB + e] = SM*(1.f/NPT);
    }
}

// ---------------- head (k-split parallel) ----------------
__global__ void k_head1(const float* __restrict__ w1, const float* __restrict__ g6,
                        const float* __restrict__ b6) {
    int jl = threadIdx.x & 15, ks = threadIdx.x >> 4;
    int j = blockIdx.x*16 + jl;
    float acc[BB];
    #pragma unroll
    for (int b = 0; b < BB; b++) acc[b] = 0.f;
    for (int k = ks*128; k < ks*128 + 128; k++) {
        float wv = w1[k*512 + j];
        #pragma unroll
        for (int b = 0; b < BB; b++) acc[b] += d_x12[b*2*EMB + k]*wv;
    }
    __shared__ float sh[16][16][BB];
    #pragma unroll
    for (int b = 0; b < BB; b++) sh[ks][jl][b] = acc[b];
    __syncthreads();
    if (ks == 0) {
        #pragma unroll
        for (int b = 0; b < BB; b++) {
            float s = 0.f;
            #pragma unroll
            for (int i = 0; i < 16; i++) s += sh[i][jl][b];
            acc[b] = s;
        }
        float m = 0.f;
        #pragma unroll
        for (int b = 0; b < BB; b++) m += acc[b];
        m *= (1.f/BB);
        float var = 0.f;
        #pragma unroll
        for (int b = 0; b < BB; b++) { float d = acc[b]-m; var += d*d; }
        var *= (1.f/BB);
        float sc = rsqrtf(var + 1e-5f)*g6[j], bb = b6[j];
        #pragma unroll
        for (int b = 0; b < BB; b++) {
            float o = (acc[b]-m)*sc + bb;
            d_h512[b*512 + j] = o > 0.f ? o : 0.2f*o;
        }
    }
}

__global__ void k_head2(const float* __restrict__ w2, const float* __restrict__ b2,
                        const float* __restrict__ g7, const float* __restrict__ b7) {
    int jl = threadIdx.x & 31, ks = threadIdx.x >> 5;
    int j = blockIdx.x*32 + jl;
    float acc[BB];
    #pragma unroll
    for (int b = 0; b < BB; b++) acc[b] = 0.f;
    for (int k = ks*64; k < ks*64 + 64; k++) {
        float wv = w2[k*256 + j];
        #pragma unroll
        for (int b = 0; b < BB; b++) acc[b] += d_h512[b*512 + k]*wv;
    }
    __shared__ float sh[8][32][BB];
    #pragma unroll
    for (int b = 0; b < BB; b++) sh[ks][jl][b] = acc[b];
    __syncthreads();
    if (ks == 0) {
        #pragma unroll
        for (int b = 0; b < BB; b++) {
            float s = 0.f;
            #pragma unroll
            for (int i = 0; i < 8; i++) s += sh[i][jl][b];
            acc[b] = s + b2[j];
        }
        float m = 0.f;
        #pragma unroll
        for (int b = 0; b < BB; b++) m += acc[b];
        m *= (1.f/BB);
        float var = 0.f;
        #pragma unroll
        for (int b = 0; b < BB; b++) { float d = acc[b]-m; var += d*d; }
        var *= (1.f/BB);
        float sc = rsqrtf(var + 1e-5f)*g7[j], bb = b7[j];
        #pragma unroll
        for (int b = 0; b < BB; b++) {
            float o = (acc[b]-m)*sc + bb;
            d_h256[b*256 + j] = o > 0.f ? o : 0.2f*o;
        }
    }
}

__global__ void k_head3(const float* __restrict__ w3, const float* __restrict__ b3,
                        float* __restrict__ out) {
    int jl = threadIdx.x & 63, ks = threadIdx.x >> 6;
    float acc[BB];
    #pragma unroll
    for (int b = 0; b < BB; b++) acc[b] = 0.f;
    if (jl < 40) {
        for (int k = ks*64; k < ks*64 + 64; k++) {
            float wv = w3[k*40 + jl];
            #pragma unroll
            for (int b = 0; b < BB; b++) acc[b] += d_h256[b*256 + k]*wv;
        }
    }
    __shared__ float sh[4][64][BB];
    #pragma unroll
    for (int b = 0; b < BB; b++) sh[ks][jl][b] = acc[b];
    __syncthreads();
    if (ks == 0 && jl < 40) {
        #pragma unroll
        for (int b = 0; b < BB; b++) {
            float s = b3[jl];
            #pragma unroll
            for (int i = 0; i < 4; i++) s += sh[i][jl][b];
            out[b*40 + jl] = s;
        }
    }
}

// ---------------- launch ----------------
extern "C" void kernel_launch(void* const* d_in, const int* in_sizes, int n_in,
                              void* d_out, int out_size) {
    const float* x     = (const float*)d_in[0];
    const float* w0    = (const float*)d_in[1];
    const float* b0    = (const float*)d_in[2];
    const float* g0    = (const float*)d_in[3];
    const float* be0   = (const float*)d_in[4];
    const float* wr    = (const float*)d_in[5];
    const float* br    = (const float*)d_in[6];
    const float* gr    = (const float*)d_in[7];
    const float* ber   = (const float*)d_in[8];
    const float* W     = (const float*)d_in[9];
    const float* Bv    = (const float*)d_in[10];
    const float* G     = (const float*)d_in[11];
    const float* Be    = (const float*)d_in[12];
    const float* wconv = (const float*)d_in[13];
    const float* gf    = (const float*)d_in[14];
    const float* bef   = (const float*)d_in[15];
    const float* w1    = (const float*)d_in[16];
    const float* g6    = (const float*)d_in[17];
    const float* b6    = (const float*)d_in[18];
    const float* w2    = (const float*)d_in[19];
    const float* b2    = (const float*)d_in[20];
    const float* g7    = (const float*)d_in[21];
    const float* b7    = (const float*)d_in[22];
    const float* w3    = (const float*)d_in[23];
    const float* b3    = (const float*)d_in[24];
    float* out = (float*)d_out;

    static int smem_set = 0;
    if (!smem_set) {
        cudaFuncSetAttribute(k_conv_mma, cudaFuncAttributeMaxDynamicSharedMemorySize, SMEM_CONV);
        smem_set = 1;
    }

    // graph build (k_knn kept in the 4th = captured slot)
    k_begin<<<256, 256>>>(wconv);
    k_prep<<<64, 256>>>(x);
    k_l0mm<<<4096, 256>>>(x, w0, wr, br);
    k_knn<<<1024, 256>>>();
    k_scanA<<<16, 1024>>>();
    k_scanB<<<64, 256>>>();
    k_fill<<<64, 256>>>();

    // layer 0
    k_gather_stats<<<2048, 256>>>(b0, 0);
    k_post0_mm<<<256, 256>>>(g0, be0, gr, ber, W);

    // layers 1..3
    k_gather_stats<<<2048, 256>>>(Bv, 1);
    k_postL_mm<<<256, 256>>>(1, G, Be, W + 4096);
    k_gather_stats<<<2048, 256>>>(Bv + 64, 2);
    k_postL_mm<<<256, 256>>>(2, G + 64, Be + 64, W + 8192);
    k_gather_stats<<<2048, 256>>>(Bv + 128, 3);
    k_post3<<<4096, 256>>>(G + 128, Be + 128);

    // conv 256 -> 1024 (fp16 3-term, 128x256 tile) + fused stats/extrema
    dim3 cgrid(64, 8);
    k_conv_mma<<<cgrid, 256, SMEM_CONV>>>();
    k_reduce<<<8192, 256>>>(gf, bef);

    // head
    k_head1<<<32, 256>>>(w1, g6, b6);
    k_head2<<<8, 256>>>(w2, b2, g7, b7);
    k_head3<<<1, 256>>>(w3, b3, out);
}